// round 5
// baseline (speedup 1.0000x reference)
#include <cuda_runtime.h>
#include <cuda_bf16.h>
#include <cstdint>
#include <math.h>

// ---------------- problem constants ----------------
#define MODEL_DIM 1024
#define NUM_HEADS 16
#define HEAD_DIM  64
#define WINDOW    32
#define EPS       1e-5f
#define BATCH     2
#define SEQ       2048
#define MROWS     (BATCH * SEQ)      // 4096
#define QKV_LD    (3 * MODEL_DIM)    // 3072
#define KX        3072               // expanded K: [hi | hi | lo] (A) x [hi | lo | hi] (B)

// ---------------- scratch ----------------
__device__ __nv_bfloat16 g_Hx  [MROWS * KX];
__device__ __nv_bfloat16 g_Wqkv[QKV_LD * KX];
__device__ __nv_bfloat16 g_Wo  [MODEL_DIM * KX];
__device__ float         g_bqkv[QKV_LD];
__device__ float         g_QKV [MROWS * QKV_LD];
__device__ __nv_bfloat16 g_ATTx[MROWS * KX];

// ---------------- helpers ----------------
__device__ __forceinline__ uint32_t smem_u32(const void* p) {
    uint32_t a;
    asm("{ .reg .u64 t; cvta.to.shared.u64 t, %1; cvt.u32.u64 %0, t; }" : "=r"(a) : "l"(p));
    return a;
}
__device__ __forceinline__ void cp_async16(uint32_t dst, const void* src) {
    asm volatile("cp.async.cg.shared.global [%0], [%1], 16;" :: "r"(dst), "l"(src) : "memory");
}
__device__ __forceinline__ void cp_commit() {
    asm volatile("cp.async.commit_group;" ::: "memory");
}
template<int N>
__device__ __forceinline__ void cp_wait() {
    asm volatile("cp.async.wait_group %0;" :: "n"(N) : "memory");
}
__device__ __forceinline__ void ldsm_x4(uint32_t& r0, uint32_t& r1, uint32_t& r2, uint32_t& r3, uint32_t a) {
    asm volatile("ldmatrix.sync.aligned.m8n8.x4.shared.b16 {%0,%1,%2,%3}, [%4];"
                 : "=r"(r0), "=r"(r1), "=r"(r2), "=r"(r3) : "r"(a));
}
__device__ __forceinline__ void mma_bf16(float& c0, float& c1, float& c2, float& c3,
                                         uint32_t a0, uint32_t a1, uint32_t a2, uint32_t a3,
                                         uint32_t b0, uint32_t b1) {
    asm volatile("mma.sync.aligned.m16n8k16.row.col.f32.bf16.bf16.f32 "
                 "{%0,%1,%2,%3},{%4,%5,%6,%7},{%8,%9},{%0,%1,%2,%3};"
                 : "+f"(c0), "+f"(c1), "+f"(c2), "+f"(c3)
                 : "r"(a0), "r"(a1), "r"(a2), "r"(a3), "r"(b0), "r"(b1));
}
__device__ __forceinline__ void split_bf(float v, __nv_bfloat16& hi, __nv_bfloat16& lo) {
    hi = __float2bfloat16(v);
    lo = __float2bfloat16(v - __bfloat162float(hi));
}

// ============================================================
// LayerNorm -> split-expanded bf16 row [hi | hi | lo]
// ============================================================
__global__ __launch_bounds__(256)
void ln_kernel(const float* __restrict__ x,
               const float* __restrict__ gamma,
               const float* __restrict__ beta,
               __nv_bfloat16* __restrict__ Hx)
{
    int row = blockIdx.x;
    int tid = threadIdx.x;
    float4 a = ((const float4*)(x + (size_t)row * MODEL_DIM))[tid];

    __shared__ float red[8];
    __shared__ float stat;

    float s = a.x + a.y + a.z + a.w;
    #pragma unroll
    for (int o = 16; o; o >>= 1) s += __shfl_xor_sync(0xffffffffu, s, o);
    if ((tid & 31) == 0) red[tid >> 5] = s;
    __syncthreads();
    if (tid == 0) {
        float t = 0.f;
        #pragma unroll
        for (int i = 0; i < 8; i++) t += red[i];
        stat = t * (1.0f / MODEL_DIM);
    }
    __syncthreads();
    float mu = stat;

    float dx = a.x - mu, dy = a.y - mu, dz = a.z - mu, dw = a.w - mu;
    float s2 = dx*dx + dy*dy + dz*dz + dw*dw;
    #pragma unroll
    for (int o = 16; o; o >>= 1) s2 += __shfl_xor_sync(0xffffffffu, s2, o);
    __syncthreads();
    if ((tid & 31) == 0) red[tid >> 5] = s2;
    __syncthreads();
    if (tid == 0) {
        float t = 0.f;
        #pragma unroll
        for (int i = 0; i < 8; i++) t += red[i];
        stat = rsqrtf(t * (1.0f / MODEL_DIM) + EPS);
    }
    __syncthreads();
    float rstd = stat;

    float4 g = ((const float4*)gamma)[tid];
    float4 b = ((const float4*)beta)[tid];
    float v[4];
    v[0] = dx * rstd * g.x + b.x;
    v[1] = dy * rstd * g.y + b.y;
    v[2] = dz * rstd * g.z + b.z;
    v[3] = dw * rstd * g.w + b.w;

    __nv_bfloat16 hi[4], lo[4];
    #pragma unroll
    for (int i = 0; i < 4; i++) split_bf(v[i], hi[i], lo[i]);

    size_t p = (size_t)row * KX + tid * 4;
    ((__nv_bfloat162*)(Hx + p))[0]        = __nv_bfloat162(hi[0], hi[1]);
    ((__nv_bfloat162*)(Hx + p))[1]        = __nv_bfloat162(hi[2], hi[3]);
    ((__nv_bfloat162*)(Hx + p + 1024))[0] = __nv_bfloat162(hi[0], hi[1]);
    ((__nv_bfloat162*)(Hx + p + 1024))[1] = __nv_bfloat162(hi[2], hi[3]);
    ((__nv_bfloat162*)(Hx + p + 2048))[0] = __nv_bfloat162(lo[0], lo[1]);
    ((__nv_bfloat162*)(Hx + p + 2048))[1] = __nv_bfloat162(lo[2], lo[3]);
}

// ============================================================
// Weight transpose + split-expand, all 4 weights in one launch.
// ============================================================
__global__ __launch_bounds__(256)
void wconv_kernel(const float* __restrict__ wq, const float* __restrict__ wk,
                  const float* __restrict__ wv, const float* __restrict__ wo,
                  __nv_bfloat16* __restrict__ Wqkv, __nv_bfloat16* __restrict__ Wo)
{
    __shared__ float tile[32][33];
    int tx = threadIdx.x, ty = threadIdx.y;       // (32, 8)
    int bx = blockIdx.x, by = blockIdx.y, bz = blockIdx.z;
    const float* w = (bz == 0) ? wq : (bz == 1) ? wk : (bz == 2) ? wv : wo;
    __nv_bfloat16* WT = (bz < 3) ? (Wqkv + (size_t)bz * 1024 * KX) : Wo;

    #pragma unroll
    for (int i = 0; i < 4; i++) {
        int k = by * 32 + ty + i * 8;
        int n = bx * 32 + tx;
        tile[ty + i * 8][tx] = w[(size_t)k * MODEL_DIM + n];
    }
    __syncthreads();
    #pragma unroll
    for (int i = 0; i < 4; i++) {
        int n = bx * 32 + ty + i * 8;
        int k = by * 32 + tx;
        float v = tile[tx][ty + i * 8];
        __nv_bfloat16 hi, lo;
        split_bf(v, hi, lo);
        size_t base = (size_t)n * KX + k;
        WT[base]        = hi;
        WT[base + 1024] = lo;
        WT[base + 2048] = hi;
    }
}

__global__ void bconcat_kernel(const float* __restrict__ bq,
                               const float* __restrict__ bk,
                               const float* __restrict__ bv,
                               float* __restrict__ dst)
{
    int i = blockIdx.x * 256 + threadIdx.x;
    if (i >= QKV_LD) return;
    const float* s = (i < 1024) ? bq : (i < 2048 ? bk : bv);
    dst[i] = s[i & 1023];
}

// ============================================================
// bf16 mma.sync GEMM, CTA tile 128x256x64, warp tile 64x64,
// 8 warps, 3-stage cp.async pipeline.
// ============================================================
#define BM 128
#define BN 256
#define BK 64
#define BKB 128
#define A_TILE (BM * BKB)               // 16384
#define B_TILE (BN * BKB)               // 32768
#define STAGE_BYTES (A_TILE + B_TILE)   // 49152
#define NSTAGE 3
#define NIT (KX / BK)                   // 48
#define MM_SMEM (NSTAGE * STAGE_BYTES)  // 147456

__device__ __forceinline__ void stage_A(const __nv_bfloat16* __restrict__ src,
                                        int row0, int k0, uint32_t dst)
{
    int t = threadIdx.x;
    int r = t >> 1;
    int c0 = (t & 1) * 4;
    const char* g = (const char*)(src + (size_t)(row0 + r) * KX + k0);
    uint32_t rowoff = dst + r * BKB;
    uint32_t sw = (uint32_t)(r & 7) << 4;
    #pragma unroll
    for (int j = 0; j < 4; j++) {
        uint32_t cb = (uint32_t)(c0 + j) * 16;
        cp_async16(rowoff + (cb ^ sw), g + cb);
    }
}
__device__ __forceinline__ void stage_B(const __nv_bfloat16* __restrict__ src,
                                        int row0, int k0, uint32_t dst)
{
    int r = threadIdx.x;                 // 256 rows, 1 per thread
    const char* g = (const char*)(src + (size_t)(row0 + r) * KX + k0);
    uint32_t rowoff = dst + r * BKB;
    uint32_t sw = (uint32_t)(r & 7) << 4;
    #pragma unroll
    for (int j = 0; j < 8; j++) {
        uint32_t cb = (uint32_t)j * 16;
        cp_async16(rowoff + (cb ^ sw), g + cb);
    }
}

template<bool RESID>
__global__ __launch_bounds__(256, 1)
void mm_kernel(const __nv_bfloat16* __restrict__ A,
               const __nv_bfloat16* __restrict__ B,
               const float* __restrict__ bias,
               const float* __restrict__ resid,
               float* __restrict__ C, int ldc)
{
    extern __shared__ char smem[];
    uint32_t sb = smem_u32(smem);

    int tid  = threadIdx.x;
    int wid  = tid >> 5;
    int lane = tid & 31;
    int wm = (wid >> 2) * 64;            // 2 groups of 64 rows
    int wn = (wid & 3) * 64;             // 4 groups of 64 cols
    int rowA = blockIdx.y * BM;
    int rowB = blockIdx.x * BN;

    float acc[4][8][4];
    #pragma unroll
    for (int i = 0; i < 4; i++)
        #pragma unroll
        for (int j = 0; j < 8; j++)
            #pragma unroll
            for (int q = 0; q < 4; q++) acc[i][j][q] = 0.f;

    int ra = lane & 15;
    uint32_t swa = (uint32_t)(ra & 7) << 4;
    uint32_t ca  = (uint32_t)(lane >> 4) * 16;
    int rb = (lane & 7) + ((lane >> 4) & 1) * 8;
    uint32_t swb = (uint32_t)(lane & 7) << 4;
    uint32_t cb  = (uint32_t)((lane >> 3) & 1) * 16;

    // prologue: stage first 2 K-slabs
    stage_A(A, rowA, 0, sb);
    stage_B(B, rowB, 0, sb + A_TILE);
    cp_commit();
    stage_A(A, rowA, BK, sb + STAGE_BYTES);
    stage_B(B, rowB, BK, sb + STAGE_BYTES + A_TILE);
    cp_commit();

    #pragma unroll 1
    for (int it = 0; it < NIT; it++) {
        if (it + 1 < NIT) cp_wait<1>(); else cp_wait<0>();
        __syncthreads();

        if (it + 2 < NIT) {
            uint32_t nb = sb + (uint32_t)((it + 2) % NSTAGE) * STAGE_BYTES;
            int k0 = (it + 2) * BK;
            stage_A(A, rowA, k0, nb);
            stage_B(B, rowB, k0, nb + A_TILE);
            cp_commit();
        }

        uint32_t aB = sb + (uint32_t)(it % NSTAGE) * STAGE_BYTES;
        uint32_t bB = aB + A_TILE;
        uint32_t aRow[4], bRow[4];
        #pragma unroll
        for (int tm = 0; tm < 4; tm++) aRow[tm] = aB + (uint32_t)(wm + tm * 16 + ra) * BKB;
        #pragma unroll
        for (int tg = 0; tg < 4; tg++) bRow[tg] = bB + (uint32_t)(wn + tg * 16 + rb) * BKB;

        #pragma unroll
        for (int kk = 0; kk < 4; kk++) {
            uint32_t akb = ((uint32_t)kk * 32 + ca) ^ swa;
            uint32_t bkb = ((uint32_t)kk * 32 + cb) ^ swb;
            uint32_t af[4][4];
            uint32_t bf[4][4];
            #pragma unroll
            for (int tm = 0; tm < 4; tm++)
                ldsm_x4(af[tm][0], af[tm][1], af[tm][2], af[tm][3], aRow[tm] + akb);
            #pragma unroll
            for (int tg = 0; tg < 4; tg++)
                ldsm_x4(bf[tg][0], bf[tg][1], bf[tg][2], bf[tg][3], bRow[tg] + bkb);

            #pragma unroll
            for (int tm = 0; tm < 4; tm++)
                #pragma unroll
                for (int tn = 0; tn < 8; tn++) {
                    uint32_t b0 = bf[tn >> 1][(tn & 1) * 2 + 0];
                    uint32_t b1 = bf[tn >> 1][(tn & 1) * 2 + 1];
                    mma_bf16(acc[tm][tn][0], acc[tm][tn][1], acc[tm][tn][2], acc[tm][tn][3],
                             af[tm][0], af[tm][1], af[tm][2], af[tm][3], b0, b1);
                }
        }
        __syncthreads();
    }

    // epilogue
    int mBase = rowA + wm + (lane >> 2);
    int nBase = rowB + wn + (lane & 3) * 2;
    #pragma unroll
    for (int tm = 0; tm < 4; tm++) {
        int m0 = mBase + tm * 16;
        #pragma unroll
        for (int tn = 0; tn < 8; tn++) {
            int n = nBase + tn * 8;
            float bx0 = bias[n], bx1 = bias[n + 1];
            float2 v0, v1;
            v0.x = acc[tm][tn][0] + bx0;
            v0.y = acc[tm][tn][1] + bx1;
            v1.x = acc[tm][tn][2] + bx0;
            v1.y = acc[tm][tn][3] + bx1;
            if (RESID) {
                float2 r0 = *(const float2*)(resid + (size_t)m0 * MODEL_DIM + n);
                float2 r1 = *(const float2*)(resid + (size_t)(m0 + 8) * MODEL_DIM + n);
                v0.x += r0.x; v0.y += r0.y;
                v1.x += r1.x; v1.y += r1.y;
            }
            *(float2*)(C + (size_t)m0 * ldc + n)       = v0;
            *(float2*)(C + (size_t)(m0 + 8) * ldc + n) = v1;
        }
    }
}

// ============================================================
// Sliding-window attention (KROW=68: aligned, conflict-free)
// ============================================================
#define QT 128
#define NS (QT + 2 * WINDOW)    // 192
#define KROW 68
#define ATT_SMEM (2 * NS * KROW * 4)   // 104448

__global__ __launch_bounds__(QT)
void attn_kernel(const float* __restrict__ QKV,
                 __nv_bfloat16* __restrict__ Ox)
{
    extern __shared__ float sm[];
    float* Ks = sm;
    float* Vs = sm + NS * KROW;

    int qt = blockIdx.x * QT;
    int h  = blockIdx.y;
    int b  = blockIdx.z;
    int t  = threadIdx.x;
    size_t base = (size_t)b * SEQ * QKV_LD;

    for (int idx = t; idx < NS * 16; idx += QT) {
        int kk = idx >> 4;
        int c  = idx & 15;
        int j  = qt - WINDOW + kk;
        float4 kv = make_float4(0.f, 0.f, 0.f, 0.f);
        float4 vv = kv;
        if (j >= 0 && j < SEQ) {
            const float* p = QKV + base + (size_t)j * QKV_LD + h * HEAD_DIM + c * 4;
            kv = *(const float4*)(p + MODEL_DIM);
            vv = *(const float4*)(p + 2 * MODEL_DIM);
        }
        *(float4*)(Ks + kk * KROW + c * 4) = kv;
        *(float4*)(Vs + kk * KROW + c * 4) = vv;
    }
    __syncthreads();

    int s = qt + t;
    const float4* qp4 = (const float4*)(QKV + base + (size_t)s * QKV_LD + h * HEAD_DIM);
    float q[HEAD_DIM];
    #pragma unroll
    for (int i = 0; i < 16; i++) {
        float4 u = qp4[i];
        q[4*i+0] = u.x * 0.125f;
        q[4*i+1] = u.y * 0.125f;
        q[4*i+2] = u.z * 0.125f;
        q[4*i+3] = u.w * 0.125f;
    }

    float sc[2 * WINDOW + 1];
    float m = -1e30f;
    #pragma unroll 1
    for (int w = 0; w < 2 * WINDOW + 1; w++) {
        int j = s - WINDOW + w;
        const float4* kr4 = (const float4*)(Ks + (t + w) * KROW);
        float dot = 0.f;
        #pragma unroll
        for (int i = 0; i < 16; i++) {
            float4 kv = kr4[i];
            dot = fmaf(q[4*i+0], kv.x, dot);
            dot = fmaf(q[4*i+1], kv.y, dot);
            dot = fmaf(q[4*i+2], kv.z, dot);
            dot = fmaf(q[4*i+3], kv.w, dot);
        }
        dot = (j >= 0 && j < SEQ) ? dot : -1e30f;
        sc[w] = dot;
        m = fmaxf(m, dot);
    }

    float denom = 0.f;
    #pragma unroll
    for (int w = 0; w < 2 * WINDOW + 1; w++) {
        float e = __expf(sc[w] - m);
        sc[w] = e;
        denom += e;
    }
    float inv = 1.0f / denom;

    float o[HEAD_DIM];
    #pragma unroll
    for (int d = 0; d < HEAD_DIM; d++) o[d] = 0.f;
    #pragma unroll 1
    for (int w = 0; w < 2 * WINDOW + 1; w++) {
        float p = sc[w];
        const float4* vr4 = (const float4*)(Vs + (t + w) * KROW);
        #pragma unroll
        for (int i = 0; i < 16; i++) {
            float4 vv = vr4[i];
            o[4*i+0] = fmaf(p, vv.x, o[4*i+0]);
            o[4*i+1] = fmaf(p, vv.y, o[4*i+1]);
            o[4*i+2] = fmaf(p, vv.z, o[4*i+2]);
            o[4*i+3] = fmaf(p, vv.w, o[4*i+3]);
        }
    }

    size_t op = (size_t)(b * SEQ + s) * KX + h * HEAD_DIM;
    #pragma unroll
    for (int i = 0; i < 32; i++) {
        float v0 = o[2*i + 0] * inv;
        float v1 = o[2*i + 1] * inv;
        __nv_bfloat16 h0, l0, h1, l1;
        split_bf(v0, h0, l0);
        split_bf(v1, h1, l1);
        __nv_bfloat162 hp(h0, h1), lp(l0, l1);
        ((__nv_bfloat162*)(Ox + op))[i]          = hp;
        ((__nv_bfloat162*)(Ox + op + 1024))[i]   = hp;
        ((__nv_bfloat162*)(Ox + op + 2048))[i]   = lp;
    }
}

// ============================================================
// launch
// ============================================================
extern "C" void kernel_launch(void* const* d_in, const int* in_sizes, int n_in,
                              void* d_out, int out_size)
{
    (void)in_sizes; (void)n_in; (void)out_size;
    const float* x     = (const float*)d_in[0];
    const float* w_q   = (const float*)d_in[1];
    const float* b_q   = (const float*)d_in[2];
    const float* w_k   = (const float*)d_in[3];
    const float* b_k   = (const float*)d_in[4];
    const float* w_v   = (const float*)d_in[5];
    const float* b_v   = (const float*)d_in[6];
    const float* w_o   = (const float*)d_in[7];
    const float* b_o   = (const float*)d_in[8];
    const float* gamma = (const float*)d_in[9];
    const float* beta  = (const float*)d_in[10];
    float* out = (float*)d_out;

    void *pHx, *pWqkv, *pWo, *pBq, *pQKV, *pAx;
    cudaGetSymbolAddress(&pHx,   g_Hx);
    cudaGetSymbolAddress(&pWqkv, g_Wqkv);
    cudaGetSymbolAddress(&pWo,   g_Wo);
    cudaGetSymbolAddress(&pBq,   g_bqkv);
    cudaGetSymbolAddress(&pQKV,  g_QKV);
    cudaGetSymbolAddress(&pAx,   g_ATTx);
    __nv_bfloat16* Hx   = (__nv_bfloat16*)pHx;
    __nv_bfloat16* Wqkv = (__nv_bfloat16*)pWqkv;
    __nv_bfloat16* Wo   = (__nv_bfloat16*)pWo;
    float*         bqkv = (float*)pBq;
    float*         QKV  = (float*)pQKV;
    __nv_bfloat16* ATTx = (__nv_bfloat16*)pAx;

    cudaFuncSetAttribute(mm_kernel<false>, cudaFuncAttributeMaxDynamicSharedMemorySize, MM_SMEM);
    cudaFuncSetAttribute(mm_kernel<true>,  cudaFuncAttributeMaxDynamicSharedMemorySize, MM_SMEM);
    cudaFuncSetAttribute(attn_kernel, cudaFuncAttributeMaxDynamicSharedMemorySize, ATT_SMEM);

    // prep
    dim3 wb(32, 8);
    dim3 wg(32, 32, 4);
    wconv_kernel<<<wg, wb>>>(w_q, w_k, w_v, w_o, Wqkv, Wo);
    bconcat_kernel<<<(QKV_LD + 255) / 256, 256>>>(b_q, b_k, b_v, bqkv);
    ln_kernel<<<MROWS, 256>>>(x, gamma, beta, Hx);

    // fused QKV GEMM: [4096 x 3072]
    dim3 gq(QKV_LD / BN, MROWS / BM);     // (12, 32)
    mm_kernel<false><<<gq, 256, MM_SMEM>>>(Hx, Wqkv, bqkv, nullptr, QKV, QKV_LD);

    // attention
    dim3 ga(SEQ / QT, NUM_HEADS, BATCH);
    attn_kernel<<<ga, QT, ATT_SMEM>>>(QKV, ATTx);

    // output projection + bias + residual
    dim3 go(MODEL_DIM / BN, MROWS / BM);  // (4, 32)
    mm_kernel<true><<<go, 256, MM_SMEM>>>(ATTx, Wo, b_o, x, out, MODEL_DIM);
}

// round 6
// speedup vs baseline: 1.0665x; 1.0665x over previous
#include <cuda_runtime.h>
#include <cuda_bf16.h>
#include <cstdint>
#include <math.h>

// ---------------- problem constants ----------------
#define MODEL_DIM 1024
#define NUM_HEADS 16
#define HEAD_DIM  64
#define WINDOW    32
#define EPS       1e-5f
#define BATCH     2
#define SEQ       2048
#define MROWS     (BATCH * SEQ)      // 4096
#define QKV_LD    (3 * MODEL_DIM)    // 3072
#define KX        3072               // expanded K: [hi | hi | lo] (A) x [hi | lo | hi] (B)

// ---------------- scratch ----------------
__device__ __nv_bfloat16 g_Hx  [MROWS * KX];
__device__ __nv_bfloat16 g_Wqkv[QKV_LD * KX];
__device__ __nv_bfloat16 g_Wo  [MODEL_DIM * KX];
__device__ float         g_bqkv[QKV_LD];
__device__ float         g_QKV [MROWS * QKV_LD];
__device__ __nv_bfloat16 g_ATTx[MROWS * KX];

// ---------------- helpers ----------------
__device__ __forceinline__ uint32_t smem_u32(const void* p) {
    uint32_t a;
    asm("{ .reg .u64 t; cvta.to.shared.u64 t, %1; cvt.u32.u64 %0, t; }" : "=r"(a) : "l"(p));
    return a;
}
__device__ __forceinline__ void cp_async16(uint32_t dst, const void* src) {
    asm volatile("cp.async.cg.shared.global [%0], [%1], 16;" :: "r"(dst), "l"(src) : "memory");
}
__device__ __forceinline__ void cp_commit() {
    asm volatile("cp.async.commit_group;" ::: "memory");
}
template<int N>
__device__ __forceinline__ void cp_wait() {
    asm volatile("cp.async.wait_group %0;" :: "n"(N) : "memory");
}
__device__ __forceinline__ void ldsm_x4(uint32_t& r0, uint32_t& r1, uint32_t& r2, uint32_t& r3, uint32_t a) {
    asm volatile("ldmatrix.sync.aligned.m8n8.x4.shared.b16 {%0,%1,%2,%3}, [%4];"
                 : "=r"(r0), "=r"(r1), "=r"(r2), "=r"(r3) : "r"(a));
}
__device__ __forceinline__ void mma_bf16(float& c0, float& c1, float& c2, float& c3,
                                         uint32_t a0, uint32_t a1, uint32_t a2, uint32_t a3,
                                         uint32_t b0, uint32_t b1) {
    asm volatile("mma.sync.aligned.m16n8k16.row.col.f32.bf16.bf16.f32 "
                 "{%0,%1,%2,%3},{%4,%5,%6,%7},{%8,%9},{%0,%1,%2,%3};"
                 : "+f"(c0), "+f"(c1), "+f"(c2), "+f"(c3)
                 : "r"(a0), "r"(a1), "r"(a2), "r"(a3), "r"(b0), "r"(b1));
}
__device__ __forceinline__ void split_bf(float v, __nv_bfloat16& hi, __nv_bfloat16& lo) {
    hi = __float2bfloat16(v);
    lo = __float2bfloat16(v - __bfloat162float(hi));
}

// ============================================================
// LayerNorm -> split-expanded bf16 row [hi | hi | lo]
// ============================================================
__global__ __launch_bounds__(256)
void ln_kernel(const float* __restrict__ x,
               const float* __restrict__ gamma,
               const float* __restrict__ beta,
               __nv_bfloat16* __restrict__ Hx)
{
    int row = blockIdx.x;
    int tid = threadIdx.x;
    float4 a = ((const float4*)(x + (size_t)row * MODEL_DIM))[tid];

    __shared__ float red[8];
    __shared__ float stat;

    float s = a.x + a.y + a.z + a.w;
    #pragma unroll
    for (int o = 16; o; o >>= 1) s += __shfl_xor_sync(0xffffffffu, s, o);
    if ((tid & 31) == 0) red[tid >> 5] = s;
    __syncthreads();
    if (tid == 0) {
        float t = 0.f;
        #pragma unroll
        for (int i = 0; i < 8; i++) t += red[i];
        stat = t * (1.0f / MODEL_DIM);
    }
    __syncthreads();
    float mu = stat;

    float dx = a.x - mu, dy = a.y - mu, dz = a.z - mu, dw = a.w - mu;
    float s2 = dx*dx + dy*dy + dz*dz + dw*dw;
    #pragma unroll
    for (int o = 16; o; o >>= 1) s2 += __shfl_xor_sync(0xffffffffu, s2, o);
    __syncthreads();
    if ((tid & 31) == 0) red[tid >> 5] = s2;
    __syncthreads();
    if (tid == 0) {
        float t = 0.f;
        #pragma unroll
        for (int i = 0; i < 8; i++) t += red[i];
        stat = rsqrtf(t * (1.0f / MODEL_DIM) + EPS);
    }
    __syncthreads();
    float rstd = stat;

    float4 g = ((const float4*)gamma)[tid];
    float4 b = ((const float4*)beta)[tid];
    float v[4];
    v[0] = dx * rstd * g.x + b.x;
    v[1] = dy * rstd * g.y + b.y;
    v[2] = dz * rstd * g.z + b.z;
    v[3] = dw * rstd * g.w + b.w;

    __nv_bfloat16 hi[4], lo[4];
    #pragma unroll
    for (int i = 0; i < 4; i++) split_bf(v[i], hi[i], lo[i]);

    size_t p = (size_t)row * KX + tid * 4;
    ((__nv_bfloat162*)(Hx + p))[0]        = __nv_bfloat162(hi[0], hi[1]);
    ((__nv_bfloat162*)(Hx + p))[1]        = __nv_bfloat162(hi[2], hi[3]);
    ((__nv_bfloat162*)(Hx + p + 1024))[0] = __nv_bfloat162(hi[0], hi[1]);
    ((__nv_bfloat162*)(Hx + p + 1024))[1] = __nv_bfloat162(hi[2], hi[3]);
    ((__nv_bfloat162*)(Hx + p + 2048))[0] = __nv_bfloat162(lo[0], lo[1]);
    ((__nv_bfloat162*)(Hx + p + 2048))[1] = __nv_bfloat162(lo[2], lo[3]);
}

// ============================================================
// Weight transpose + split-expand, all 4 weights in one launch.
// ============================================================
__global__ __launch_bounds__(256)
void wconv_kernel(const float* __restrict__ wq, const float* __restrict__ wk,
                  const float* __restrict__ wv, const float* __restrict__ wo,
                  __nv_bfloat16* __restrict__ Wqkv, __nv_bfloat16* __restrict__ Wo)
{
    __shared__ float tile[32][33];
    int tx = threadIdx.x, ty = threadIdx.y;       // (32, 8)
    int bx = blockIdx.x, by = blockIdx.y, bz = blockIdx.z;
    const float* w = (bz == 0) ? wq : (bz == 1) ? wk : (bz == 2) ? wv : wo;
    __nv_bfloat16* WT = (bz < 3) ? (Wqkv + (size_t)bz * 1024 * KX) : Wo;

    #pragma unroll
    for (int i = 0; i < 4; i++) {
        int k = by * 32 + ty + i * 8;
        int n = bx * 32 + tx;
        tile[ty + i * 8][tx] = w[(size_t)k * MODEL_DIM + n];
    }
    __syncthreads();
    #pragma unroll
    for (int i = 0; i < 4; i++) {
        int n = bx * 32 + ty + i * 8;
        int k = by * 32 + tx;
        float v = tile[tx][ty + i * 8];
        __nv_bfloat16 hi, lo;
        split_bf(v, hi, lo);
        size_t base = (size_t)n * KX + k;
        WT[base]        = hi;
        WT[base + 1024] = lo;
        WT[base + 2048] = hi;
    }
}

__global__ void bconcat_kernel(const float* __restrict__ bq,
                               const float* __restrict__ bk,
                               const float* __restrict__ bv,
                               float* __restrict__ dst)
{
    int i = blockIdx.x * 256 + threadIdx.x;
    if (i >= QKV_LD) return;
    const float* s = (i < 1024) ? bq : (i < 2048 ? bk : bv);
    dst[i] = s[i & 1023];
}

// ============================================================
// bf16 mma.sync GEMM, CTA tile 128x128x64, warp tile 64x32,
// 8 warps, 4-stage cp.async pipeline, register-fragment
// double buffering, ONE barrier per K-iter.
// ============================================================
#define BM 128
#define BN 128
#define BK 64
#define BKB 128
#define A_TILE (BM * BKB)               // 16384
#define B_TILE (BN * BKB)               // 16384
#define STAGE_BYTES (A_TILE + B_TILE)   // 32768
#define NSTAGE 4
#define NIT (KX / BK)                   // 48
#define MM_SMEM (NSTAGE * STAGE_BYTES)  // 131072

__device__ __forceinline__ void stage_tile(const __nv_bfloat16* __restrict__ src,
                                           int row0, int k0, uint32_t dst)
{
    int t = threadIdx.x;
    int r = t >> 1;
    int c0 = (t & 1) * 4;
    const char* g = (const char*)(src + (size_t)(row0 + r) * KX + k0);
    uint32_t rowoff = dst + r * BKB;
    uint32_t sw = (uint32_t)(r & 7) << 4;
    #pragma unroll
    for (int j = 0; j < 4; j++) {
        uint32_t cb = (uint32_t)(c0 + j) * 16;
        cp_async16(rowoff + (cb ^ sw), g + cb);
    }
}

template<bool RESID>
__global__ __launch_bounds__(256, 1)
void mm_kernel(const __nv_bfloat16* __restrict__ A,
               const __nv_bfloat16* __restrict__ B,
               const float* __restrict__ bias,
               const float* __restrict__ resid,
               float* __restrict__ C, int ldc)
{
    extern __shared__ char smem[];
    uint32_t sb = smem_u32(smem);

    int tid  = threadIdx.x;
    int wid  = tid >> 5;
    int lane = tid & 31;
    int wm = (wid >> 2) * 64;            // 0 / 64
    int wn = (wid & 3) * 32;             // 0/32/64/96
    int rowA = blockIdx.y * BM;
    int rowB = blockIdx.x * BN;

    float acc[4][4][4];
    #pragma unroll
    for (int i = 0; i < 4; i++)
        #pragma unroll
        for (int j = 0; j < 4; j++)
            #pragma unroll
            for (int q = 0; q < 4; q++) acc[i][j][q] = 0.f;

    int ra = lane & 15;
    uint32_t swa = (uint32_t)(ra & 7) << 4;
    uint32_t ca  = (uint32_t)(lane >> 4) * 16;
    int rb = (lane & 7) + ((lane >> 4) & 1) * 8;
    uint32_t swb = (uint32_t)(lane & 7) << 4;
    uint32_t cb  = (uint32_t)((lane >> 3) & 1) * 16;

    // prologue: stage first 3 K-slabs
    #pragma unroll
    for (int p = 0; p < 3; p++) {
        uint32_t st = sb + (uint32_t)p * STAGE_BYTES;
        stage_tile(A, rowA, p * BK, st);
        stage_tile(B, rowB, p * BK, st + A_TILE);
        cp_commit();
    }

    uint32_t af[2][4][4];
    uint32_t bf[2][2][4];

    #pragma unroll 1
    for (int it = 0; it < NIT; it++) {
        cp_wait<2>();
        __syncthreads();

        // prefetch slab it+3 into stage (it+3)%4 (last read at it-1)
        if (it + 3 < NIT) {
            uint32_t nb = sb + (uint32_t)((it + 3) % NSTAGE) * STAGE_BYTES;
            int k0 = (it + 3) * BK;
            stage_tile(A, rowA, k0, nb);
            stage_tile(B, rowB, k0, nb + A_TILE);
        }
        cp_commit();   // commit even when empty to keep group count in sync

        uint32_t aB = sb + (uint32_t)(it % NSTAGE) * STAGE_BYTES;
        uint32_t bB = aB + A_TILE;
        uint32_t aRow[4], bRow[2];
        #pragma unroll
        for (int tm = 0; tm < 4; tm++) aRow[tm] = aB + (uint32_t)(wm + tm * 16 + ra) * BKB;
        #pragma unroll
        for (int tg = 0; tg < 2; tg++) bRow[tg] = bB + (uint32_t)(wn + tg * 16 + rb) * BKB;

        // load fragments for kk=0
        {
            uint32_t akb = ca ^ swa;
            uint32_t bkb = cb ^ swb;
            #pragma unroll
            for (int tm = 0; tm < 4; tm++)
                ldsm_x4(af[0][tm][0], af[0][tm][1], af[0][tm][2], af[0][tm][3], aRow[tm] + akb);
            #pragma unroll
            for (int tg = 0; tg < 2; tg++)
                ldsm_x4(bf[0][tg][0], bf[0][tg][1], bf[0][tg][2], bf[0][tg][3], bRow[tg] + bkb);
        }

        #pragma unroll
        for (int kk = 0; kk < 4; kk++) {
            int cur = kk & 1;
            if (kk < 3) {
                int nxt = cur ^ 1;
                uint32_t akb = ((uint32_t)(kk + 1) * 32 + ca) ^ swa;
                uint32_t bkb = ((uint32_t)(kk + 1) * 32 + cb) ^ swb;
                #pragma unroll
                for (int tm = 0; tm < 4; tm++)
                    ldsm_x4(af[nxt][tm][0], af[nxt][tm][1], af[nxt][tm][2], af[nxt][tm][3], aRow[tm] + akb);
                #pragma unroll
                for (int tg = 0; tg < 2; tg++)
                    ldsm_x4(bf[nxt][tg][0], bf[nxt][tg][1], bf[nxt][tg][2], bf[nxt][tg][3], bRow[tg] + bkb);
            }
            #pragma unroll
            for (int tm = 0; tm < 4; tm++)
                #pragma unroll
                for (int tn = 0; tn < 4; tn++) {
                    uint32_t b0 = bf[cur][tn >> 1][(tn & 1) * 2 + 0];
                    uint32_t b1 = bf[cur][tn >> 1][(tn & 1) * 2 + 1];
                    mma_bf16(acc[tm][tn][0], acc[tm][tn][1], acc[tm][tn][2], acc[tm][tn][3],
                             af[cur][tm][0], af[cur][tm][1], af[cur][tm][2], af[cur][tm][3], b0, b1);
                }
        }
    }

    // epilogue
    int mBase = rowA + wm + (lane >> 2);
    int nBase = rowB + wn + (lane & 3) * 2;
    #pragma unroll
    for (int tm = 0; tm < 4; tm++) {
        int m0 = mBase + tm * 16;
        #pragma unroll
        for (int tn = 0; tn < 4; tn++) {
            int n = nBase + tn * 8;
            float bx0 = bias[n], bx1 = bias[n + 1];
            float2 v0, v1;
            v0.x = acc[tm][tn][0] + bx0;
            v0.y = acc[tm][tn][1] + bx1;
            v1.x = acc[tm][tn][2] + bx0;
            v1.y = acc[tm][tn][3] + bx1;
            if (RESID) {
                float2 r0 = *(const float2*)(resid + (size_t)m0 * MODEL_DIM + n);
                float2 r1 = *(const float2*)(resid + (size_t)(m0 + 8) * MODEL_DIM + n);
                v0.x += r0.x; v0.y += r0.y;
                v1.x += r1.x; v1.y += r1.y;
            }
            *(float2*)(C + (size_t)m0 * ldc + n)       = v0;
            *(float2*)(C + (size_t)(m0 + 8) * ldc + n) = v1;
        }
    }
}

// ============================================================
// Sliding-window attention (KROW=68: aligned, conflict-free)
// ============================================================
#define QT 128
#define NS (QT + 2 * WINDOW)    // 192
#define KROW 68
#define ATT_SMEM (2 * NS * KROW * 4)   // 104448

__global__ __launch_bounds__(QT)
void attn_kernel(const float* __restrict__ QKV,
                 __nv_bfloat16* __restrict__ Ox)
{
    extern __shared__ float sm[];
    float* Ks = sm;
    float* Vs = sm + NS * KROW;

    int qt = blockIdx.x * QT;
    int h  = blockIdx.y;
    int b  = blockIdx.z;
    int t  = threadIdx.x;
    size_t base = (size_t)b * SEQ * QKV_LD;

    for (int idx = t; idx < NS * 16; idx += QT) {
        int kk = idx >> 4;
        int c  = idx & 15;
        int j  = qt - WINDOW + kk;
        float4 kv = make_float4(0.f, 0.f, 0.f, 0.f);
        float4 vv = kv;
        if (j >= 0 && j < SEQ) {
            const float* p = QKV + base + (size_t)j * QKV_LD + h * HEAD_DIM + c * 4;
            kv = *(const float4*)(p + MODEL_DIM);
            vv = *(const float4*)(p + 2 * MODEL_DIM);
        }
        *(float4*)(Ks + kk * KROW + c * 4) = kv;
        *(float4*)(Vs + kk * KROW + c * 4) = vv;
    }
    __syncthreads();

    int s = qt + t;
    const float4* qp4 = (const float4*)(QKV + base + (size_t)s * QKV_LD + h * HEAD_DIM);
    float q[HEAD_DIM];
    #pragma unroll
    for (int i = 0; i < 16; i++) {
        float4 u = qp4[i];
        q[4*i+0] = u.x * 0.125f;
        q[4*i+1] = u.y * 0.125f;
        q[4*i+2] = u.z * 0.125f;
        q[4*i+3] = u.w * 0.125f;
    }

    float sc[2 * WINDOW + 1];
    float m = -1e30f;
    #pragma unroll 1
    for (int w = 0; w < 2 * WINDOW + 1; w++) {
        int j = s - WINDOW + w;
        const float4* kr4 = (const float4*)(Ks + (t + w) * KROW);
        float dot = 0.f;
        #pragma unroll
        for (int i = 0; i < 16; i++) {
            float4 kv = kr4[i];
            dot = fmaf(q[4*i+0], kv.x, dot);
            dot = fmaf(q[4*i+1], kv.y, dot);
            dot = fmaf(q[4*i+2], kv.z, dot);
            dot = fmaf(q[4*i+3], kv.w, dot);
        }
        dot = (j >= 0 && j < SEQ) ? dot : -1e30f;
        sc[w] = dot;
        m = fmaxf(m, dot);
    }

    float denom = 0.f;
    #pragma unroll
    for (int w = 0; w < 2 * WINDOW + 1; w++) {
        float e = __expf(sc[w] - m);
        sc[w] = e;
        denom += e;
    }
    float inv = 1.0f / denom;

    float o[HEAD_DIM];
    #pragma unroll
    for (int d = 0; d < HEAD_DIM; d++) o[d] = 0.f;
    #pragma unroll 1
    for (int w = 0; w < 2 * WINDOW + 1; w++) {
        float p = sc[w];
        const float4* vr4 = (const float4*)(Vs + (t + w) * KROW);
        #pragma unroll
        for (int i = 0; i < 16; i++) {
            float4 vv = vr4[i];
            o[4*i+0] = fmaf(p, vv.x, o[4*i+0]);
            o[4*i+1] = fmaf(p, vv.y, o[4*i+1]);
            o[4*i+2] = fmaf(p, vv.z, o[4*i+2]);
            o[4*i+3] = fmaf(p, vv.w, o[4*i+3]);
        }
    }

    size_t op = (size_t)(b * SEQ + s) * KX + h * HEAD_DIM;
    #pragma unroll
    for (int i = 0; i < 32; i++) {
        float v0 = o[2*i + 0] * inv;
        float v1 = o[2*i + 1] * inv;
        __nv_bfloat16 h0, l0, h1, l1;
        split_bf(v0, h0, l0);
        split_bf(v1, h1, l1);
        __nv_bfloat162 hp(h0, h1), lp(l0, l1);
        ((__nv_bfloat162*)(Ox + op))[i]          = hp;
        ((__nv_bfloat162*)(Ox + op + 1024))[i]   = hp;
        ((__nv_bfloat162*)(Ox + op + 2048))[i]   = lp;
    }
}

// ============================================================
// launch
// ============================================================
extern "C" void kernel_launch(void* const* d_in, const int* in_sizes, int n_in,
                              void* d_out, int out_size)
{
    (void)in_sizes; (void)n_in; (void)out_size;
    const float* x     = (const float*)d_in[0];
    const float* w_q   = (const float*)d_in[1];
    const float* b_q   = (const float*)d_in[2];
    const float* w_k   = (const float*)d_in[3];
    const float* b_k   = (const float*)d_in[4];
    const float* w_v   = (const float*)d_in[5];
    const float* b_v   = (const float*)d_in[6];
    const float* w_o   = (const float*)d_in[7];
    const float* b_o   = (const float*)d_in[8];
    const float* gamma = (const float*)d_in[9];
    const float* beta  = (const float*)d_in[10];
    float* out = (float*)d_out;

    void *pHx, *pWqkv, *pWo, *pBq, *pQKV, *pAx;
    cudaGetSymbolAddress(&pHx,   g_Hx);
    cudaGetSymbolAddress(&pWqkv, g_Wqkv);
    cudaGetSymbolAddress(&pWo,   g_Wo);
    cudaGetSymbolAddress(&pBq,   g_bqkv);
    cudaGetSymbolAddress(&pQKV,  g_QKV);
    cudaGetSymbolAddress(&pAx,   g_ATTx);
    __nv_bfloat16* Hx   = (__nv_bfloat16*)pHx;
    __nv_bfloat16* Wqkv = (__nv_bfloat16*)pWqkv;
    __nv_bfloat16* Wo   = (__nv_bfloat16*)pWo;
    float*         bqkv = (float*)pBq;
    float*         QKV  = (float*)pQKV;
    __nv_bfloat16* ATTx = (__nv_bfloat16*)pAx;

    cudaFuncSetAttribute(mm_kernel<false>, cudaFuncAttributeMaxDynamicSharedMemorySize, MM_SMEM);
    cudaFuncSetAttribute(mm_kernel<true>,  cudaFuncAttributeMaxDynamicSharedMemorySize, MM_SMEM);
    cudaFuncSetAttribute(attn_kernel, cudaFuncAttributeMaxDynamicSharedMemorySize, ATT_SMEM);

    // prep
    dim3 wb(32, 8);
    dim3 wg(32, 32, 4);
    wconv_kernel<<<wg, wb>>>(w_q, w_k, w_v, w_o, Wqkv, Wo);
    bconcat_kernel<<<(QKV_LD + 255) / 256, 256>>>(b_q, b_k, b_v, bqkv);
    ln_kernel<<<MROWS, 256>>>(x, gamma, beta, Hx);

    // fused QKV GEMM: [4096 x 3072]
    dim3 gq(QKV_LD / BN, MROWS / BM);     // (24, 32)
    mm_kernel<false><<<gq, 256, MM_SMEM>>>(Hx, Wqkv, bqkv, nullptr, QKV, QKV_LD);

    // attention
    dim3 ga(SEQ / QT, NUM_HEADS, BATCH);
    attn_kernel<<<ga, QT, ATT_SMEM>>>(QKV, ATTx);

    // output projection + bias + residual
    dim3 go(MODEL_DIM / BN, MROWS / BM);  // (8, 32)
    mm_kernel<true><<<go, 256, MM_SMEM>>>(ATTx, Wo, b_o, x, out, MODEL_DIM);
}

// round 8
// speedup vs baseline: 1.9388x; 1.8178x over previous
#include <cuda_runtime.h>
#include <cuda_bf16.h>
#include <cstdint>
#include <math.h>

// ---------------- problem constants ----------------
#define MODEL_DIM 1024
#define NUM_HEADS 16
#define HEAD_DIM  64
#define WINDOW    32
#define EPS       1e-5f
#define BATCH     2
#define SEQ       2048
#define MROWS     (BATCH * SEQ)      // 4096
#define QKV_LD    (3 * MODEL_DIM)    // 3072
#define KDIM      MODEL_DIM          // 1024
#define KT_PER_ROW (KDIM / 8)        // 128 k-tiles per row-block

// ---------------- scratch (fragment-ordered tf32) ----------------
__device__ float g_Hx  [MROWS / 16 * KT_PER_ROW * 128];      // 16 MB
__device__ float g_Wqkv[QKV_LD / 8 * KT_PER_ROW * 64];       // 12 MB
__device__ float g_Wo  [MODEL_DIM / 8 * KT_PER_ROW * 64];    // 4 MB
__device__ float g_bqkv[QKV_LD];
__device__ float g_QKV [MROWS * QKV_LD];                     // 48 MB fp32
__device__ float g_ATTx[MROWS / 16 * KT_PER_ROW * 128];      // 16 MB

// ---------------- helpers ----------------
__device__ __forceinline__ uint32_t smem_u32(const void* p) {
    uint32_t a;
    asm("{ .reg .u64 t; cvta.to.shared.u64 t, %1; cvt.u32.u64 %0, t; }" : "=r"(a) : "l"(p));
    return a;
}
__device__ __forceinline__ void cp_async16(uint32_t dst, const void* src) {
    asm volatile("cp.async.cg.shared.global [%0], [%1], 16;" :: "r"(dst), "l"(src) : "memory");
}
__device__ __forceinline__ void cp_commit() {
    asm volatile("cp.async.commit_group;" ::: "memory");
}
template<int N>
__device__ __forceinline__ void cp_wait() {
    asm volatile("cp.async.wait_group %0;" :: "n"(N) : "memory");
}
__device__ __forceinline__ void lds128(uint32_t* r, uint32_t a) {
    asm volatile("ld.shared.v4.b32 {%0,%1,%2,%3}, [%4];"
                 : "=r"(r[0]), "=r"(r[1]), "=r"(r[2]), "=r"(r[3]) : "r"(a));
}
__device__ __forceinline__ void lds64(uint32_t* r, uint32_t a) {
    asm volatile("ld.shared.v2.b32 {%0,%1}, [%2];"
                 : "=r"(r[0]), "=r"(r[1]) : "r"(a));
}
__device__ __forceinline__ void mma_tf32(float* c, const uint32_t* a, const uint32_t* b) {
    asm volatile("mma.sync.aligned.m16n8k8.row.col.f32.tf32.tf32.f32 "
                 "{%0,%1,%2,%3},{%4,%5,%6,%7},{%8,%9},{%0,%1,%2,%3};"
                 : "+f"(c[0]), "+f"(c[1]), "+f"(c[2]), "+f"(c[3])
                 : "r"(a[0]), "r"(a[1]), "r"(a[2]), "r"(a[3]), "r"(b[0]), "r"(b[1]));
}
__device__ __forceinline__ float to_tf32(float x) {
    float y;
    asm("cvt.rna.tf32.f32 %0, %1;" : "=f"(y) : "f"(x));
    return y;
}

// fragment offsets (floats within a tile)
// A tile 16(m) x 8(k): thread L, reg j  <->  float idx L*4+j
__device__ __forceinline__ int a_off(int r, int c) {
    return ((r & 7) * 4 + (c & 3)) * 4 + (r >> 3) + 2 * (c >> 2);
}
// B tile 8(k) x 8(n): thread L, reg j  <->  float idx L*2+j
__device__ __forceinline__ int b_off(int k, int n) {
    return (n * 4 + (k & 3)) * 2 + (k >> 2);
}

// ============================================================
// LayerNorm -> A-fragment-ordered tf32
// ============================================================
__global__ __launch_bounds__(256)
void ln_kernel(const float* __restrict__ x,
               const float* __restrict__ gamma,
               const float* __restrict__ beta,
               float* __restrict__ Hx)
{
    int row = blockIdx.x;
    int tid = threadIdx.x;
    float4 a = ((const float4*)(x + (size_t)row * MODEL_DIM))[tid];

    __shared__ float red[8];
    __shared__ float stat;

    float s = a.x + a.y + a.z + a.w;
    #pragma unroll
    for (int o = 16; o; o >>= 1) s += __shfl_xor_sync(0xffffffffu, s, o);
    if ((tid & 31) == 0) red[tid >> 5] = s;
    __syncthreads();
    if (tid == 0) {
        float t = 0.f;
        #pragma unroll
        for (int i = 0; i < 8; i++) t += red[i];
        stat = t * (1.0f / MODEL_DIM);
    }
    __syncthreads();
    float mu = stat;

    float dx = a.x - mu, dy = a.y - mu, dz = a.z - mu, dw = a.w - mu;
    float s2 = dx*dx + dy*dy + dz*dz + dw*dw;
    #pragma unroll
    for (int o = 16; o; o >>= 1) s2 += __shfl_xor_sync(0xffffffffu, s2, o);
    __syncthreads();
    if ((tid & 31) == 0) red[tid >> 5] = s2;
    __syncthreads();
    if (tid == 0) {
        float t = 0.f;
        #pragma unroll
        for (int i = 0; i < 8; i++) t += red[i];
        stat = rsqrtf(t * (1.0f / MODEL_DIM) + EPS);
    }
    __syncthreads();
    float rstd = stat;

    float4 g = ((const float4*)gamma)[tid];
    float4 b = ((const float4*)beta)[tid];
    float v[4];
    v[0] = dx * rstd * g.x + b.x;
    v[1] = dy * rstd * g.y + b.y;
    v[2] = dz * rstd * g.z + b.z;
    v[3] = dw * rstd * g.w + b.w;

    int mt = row >> 4, r = row & 15;
    int k0 = tid * 4;
    int kt = k0 >> 3;
    int c0 = k0 & 7;                  // 0 or 4
    float* tile = Hx + ((size_t)mt * KT_PER_ROW + kt) * 128;
    #pragma unroll
    for (int j = 0; j < 4; j++)
        tile[a_off(r, c0 + j)] = to_tf32(v[j]);
}

// ============================================================
// Weight -> B-fragment-ordered tf32.  w[K,N] row-major.
// ============================================================
__global__ __launch_bounds__(256)
void wconv_kernel(const float* __restrict__ wq, const float* __restrict__ wk,
                  const float* __restrict__ wv, const float* __restrict__ wo,
                  float* __restrict__ Wqkv, float* __restrict__ Wo)
{
    int bz = blockIdx.y;
    const float* w = (bz == 0) ? wq : (bz == 1) ? wk : (bz == 2) ? wv : wo;
    float* WT = (bz < 3) ? (Wqkv + (size_t)bz * (1024 / 8) * KT_PER_ROW * 64) : Wo;

    int idx = blockIdx.x * 256 + threadIdx.x;      // 1024*1024 elements
    int k = idx >> 10;
    int n = idx & 1023;
    float v = to_tf32(w[idx]);
    int nt = n >> 3, kt = k >> 3;
    WT[((size_t)nt * KT_PER_ROW + kt) * 64 + b_off(k & 7, n & 7)] = v;
}

__global__ void bconcat_kernel(const float* __restrict__ bq,
                               const float* __restrict__ bk,
                               const float* __restrict__ bv,
                               float* __restrict__ dst)
{
    int i = blockIdx.x * 256 + threadIdx.x;
    if (i >= QKV_LD) return;
    const float* s = (i < 1024) ? bq : (i < 2048 ? bk : bv);
    dst[i] = s[i & 1023];
}

// ============================================================
// tf32 mma.sync GEMM. CTA 128x128x32, 8 warps (64x32), 3-stage
// cp.async, fragment-ordered smem (conflict-free lds.128/lds.64).
// ============================================================
#define BM 128
#define BN 128
#define BK 32
#define A_TILE 16384                  // 8 mt x 4 kt x 512 B
#define B_TILE 16384                  // 16 nt x 4 kt x 256 B
#define STAGE_BYTES (A_TILE + B_TILE) // 32768
#define NSTAGE 3
#define NIT (KDIM / BK)               // 32
#define MM_SMEM (NSTAGE * STAGE_BYTES)// 98304

__device__ __forceinline__ void stage_A(const float* __restrict__ src,
                                        int mt0, int kt0, uint32_t dst)
{
    #pragma unroll
    for (int p = 0; p < 4; p++) {
        int ch = threadIdx.x + p * 256;      // 1024 chunks of 16B
        int tl = ch >> 5;                    // tile linear = mti*4+kti
        int in = ch & 31;
        int mti = tl >> 2, kti = tl & 3;
        const char* g = (const char*)(src + ((size_t)(mt0 + mti) * KT_PER_ROW + kt0 + kti) * 128) + in * 16;
        cp_async16(dst + (uint32_t)tl * 512 + in * 16, g);
    }
}
__device__ __forceinline__ void stage_B(const float* __restrict__ src,
                                        int nt0, int kt0, uint32_t dst)
{
    #pragma unroll
    for (int p = 0; p < 4; p++) {
        int ch = threadIdx.x + p * 256;
        int tl = ch >> 4;                    // tile linear = nti*4+kti
        int in = ch & 15;
        int nti = tl >> 2, kti = tl & 3;
        const char* g = (const char*)(src + ((size_t)(nt0 + nti) * KT_PER_ROW + kt0 + kti) * 64) + in * 16;
        cp_async16(dst + (uint32_t)tl * 256 + in * 16, g);
    }
}

template<bool RESID>
__global__ __launch_bounds__(256, 2)
void mm_kernel(const float* __restrict__ A,
               const float* __restrict__ B,
               const float* __restrict__ bias,
               const float* __restrict__ resid,
               float* __restrict__ C, int ldc)
{
    extern __shared__ char smem[];
    uint32_t sb = smem_u32(smem);

    int tid  = threadIdx.x;
    int wid  = tid >> 5;
    int lane = tid & 31;
    int mtb = (wid >> 2) * 4;            // warp m tile base (0/4)
    int ntb = (wid & 3) * 4;             // warp n tile base (0/4/8/12)
    int mt0 = blockIdx.y * 8;
    int nt0 = blockIdx.x * 16;

    float acc[4][4][4];
    #pragma unroll
    for (int i = 0; i < 4; i++)
        #pragma unroll
        for (int j = 0; j < 4; j++)
            #pragma unroll
            for (int q = 0; q < 4; q++) acc[i][j][q] = 0.f;

    // prologue: stage slabs 0, 1
    stage_A(A, mt0, 0, sb);
    stage_B(B, nt0, 0, sb + A_TILE);
    cp_commit();
    stage_A(A, mt0, 4, sb + STAGE_BYTES);
    stage_B(B, nt0, 4, sb + STAGE_BYTES + A_TILE);
    cp_commit();

    uint32_t aoff = (uint32_t)lane * 16;
    uint32_t boff = (uint32_t)lane * 8;

    #pragma unroll 1
    for (int it = 0; it < NIT; it++) {
        cp_wait<1>();
        __syncthreads();

        if (it + 2 < NIT) {
            uint32_t nb = sb + (uint32_t)((it + 2) % NSTAGE) * STAGE_BYTES;
            stage_A(A, mt0, (it + 2) * 4, nb);
            stage_B(B, nt0, (it + 2) * 4, nb + A_TILE);
        }
        cp_commit();

        uint32_t aB = sb + (uint32_t)(it % NSTAGE) * STAGE_BYTES;
        uint32_t bB = aB + A_TILE;

        #pragma unroll
        for (int kti = 0; kti < 4; kti++) {
            uint32_t af[4][4];
            uint32_t bfr[4][2];
            #pragma unroll
            for (int i = 0; i < 4; i++)
                lds128(af[i], aB + (uint32_t)((mtb + i) * 4 + kti) * 512 + aoff);
            #pragma unroll
            for (int j = 0; j < 4; j++)
                lds64(bfr[j], bB + (uint32_t)((ntb + j) * 4 + kti) * 256 + boff);
            #pragma unroll
            for (int i = 0; i < 4; i++)
                #pragma unroll
                for (int j = 0; j < 4; j++)
                    mma_tf32(acc[i][j], af[i], bfr[j]);
        }
    }

    // epilogue
    int mBase = mt0 * 16 + mtb * 16 + (lane >> 2);
    int nBase = nt0 * 8 + ntb * 8 + (lane & 3) * 2;
    #pragma unroll
    for (int i = 0; i < 4; i++) {
        int m0 = mBase + i * 16;
        #pragma unroll
        for (int j = 0; j < 4; j++) {
            int n = nBase + j * 8;
            float bx0 = bias[n], bx1 = bias[n + 1];
            float2 v0, v1;
            v0.x = acc[i][j][0] + bx0;
            v0.y = acc[i][j][1] + bx1;
            v1.x = acc[i][j][2] + bx0;
            v1.y = acc[i][j][3] + bx1;
            if (RESID) {
                float2 r0 = *(const float2*)(resid + (size_t)m0 * MODEL_DIM + n);
                float2 r1 = *(const float2*)(resid + (size_t)(m0 + 8) * MODEL_DIM + n);
                v0.x += r0.x; v0.y += r0.y;
                v1.x += r1.x; v1.y += r1.y;
            }
            *(float2*)(C + (size_t)m0 * ldc + n)       = v0;
            *(float2*)(C + (size_t)(m0 + 8) * ldc + n) = v1;
        }
    }
}

// ============================================================
// Sliding-window attention; epilogue writes A-fragment tf32
// ============================================================
#define QT 128
#define NS (QT + 2 * WINDOW)    // 192
#define KROW 68
#define ATT_SMEM (2 * NS * KROW * 4)   // 104448

__global__ __launch_bounds__(QT)
void attn_kernel(const float* __restrict__ QKV,
                 float* __restrict__ Ox)
{
    extern __shared__ float sm[];
    float* Ks = sm;
    float* Vs = sm + NS * KROW;

    int qt = blockIdx.x * QT;
    int h  = blockIdx.y;
    int b  = blockIdx.z;
    int t  = threadIdx.x;
    size_t base = (size_t)b * SEQ * QKV_LD;

    for (int idx = t; idx < NS * 16; idx += QT) {
        int kk = idx >> 4;
        int c  = idx & 15;
        int j  = qt - WINDOW + kk;
        float4 kv = make_float4(0.f, 0.f, 0.f, 0.f);
        float4 vv = kv;
        if (j >= 0 && j < SEQ) {
            const float* p = QKV + base + (size_t)j * QKV_LD + h * HEAD_DIM + c * 4;
            kv = *(const float4*)(p + MODEL_DIM);
            vv = *(const float4*)(p + 2 * MODEL_DIM);
        }
        *(float4*)(Ks + kk * KROW + c * 4) = kv;
        *(float4*)(Vs + kk * KROW + c * 4) = vv;
    }
    __syncthreads();

    int s = qt + t;
    const float4* qp4 = (const float4*)(QKV + base + (size_t)s * QKV_LD + h * HEAD_DIM);
    float q[HEAD_DIM];
    #pragma unroll
    for (int i = 0; i < 16; i++) {
        float4 u = qp4[i];
        q[4*i+0] = u.x * 0.125f;
        q[4*i+1] = u.y * 0.125f;
        q[4*i+2] = u.z * 0.125f;
        q[4*i+3] = u.w * 0.125f;
    }

    float sc[2 * WINDOW + 1];
    float m = -1e30f;
    #pragma unroll 1
    for (int w = 0; w < 2 * WINDOW + 1; w++) {
        int j = s - WINDOW + w;
        const float4* kr4 = (const float4*)(Ks + (t + w) * KROW);
        float dot = 0.f;
        #pragma unroll
        for (int i = 0; i < 16; i++) {
            float4 kv = kr4[i];
            dot = fmaf(q[4*i+0], kv.x, dot);
            dot = fmaf(q[4*i+1], kv.y, dot);
            dot = fmaf(q[4*i+2], kv.z, dot);
            dot = fmaf(q[4*i+3], kv.w, dot);
        }
        dot = (j >= 0 && j < SEQ) ? dot : -1e30f;
        sc[w] = dot;
        m = fmaxf(m, dot);
    }

    float denom = 0.f;
    #pragma unroll
    for (int w = 0; w < 2 * WINDOW + 1; w++) {
        float e = __expf(sc[w] - m);
        sc[w] = e;
        denom += e;
    }
    float inv = 1.0f / denom;

    float o[HEAD_DIM];
    #pragma unroll
    for (int d = 0; d < HEAD_DIM; d++) o[d] = 0.f;
    #pragma unroll 1
    for (int w = 0; w < 2 * WINDOW + 1; w++) {
        float p = sc[w];
        const float4* vr4 = (const float4*)(Vs + (t + w) * KROW);
        #pragma unroll
        for (int i = 0; i < 16; i++) {
            float4 vv = vr4[i];
            o[4*i+0] = fmaf(p, vv.x, o[4*i+0]);
            o[4*i+1] = fmaf(p, vv.y, o[4*i+1]);
            o[4*i+2] = fmaf(p, vv.z, o[4*i+2]);
            o[4*i+3] = fmaf(p, vv.w, o[4*i+3]);
        }
    }

    // write A-fragment-ordered tf32
    int mrow = b * SEQ + s;
    int mt = mrow >> 4, r = mrow & 15;
    #pragma unroll
    for (int i = 0; i < HEAD_DIM; i++) {
        int k = h * HEAD_DIM + i;
        int kt = k >> 3, c = k & 7;
        Ox[((size_t)mt * KT_PER_ROW + kt) * 128 + a_off(r, c)] = to_tf32(o[i] * inv);
    }
}

// ============================================================
// launch
// ============================================================
extern "C" void kernel_launch(void* const* d_in, const int* in_sizes, int n_in,
                              void* d_out, int out_size)
{
    (void)in_sizes; (void)n_in; (void)out_size;
    const float* x     = (const float*)d_in[0];
    const float* w_q   = (const float*)d_in[1];
    const float* b_q   = (const float*)d_in[2];
    const float* w_k   = (const float*)d_in[3];
    const float* b_k   = (const float*)d_in[4];
    const float* w_v   = (const float*)d_in[5];
    const float* b_v   = (const float*)d_in[6];
    const float* w_o   = (const float*)d_in[7];
    const float* b_o   = (const float*)d_in[8];
    const float* gamma = (const float*)d_in[9];
    const float* beta  = (const float*)d_in[10];
    float* out = (float*)d_out;

    void *pHx, *pWqkv, *pWo, *pBq, *pQKV, *pAx;
    cudaGetSymbolAddress(&pHx,   g_Hx);
    cudaGetSymbolAddress(&pWqkv, g_Wqkv);
    cudaGetSymbolAddress(&pWo,   g_Wo);
    cudaGetSymbolAddress(&pBq,   g_bqkv);
    cudaGetSymbolAddress(&pQKV,  g_QKV);
    cudaGetSymbolAddress(&pAx,   g_ATTx);
    float* Hx   = (float*)pHx;
    float* Wqkv = (float*)pWqkv;
    float* Wo   = (float*)pWo;
    float* bqkv = (float*)pBq;
    float* QKV  = (float*)pQKV;
    float* ATTx = (float*)pAx;

    cudaFuncSetAttribute(mm_kernel<false>, cudaFuncAttributeMaxDynamicSharedMemorySize, MM_SMEM);
    cudaFuncSetAttribute(mm_kernel<true>,  cudaFuncAttributeMaxDynamicSharedMemorySize, MM_SMEM);
    cudaFuncSetAttribute(attn_kernel, cudaFuncAttributeMaxDynamicSharedMemorySize, ATT_SMEM);

    // prep
    wconv_kernel<<<dim3(1024 * 1024 / 256, 4), 256>>>(w_q, w_k, w_v, w_o, Wqkv, Wo);
    bconcat_kernel<<<(QKV_LD + 255) / 256, 256>>>(b_q, b_k, b_v, bqkv);
    ln_kernel<<<MROWS, 256>>>(x, gamma, beta, Hx);

    // fused QKV GEMM: [4096 x 3072] = Hx @ Wqkv^T
    dim3 gq(QKV_LD / BN, MROWS / BM);     // (24, 32)
    mm_kernel<false><<<gq, 256, MM_SMEM>>>(Hx, Wqkv, bqkv, nullptr, QKV, QKV_LD);

    // attention
    dim3 ga(SEQ / QT, NUM_HEADS, BATCH);
    attn_kernel<<<ga, QT, ATT_SMEM>>>(QKV, ATTx);

    // output projection + bias + residual
    dim3 go(MODEL_DIM / BN, MROWS / BM);  // (8, 32)
    mm_kernel<true><<<go, 256, MM_SMEM>>>(ATTx, Wo, b_o, x, out, MODEL_DIM);
}

// round 9
// speedup vs baseline: 2.2186x; 1.1443x over previous
#include <cuda_runtime.h>
#include <cuda_bf16.h>
#include <cstdint>
#include <math.h>

// ---------------- problem constants ----------------
#define MODEL_DIM 1024
#define NUM_HEADS 16
#define HEAD_DIM  64
#define WINDOW    32
#define EPS       1e-5f
#define BATCH     2
#define SEQ       2048
#define MROWS     (BATCH * SEQ)      // 4096
#define QKV_LD    (3 * MODEL_DIM)    // 3072
#define KDIM      MODEL_DIM          // 1024
#define KT_PER_ROW (KDIM / 8)        // 128

// ---------------- scratch (fragment-ordered tf32) ----------------
__device__ float g_Hx  [MROWS / 16 * KT_PER_ROW * 128];
__device__ float g_Wqkv[QKV_LD / 8 * KT_PER_ROW * 64];
__device__ float g_Wo  [MODEL_DIM / 8 * KT_PER_ROW * 64];
__device__ float g_bqkv[QKV_LD];
__device__ float g_QKV [MROWS * QKV_LD];
__device__ float g_ATTx[MROWS / 16 * KT_PER_ROW * 128];

// ---------------- helpers ----------------
__device__ __forceinline__ uint32_t smem_u32(const void* p) {
    uint32_t a;
    asm("{ .reg .u64 t; cvta.to.shared.u64 t, %1; cvt.u32.u64 %0, t; }" : "=r"(a) : "l"(p));
    return a;
}
__device__ __forceinline__ void cp_async16(uint32_t dst, const void* src) {
    asm volatile("cp.async.cg.shared.global [%0], [%1], 16;" :: "r"(dst), "l"(src) : "memory");
}
__device__ __forceinline__ void cp_commit() {
    asm volatile("cp.async.commit_group;" ::: "memory");
}
template<int N>
__device__ __forceinline__ void cp_wait() {
    asm volatile("cp.async.wait_group %0;" :: "n"(N) : "memory");
}
__device__ __forceinline__ void lds128(uint32_t* r, uint32_t a) {
    asm volatile("ld.shared.v4.b32 {%0,%1,%2,%3}, [%4];"
                 : "=r"(r[0]), "=r"(r[1]), "=r"(r[2]), "=r"(r[3]) : "r"(a));
}
__device__ __forceinline__ void lds64(uint32_t* r, uint32_t a) {
    asm volatile("ld.shared.v2.b32 {%0,%1}, [%2];"
                 : "=r"(r[0]), "=r"(r[1]) : "r"(a));
}
__device__ __forceinline__ void mma_tf32(float* c, const uint32_t* a, const uint32_t* b) {
    asm volatile("mma.sync.aligned.m16n8k8.row.col.f32.tf32.tf32.f32 "
                 "{%0,%1,%2,%3},{%4,%5,%6,%7},{%8,%9},{%0,%1,%2,%3};"
                 : "+f"(c[0]), "+f"(c[1]), "+f"(c[2]), "+f"(c[3])
                 : "r"(a[0]), "r"(a[1]), "r"(a[2]), "r"(a[3]), "r"(b[0]), "r"(b[1]));
}
__device__ __forceinline__ float to_tf32(float x) {
    float y;
    asm("cvt.rna.tf32.f32 %0, %1;" : "=f"(y) : "f"(x));
    return y;
}

// A tile 16(m) x 8(k): thread L, reg j <-> float idx L*4+j
__device__ __forceinline__ int a_off(int r, int c) {
    return ((r & 7) * 4 + (c & 3)) * 4 + (r >> 3) + 2 * (c >> 2);
}
// B tile 8(k) x 8(n): thread L, reg j <-> float idx L*2+j
__device__ __forceinline__ int b_off(int k, int n) {
    return (n * 4 + (k & 3)) * 2 + (k >> 2);
}

// ============================================================
// LayerNorm -> A-fragment-ordered tf32
// ============================================================
__global__ __launch_bounds__(256)
void ln_kernel(const float* __restrict__ x,
               const float* __restrict__ gamma,
               const float* __restrict__ beta,
               float* __restrict__ Hx)
{
    int row = blockIdx.x;
    int tid = threadIdx.x;
    float4 a = ((const float4*)(x + (size_t)row * MODEL_DIM))[tid];

    __shared__ float red[8];
    __shared__ float stat;

    float s = a.x + a.y + a.z + a.w;
    #pragma unroll
    for (int o = 16; o; o >>= 1) s += __shfl_xor_sync(0xffffffffu, s, o);
    if ((tid & 31) == 0) red[tid >> 5] = s;
    __syncthreads();
    if (tid == 0) {
        float t = 0.f;
        #pragma unroll
        for (int i = 0; i < 8; i++) t += red[i];
        stat = t * (1.0f / MODEL_DIM);
    }
    __syncthreads();
    float mu = stat;

    float dx = a.x - mu, dy = a.y - mu, dz = a.z - mu, dw = a.w - mu;
    float s2 = dx*dx + dy*dy + dz*dz + dw*dw;
    #pragma unroll
    for (int o = 16; o; o >>= 1) s2 += __shfl_xor_sync(0xffffffffu, s2, o);
    __syncthreads();
    if ((tid & 31) == 0) red[tid >> 5] = s2;
    __syncthreads();
    if (tid == 0) {
        float t = 0.f;
        #pragma unroll
        for (int i = 0; i < 8; i++) t += red[i];
        stat = rsqrtf(t * (1.0f / MODEL_DIM) + EPS);
    }
    __syncthreads();
    float rstd = stat;

    float4 g = ((const float4*)gamma)[tid];
    float4 b = ((const float4*)beta)[tid];
    float v[4];
    v[0] = dx * rstd * g.x + b.x;
    v[1] = dy * rstd * g.y + b.y;
    v[2] = dz * rstd * g.z + b.z;
    v[3] = dw * rstd * g.w + b.w;

    int mt = row >> 4, r = row & 15;
    int k0 = tid * 4;
    int kt = k0 >> 3;
    int c0 = k0 & 7;
    float* tile = Hx + ((size_t)mt * KT_PER_ROW + kt) * 128;
    #pragma unroll
    for (int j = 0; j < 4; j++)
        tile[a_off(r, c0 + j)] = to_tf32(v[j]);
}

// ============================================================
// Weight -> B-fragment-ordered tf32
// ============================================================
__global__ __launch_bounds__(256)
void wconv_kernel(const float* __restrict__ wq, const float* __restrict__ wk,
                  const float* __restrict__ wv, const float* __restrict__ wo,
                  float* __restrict__ Wqkv, float* __restrict__ Wo)
{
    int bz = blockIdx.y;
    const float* w = (bz == 0) ? wq : (bz == 1) ? wk : (bz == 2) ? wv : wo;
    float* WT = (bz < 3) ? (Wqkv + (size_t)bz * (1024 / 8) * KT_PER_ROW * 64) : Wo;

    int idx = blockIdx.x * 256 + threadIdx.x;
    int k = idx >> 10;
    int n = idx & 1023;
    float v = to_tf32(w[idx]);
    int nt = n >> 3, kt = k >> 3;
    WT[((size_t)nt * KT_PER_ROW + kt) * 64 + b_off(k & 7, n & 7)] = v;
}

__global__ void bconcat_kernel(const float* __restrict__ bq,
                               const float* __restrict__ bk,
                               const float* __restrict__ bv,
                               float* __restrict__ dst)
{
    int i = blockIdx.x * 256 + threadIdx.x;
    if (i >= QKV_LD) return;
    const float* s = (i < 1024) ? bq : (i < 2048 ? bk : bv);
    dst[i] = s[i & 1023];
}

// ============================================================
// tf32 mma.sync GEMM (proven R8 config)
// ============================================================
#define BM 128
#define BN 128
#define BK 32
#define A_TILE 16384
#define B_TILE 16384
#define STAGE_BYTES (A_TILE + B_TILE)
#define NSTAGE 3
#define NIT (KDIM / BK)
#define MM_SMEM (NSTAGE * STAGE_BYTES)

__device__ __forceinline__ void stage_A(const float* __restrict__ src,
                                        int mt0, int kt0, uint32_t dst)
{
    #pragma unroll
    for (int p = 0; p < 4; p++) {
        int ch = threadIdx.x + p * 256;
        int tl = ch >> 5;
        int in = ch & 31;
        int mti = tl >> 2, kti = tl & 3;
        const char* g = (const char*)(src + ((size_t)(mt0 + mti) * KT_PER_ROW + kt0 + kti) * 128) + in * 16;
        cp_async16(dst + (uint32_t)tl * 512 + in * 16, g);
    }
}
__device__ __forceinline__ void stage_B(const float* __restrict__ src,
                                        int nt0, int kt0, uint32_t dst)
{
    #pragma unroll
    for (int p = 0; p < 4; p++) {
        int ch = threadIdx.x + p * 256;
        int tl = ch >> 4;
        int in = ch & 15;
        int nti = tl >> 2, kti = tl & 3;
        const char* g = (const char*)(src + ((size_t)(nt0 + nti) * KT_PER_ROW + kt0 + kti) * 64) + in * 16;
        cp_async16(dst + (uint32_t)tl * 256 + in * 16, g);
    }
}

template<bool RESID>
__global__ __launch_bounds__(256, 2)
void mm_kernel(const float* __restrict__ A,
               const float* __restrict__ B,
               const float* __restrict__ bias,
               const float* __restrict__ resid,
               float* __restrict__ C, int ldc)
{
    extern __shared__ char smem[];
    uint32_t sb = smem_u32(smem);

    int tid  = threadIdx.x;
    int wid  = tid >> 5;
    int lane = tid & 31;
    int mtb = (wid >> 2) * 4;
    int ntb = (wid & 3) * 4;
    int mt0 = blockIdx.y * 8;
    int nt0 = blockIdx.x * 16;

    float acc[4][4][4];
    #pragma unroll
    for (int i = 0; i < 4; i++)
        #pragma unroll
        for (int j = 0; j < 4; j++)
            #pragma unroll
            for (int q = 0; q < 4; q++) acc[i][j][q] = 0.f;

    stage_A(A, mt0, 0, sb);
    stage_B(B, nt0, 0, sb + A_TILE);
    cp_commit();
    stage_A(A, mt0, 4, sb + STAGE_BYTES);
    stage_B(B, nt0, 4, sb + STAGE_BYTES + A_TILE);
    cp_commit();

    uint32_t aoff = (uint32_t)lane * 16;
    uint32_t boff = (uint32_t)lane * 8;

    #pragma unroll 1
    for (int it = 0; it < NIT; it++) {
        cp_wait<1>();
        __syncthreads();

        if (it + 2 < NIT) {
            uint32_t nb = sb + (uint32_t)((it + 2) % NSTAGE) * STAGE_BYTES;
            stage_A(A, mt0, (it + 2) * 4, nb);
            stage_B(B, nt0, (it + 2) * 4, nb + A_TILE);
        }
        cp_commit();

        uint32_t aB = sb + (uint32_t)(it % NSTAGE) * STAGE_BYTES;
        uint32_t bB = aB + A_TILE;

        #pragma unroll
        for (int kti = 0; kti < 4; kti++) {
            uint32_t af[4][4];
            uint32_t bfr[4][2];
            #pragma unroll
            for (int i = 0; i < 4; i++)
                lds128(af[i], aB + (uint32_t)((mtb + i) * 4 + kti) * 512 + aoff);
            #pragma unroll
            for (int j = 0; j < 4; j++)
                lds64(bfr[j], bB + (uint32_t)((ntb + j) * 4 + kti) * 256 + boff);
            #pragma unroll
            for (int i = 0; i < 4; i++)
                #pragma unroll
                for (int j = 0; j < 4; j++)
                    mma_tf32(acc[i][j], af[i], bfr[j]);
        }
    }

    int mBase = mt0 * 16 + mtb * 16 + (lane >> 2);
    int nBase = nt0 * 8 + ntb * 8 + (lane & 3) * 2;
    #pragma unroll
    for (int i = 0; i < 4; i++) {
        int m0 = mBase + i * 16;
        #pragma unroll
        for (int j = 0; j < 4; j++) {
            int n = nBase + j * 8;
            float bx0 = bias[n], bx1 = bias[n + 1];
            float2 v0, v1;
            v0.x = acc[i][j][0] + bx0;
            v0.y = acc[i][j][1] + bx1;
            v1.x = acc[i][j][2] + bx0;
            v1.y = acc[i][j][3] + bx1;
            if (RESID) {
                float2 r0 = *(const float2*)(resid + (size_t)m0 * MODEL_DIM + n);
                float2 r1 = *(const float2*)(resid + (size_t)(m0 + 8) * MODEL_DIM + n);
                v0.x += r0.x; v0.y += r0.y;
                v1.x += r1.x; v1.y += r1.y;
            }
            *(float2*)(C + (size_t)m0 * ldc + n)       = v0;
            *(float2*)(C + (size_t)(m0 + 8) * ldc + n) = v1;
        }
    }
}

// ============================================================
// Banded MMA attention.
// Block = 64 queries x 1 head x 1 batch, 256 threads (8 warps).
// Window rows: 128 (q0-32 .. q0+95). Band: per 16-row m-tile,
// 10 col-tiles (cols 16m..16m+79) cover all 65-wide windows.
// ============================================================
#define AQT 64
#define ANW 128                       // window rows
// smem float offsets
#define SQ_F 0                        // Qf: 4*8*128 = 4096
#define SK_F 4096                     // Kf: 16*8*64 = 8192
#define SV_F 12288                    // Vf: 8*16*64 = 8192
#define SP_F 20480                    // Pf: 4*10*128 = 5120
#define SI_F 25600                    // inv: 64
#define ATT_SMEM ((25600 + 64) * 4)   // 102656 B

__global__ __launch_bounds__(256, 2)
void attn_kernel(const float* __restrict__ QKV,
                 float* __restrict__ Ox)
{
    extern __shared__ float sf[];
    uint32_t sb = smem_u32(sf);
    float* Qf  = sf + SQ_F;
    float* Kf  = sf + SK_F;
    float* Vf  = sf + SV_F;
    float* Pf  = sf + SP_F;
    float* inv = sf + SI_F;

    int tid = threadIdx.x;
    int q0  = blockIdx.x * AQT;
    int h   = blockIdx.y;
    int b   = blockIdx.z;
    size_t base = (size_t)b * SEQ * QKV_LD;

    // ---- stage Q (scaled, tf32, A-frag) ----
    #pragma unroll
    for (int i = 0; i < 4; i++) {
        int idx4 = tid + i * 256;            // 0..1023
        int r  = idx4 >> 4;                  // 0..63
        int c4 = idx4 & 15;
        float4 v = *(const float4*)(QKV + base + (size_t)(q0 + r) * QKV_LD + h * HEAD_DIM + c4 * 4);
        int mt = r >> 4, rr = r & 15;
        float vv[4] = {v.x, v.y, v.z, v.w};
        #pragma unroll
        for (int j = 0; j < 4; j++) {
            int c = c4 * 4 + j;
            Qf[((mt * 8) + (c >> 3)) * 128 + a_off(rr, c & 7)] = to_tf32(vv[j] * 0.125f);
        }
    }
    // ---- stage K (B-frag for S = Q K^T) and V (B-frag for O = P V) ----
    #pragma unroll
    for (int i = 0; i < 8; i++) {
        int idx4 = tid + i * 256;            // 0..2047
        int jrow = idx4 >> 4;                // 0..127
        int c4   = idx4 & 15;
        int gk = q0 - WINDOW + jrow;
        float4 kv = make_float4(0.f, 0.f, 0.f, 0.f);
        float4 vv = kv;
        if (gk >= 0 && gk < SEQ) {
            const float* p = QKV + base + (size_t)gk * QKV_LD + h * HEAD_DIM + c4 * 4;
            kv = *(const float4*)(p + MODEL_DIM);
            vv = *(const float4*)(p + 2 * MODEL_DIM);
        }
        float ka[4] = {kv.x, kv.y, kv.z, kv.w};
        float va[4] = {vv.x, vv.y, vv.z, vv.w};
        #pragma unroll
        for (int j = 0; j < 4; j++) {
            int d = c4 * 4 + j;
            // K: nt=key tile, kt=dim tile, b_off(dim, key)
            Kf[((jrow >> 3) * 8 + (d >> 3)) * 64 + b_off(d & 7, jrow & 7)] = to_tf32(ka[j]);
            // V: nt=dim tile, kt=token tile, b_off(token, dim)
            Vf[((d >> 3) * 16 + (jrow >> 3)) * 64 + b_off(jrow & 7, d & 7)] = to_tf32(va[j]);
        }
    }
    __syncthreads();

    int w  = tid >> 5;
    int L  = tid & 31;
    int mt = w >> 1;
    int half = w & 1;

    // ---- GEMM1: banded S, C stored to Pf in A-frag order ----
    {
        uint32_t qbase = sb + SQ_F * 4;
        uint32_t kbase = sb + SK_F * 4;
        uint32_t af[8][4];
        #pragma unroll
        for (int kt = 0; kt < 8; kt++)
            lds128(af[kt], qbase + (uint32_t)((mt * 8 + kt) * 128 + L * 4) * 4);
        #pragma unroll
        for (int nn = 0; nn < 5; nn++) {
            int ntl = half * 5 + nn;
            int ntg = 2 * mt + ntl;
            float acc[4] = {0.f, 0.f, 0.f, 0.f};
            #pragma unroll
            for (int kt = 0; kt < 8; kt++) {
                uint32_t bfr[2];
                lds64(bfr, kbase + (uint32_t)((ntg * 8 + kt) * 64 + L * 2) * 4);
                mma_tf32(acc, af[kt], bfr);
            }
            int r = L >> 2, c = (L & 3) * 2;
            float* Pt = Pf + (mt * 10 + ntl) * 128;
            Pt[a_off(r, c)]         = acc[0];
            Pt[a_off(r, c + 1)]     = acc[1];
            Pt[a_off(r + 8, c)]     = acc[2];
            Pt[a_off(r + 8, c + 1)] = acc[3];
        }
    }
    __syncthreads();

    // ---- softmax: 4 threads per row, 20 cols each ----
    {
        int row  = tid >> 2;                 // 0..63
        int part = tid & 3;
        int rmt = row >> 4, r = row & 15;
        float* Pb = Pf + rmt * 10 * 128;
        int jb = rmt * 16;

        float mx = -1e30f;
        #pragma unroll
        for (int u = 0; u < 20; u++) {
            int jl = part * 20 + u;
            int J  = jb + jl;
            int gk = q0 - WINDOW + J;
            bool valid = (J >= row) && (J <= row + 64) && (gk >= 0) && (gk < SEQ);
            float s = Pb[(jl >> 3) * 128 + a_off(r, jl & 7)];
            if (valid) mx = fmaxf(mx, s);
        }
        mx = fmaxf(mx, __shfl_xor_sync(0xffffffffu, mx, 1));
        mx = fmaxf(mx, __shfl_xor_sync(0xffffffffu, mx, 2));

        float sum = 0.f;
        #pragma unroll
        for (int u = 0; u < 20; u++) {
            int jl = part * 20 + u;
            int J  = jb + jl;
            int gk = q0 - WINDOW + J;
            bool valid = (J >= row) && (J <= row + 64) && (gk >= 0) && (gk < SEQ);
            int off = (jl >> 3) * 128 + a_off(r, jl & 7);
            float e = valid ? __expf(Pb[off] - mx) : 0.f;
            sum += e;
            Pb[off] = to_tf32(e);
        }
        sum += __shfl_xor_sync(0xffffffffu, sum, 1);
        sum += __shfl_xor_sync(0xffffffffu, sum, 2);
        if (part == 0) inv[row] = 1.0f / sum;
    }
    __syncthreads();

    // ---- GEMM2: O = P V (banded K-dim), epilogue -> ATTx (A-frag tf32) ----
    {
        uint32_t pbase = sb + SP_F * 4;
        uint32_t vbase = sb + SV_F * 4;
        int ntd0 = half * 4;
        float acc2[4][4];
        #pragma unroll
        for (int j = 0; j < 4; j++)
            #pragma unroll
            for (int q = 0; q < 4; q++) acc2[j][q] = 0.f;

        #pragma unroll
        for (int ktl = 0; ktl < 10; ktl++) {
            int kt_tok = 2 * mt + ktl;
            uint32_t af[4];
            lds128(af, pbase + (uint32_t)((mt * 10 + ktl) * 128 + L * 4) * 4);
            #pragma unroll
            for (int jn = 0; jn < 4; jn++) {
                uint32_t bfr[2];
                lds64(bfr, vbase + (uint32_t)(((ntd0 + jn) * 16 + kt_tok) * 64 + L * 2) * 4);
                mma_tf32(acc2[jn], af, bfr);
            }
        }

        int r0 = mt * 16 + (L >> 2);          // local query row
        float i0 = inv[r0], i1 = inv[r0 + 8];
        int grow0 = b * SEQ + q0 + r0;
        int grow1 = grow0 + 8;
        #pragma unroll
        for (int jn = 0; jn < 4; jn++) {
            int col = h * HEAD_DIM + (ntd0 + jn) * 8 + (L & 3) * 2;
            size_t t0 = ((size_t)(grow0 >> 4) * KT_PER_ROW + (col >> 3)) * 128;
            size_t t1 = ((size_t)(grow1 >> 4) * KT_PER_ROW + (col >> 3)) * 128;
            Ox[t0 + a_off(grow0 & 15, col & 7)]       = to_tf32(acc2[jn][0] * i0);
            Ox[t0 + a_off(grow0 & 15, (col + 1) & 7)] = to_tf32(acc2[jn][1] * i0);
            Ox[t1 + a_off(grow1 & 15, col & 7)]       = to_tf32(acc2[jn][2] * i1);
            Ox[t1 + a_off(grow1 & 15, (col + 1) & 7)] = to_tf32(acc2[jn][3] * i1);
        }
    }
}

// ============================================================
// launch
// ============================================================
extern "C" void kernel_launch(void* const* d_in, const int* in_sizes, int n_in,
                              void* d_out, int out_size)
{
    (void)in_sizes; (void)n_in; (void)out_size;
    const float* x     = (const float*)d_in[0];
    const float* w_q   = (const float*)d_in[1];
    const float* b_q   = (const float*)d_in[2];
    const float* w_k   = (const float*)d_in[3];
    const float* b_k   = (const float*)d_in[4];
    const float* w_v   = (const float*)d_in[5];
    const float* b_v   = (const float*)d_in[6];
    const float* w_o   = (const float*)d_in[7];
    const float* b_o   = (const float*)d_in[8];
    const float* gamma = (const float*)d_in[9];
    const float* beta  = (const float*)d_in[10];
    float* out = (float*)d_out;

    void *pHx, *pWqkv, *pWo, *pBq, *pQKV, *pAx;
    cudaGetSymbolAddress(&pHx,   g_Hx);
    cudaGetSymbolAddress(&pWqkv, g_Wqkv);
    cudaGetSymbolAddress(&pWo,   g_Wo);
    cudaGetSymbolAddress(&pBq,   g_bqkv);
    cudaGetSymbolAddress(&pQKV,  g_QKV);
    cudaGetSymbolAddress(&pAx,   g_ATTx);
    float* Hx   = (float*)pHx;
    float* Wqkv = (float*)pWqkv;
    float* Wo   = (float*)pWo;
    float* bqkv = (float*)pBq;
    float* QKV  = (float*)pQKV;
    float* ATTx = (float*)pAx;

    cudaFuncSetAttribute(mm_kernel<false>, cudaFuncAttributeMaxDynamicSharedMemorySize, MM_SMEM);
    cudaFuncSetAttribute(mm_kernel<true>,  cudaFuncAttributeMaxDynamicSharedMemorySize, MM_SMEM);
    cudaFuncSetAttribute(attn_kernel, cudaFuncAttributeMaxDynamicSharedMemorySize, ATT_SMEM);

    // prep
    wconv_kernel<<<dim3(1024 * 1024 / 256, 4), 256>>>(w_q, w_k, w_v, w_o, Wqkv, Wo);
    bconcat_kernel<<<(QKV_LD + 255) / 256, 256>>>(b_q, b_k, b_v, bqkv);
    ln_kernel<<<MROWS, 256>>>(x, gamma, beta, Hx);

    // fused QKV GEMM
    dim3 gq(QKV_LD / BN, MROWS / BM);     // (24, 32)
    mm_kernel<false><<<gq, 256, MM_SMEM>>>(Hx, Wqkv, bqkv, nullptr, QKV, QKV_LD);

    // banded MMA attention
    dim3 ga(SEQ / AQT, NUM_HEADS, BATCH); // (32, 16, 2)
    attn_kernel<<<ga, 256, ATT_SMEM>>>(QKV, ATTx);

    // output projection + bias + residual
    dim3 go(MODEL_DIM / BN, MROWS / BM);  // (8, 32)
    mm_kernel<true><<<go, 256, MM_SMEM>>>(ATTx, Wo, b_o, x, out, MODEL_DIM);
}

// round 10
// speedup vs baseline: 3.2507x; 1.4652x over previous
#include <cuda_runtime.h>
#include <cuda_fp16.h>
#include <cstdint>
#include <math.h>

// ---------------- problem constants ----------------
#define MODEL_DIM 1024
#define NUM_HEADS 16
#define HEAD_DIM  64
#define WINDOW    32
#define EPS       1e-5f
#define BATCH     2
#define SEQ       2048
#define MROWS     (BATCH * SEQ)      // 4096
#define QKV_LD    (3 * MODEL_DIM)    // 3072
#define KDIM      MODEL_DIM          // 1024
#define KT16      (KDIM / 16)        // 64 k-tiles (16 wide) per row

// ---------------- scratch (fragment-ordered fp16) ----------------
// A tiles: 16(m) x 16(k) = 256 halves.  B tiles: 16(k) x 8(n) = 128 halves.
__device__ __half g_Hx  [(MROWS / 16) * KT16 * 256];
__device__ __half g_Wqkv[(QKV_LD / 8) * KT16 * 128];
__device__ __half g_Wo  [(MODEL_DIM / 8) * KT16 * 128];
__device__ float  g_bqkv[QKV_LD];
__device__ float  g_QKV [MROWS * QKV_LD];
__device__ __half g_ATTx[(MROWS / 16) * KT16 * 256];

// ---------------- helpers ----------------
__device__ __forceinline__ uint32_t smem_u32(const void* p) {
    uint32_t a;
    asm("{ .reg .u64 t; cvta.to.shared.u64 t, %1; cvt.u32.u64 %0, t; }" : "=r"(a) : "l"(p));
    return a;
}
__device__ __forceinline__ void cp_async16(uint32_t dst, const void* src) {
    asm volatile("cp.async.cg.shared.global [%0], [%1], 16;" :: "r"(dst), "l"(src) : "memory");
}
__device__ __forceinline__ void cp_commit() {
    asm volatile("cp.async.commit_group;" ::: "memory");
}
template<int N>
__device__ __forceinline__ void cp_wait() {
    asm volatile("cp.async.wait_group %0;" :: "n"(N) : "memory");
}
__device__ __forceinline__ void lds128(uint32_t* r, uint32_t a) {
    asm volatile("ld.shared.v4.b32 {%0,%1,%2,%3}, [%4];"
                 : "=r"(r[0]), "=r"(r[1]), "=r"(r[2]), "=r"(r[3]) : "r"(a));
}
__device__ __forceinline__ void lds64(uint32_t* r, uint32_t a) {
    asm volatile("ld.shared.v2.b32 {%0,%1}, [%2];"
                 : "=r"(r[0]), "=r"(r[1]) : "r"(a));
}
// mma.m16n8k16 fp16 inputs, fp32 accum
__device__ __forceinline__ void mma_f16(float* c, const uint32_t* a, const uint32_t* b) {
    asm volatile("mma.sync.aligned.m16n8k16.row.col.f32.f16.f16.f32 "
                 "{%0,%1,%2,%3},{%4,%5,%6,%7},{%8,%9},{%0,%1,%2,%3};"
                 : "+f"(c[0]), "+f"(c[1]), "+f"(c[2]), "+f"(c[3])
                 : "r"(a[0]), "r"(a[1]), "r"(a[2]), "r"(a[3]), "r"(b[0]), "r"(b[1]));
}

// fragment maps (half index within tile)
// A 16x16: thread L holds 4 b32 regs (8 halves): half idx = L*8 + j*2 + e
__device__ __forceinline__ int a_off_h(int rr, int cc) {
    return ((rr & 7) * 4 + ((cc & 7) >> 1)) * 8 + ((rr >> 3) + 2 * (cc >> 3)) * 2 + (cc & 1);
}
// B 16(k)x8(n): thread L holds 2 b32 regs (4 halves): half idx = L*4 + j*2 + e
__device__ __forceinline__ int b_off_h(int k, int n) {
    return (n * 4 + ((k & 7) >> 1)) * 4 + (k >> 3) * 2 + (k & 1);
}
// C 16x8 fp32: thread L holds 4 floats: float idx = L*4 + j
__device__ __forceinline__ int c_off(int rr, int cc) {
    return ((rr & 7) * 4 + (cc >> 1)) * 4 + (rr >> 3) * 2 + (cc & 1);
}

// ============================================================
// LayerNorm -> A-fragment-ordered fp16
// ============================================================
__global__ __launch_bounds__(256)
void ln_kernel(const float* __restrict__ x,
               const float* __restrict__ gamma,
               const float* __restrict__ beta,
               __half* __restrict__ Hx)
{
    int row = blockIdx.x;
    int tid = threadIdx.x;
    float4 a = ((const float4*)(x + (size_t)row * MODEL_DIM))[tid];

    __shared__ float red[8];
    __shared__ float stat;

    float s = a.x + a.y + a.z + a.w;
    #pragma unroll
    for (int o = 16; o; o >>= 1) s += __shfl_xor_sync(0xffffffffu, s, o);
    if ((tid & 31) == 0) red[tid >> 5] = s;
    __syncthreads();
    if (tid == 0) {
        float t = 0.f;
        #pragma unroll
        for (int i = 0; i < 8; i++) t += red[i];
        stat = t * (1.0f / MODEL_DIM);
    }
    __syncthreads();
    float mu = stat;

    float dx = a.x - mu, dy = a.y - mu, dz = a.z - mu, dw = a.w - mu;
    float s2 = dx*dx + dy*dy + dz*dz + dw*dw;
    #pragma unroll
    for (int o = 16; o; o >>= 1) s2 += __shfl_xor_sync(0xffffffffu, s2, o);
    __syncthreads();
    if ((tid & 31) == 0) red[tid >> 5] = s2;
    __syncthreads();
    if (tid == 0) {
        float t = 0.f;
        #pragma unroll
        for (int i = 0; i < 8; i++) t += red[i];
        stat = rsqrtf(t * (1.0f / MODEL_DIM) + EPS);
    }
    __syncthreads();
    float rstd = stat;

    float4 g = ((const float4*)gamma)[tid];
    float4 b = ((const float4*)beta)[tid];
    float v0 = dx * rstd * g.x + b.x;
    float v1 = dy * rstd * g.y + b.y;
    float v2 = dz * rstd * g.z + b.z;
    float v3 = dw * rstd * g.w + b.w;

    int mt = row >> 4, r = row & 15;
    int kt = tid >> 2;
    int cc0 = (tid * 4) & 15;
    __half* tile = Hx + ((size_t)mt * KT16 + kt) * 256;
    int o0 = a_off_h(r, cc0);
    int o1 = a_off_h(r, cc0 + 2);
    ((__half2*)tile)[o0 >> 1] = __floats2half2_rn(v0, v1);
    ((__half2*)tile)[o1 >> 1] = __floats2half2_rn(v2, v3);
}

// ============================================================
// Weight -> B-fragment-ordered fp16.  w[K,N] row-major.
// ============================================================
__global__ __launch_bounds__(256)
void wconv_kernel(const float* __restrict__ wq, const float* __restrict__ wk,
                  const float* __restrict__ wv, const float* __restrict__ wo,
                  __half* __restrict__ Wqkv, __half* __restrict__ Wo)
{
    int bz = blockIdx.y;
    const float* w = (bz == 0) ? wq : (bz == 1) ? wk : (bz == 2) ? wv : wo;
    __half* WT = (bz < 3) ? (Wqkv + (size_t)bz * (1024 / 8) * KT16 * 128) : Wo;

    int idx = blockIdx.x * 256 + threadIdx.x;
    int k = idx >> 10;
    int n = idx & 1023;
    float v = w[idx];
    int nt = n >> 3, kt = k >> 4;
    WT[((size_t)nt * KT16 + kt) * 128 + b_off_h(k & 15, n & 7)] = __float2half_rn(v);
}

__global__ void bconcat_kernel(const float* __restrict__ bq,
                               const float* __restrict__ bk,
                               const float* __restrict__ bv,
                               float* __restrict__ dst)
{
    int i = blockIdx.x * 256 + threadIdx.x;
    if (i >= QKV_LD) return;
    const float* s = (i < 1024) ? bq : (i < 2048 ? bk : bv);
    dst[i] = s[i & 1023];
}

// ============================================================
// fp16 mma.sync GEMM. CTA 128x128x32, 8 warps (64x32), 3-stage
// cp.async, fragment-ordered smem.
// ============================================================
#define BM 128
#define BN 128
#define BK 32
#define A_TILE 8192                   // 8 mt x 2 kt x 512 B
#define B_TILE 8192                   // 16 nt x 2 kt x 256 B
#define STAGE_BYTES (A_TILE + B_TILE) // 16384
#define NSTAGE 3
#define NIT (KDIM / BK)               // 32
#define MM_SMEM (NSTAGE * STAGE_BYTES)// 49152

__device__ __forceinline__ void stage_A(const __half* __restrict__ src,
                                        int mt0, int kt0, uint32_t dst)
{
    #pragma unroll
    for (int p = 0; p < 2; p++) {
        int ch = threadIdx.x + p * 256;      // 0..511 chunks of 16B
        int tl = ch >> 5;                    // 0..15: mti*2 + kti
        int in = ch & 31;
        int mti = tl >> 1, kti = tl & 1;
        const char* g = (const char*)(src + ((size_t)(mt0 + mti) * KT16 + kt0 + kti) * 256) + in * 16;
        cp_async16(dst + (uint32_t)tl * 512 + in * 16, g);
    }
}
__device__ __forceinline__ void stage_B(const __half* __restrict__ src,
                                        int nt0, int kt0, uint32_t dst)
{
    #pragma unroll
    for (int p = 0; p < 2; p++) {
        int ch = threadIdx.x + p * 256;      // 0..511
        int tl = ch >> 4;                    // 0..31: nti*2 + kti
        int in = ch & 15;
        int nti = tl >> 1, kti = tl & 1;
        const char* g = (const char*)(src + ((size_t)(nt0 + nti) * KT16 + kt0 + kti) * 128) + in * 16;
        cp_async16(dst + (uint32_t)tl * 256 + in * 16, g);
    }
}

template<bool RESID>
__global__ __launch_bounds__(256, 2)
void mm_kernel(const __half* __restrict__ A,
               const __half* __restrict__ B,
               const float* __restrict__ bias,
               const float* __restrict__ resid,
               float* __restrict__ C, int ldc)
{
    extern __shared__ char smem[];
    uint32_t sb = smem_u32(smem);

    int tid  = threadIdx.x;
    int wid  = tid >> 5;
    int lane = tid & 31;
    int mtb = (wid >> 2) * 4;            // 4 m-tiles (64 rows)
    int ntb = (wid & 3) * 4;             // 4 n-tiles (32 cols)
    int mt0 = blockIdx.y * 8;
    int nt0 = blockIdx.x * 16;

    float acc[4][4][4];
    #pragma unroll
    for (int i = 0; i < 4; i++)
        #pragma unroll
        for (int j = 0; j < 4; j++)
            #pragma unroll
            for (int q = 0; q < 4; q++) acc[i][j][q] = 0.f;

    stage_A(A, mt0, 0, sb);
    stage_B(B, nt0, 0, sb + A_TILE);
    cp_commit();
    stage_A(A, mt0, 2, sb + STAGE_BYTES);
    stage_B(B, nt0, 2, sb + STAGE_BYTES + A_TILE);
    cp_commit();

    uint32_t aoff = (uint32_t)lane * 16;
    uint32_t boff = (uint32_t)lane * 8;

    #pragma unroll 1
    for (int it = 0; it < NIT; it++) {
        cp_wait<1>();
        __syncthreads();

        if (it + 2 < NIT) {
            uint32_t nb = sb + (uint32_t)((it + 2) % NSTAGE) * STAGE_BYTES;
            stage_A(A, mt0, (it + 2) * 2, nb);
            stage_B(B, nt0, (it + 2) * 2, nb + A_TILE);
        }
        cp_commit();

        uint32_t aB = sb + (uint32_t)(it % NSTAGE) * STAGE_BYTES;
        uint32_t bB = aB + A_TILE;

        #pragma unroll
        for (int kti = 0; kti < 2; kti++) {
            uint32_t af[4][4];
            uint32_t bfr[4][2];
            #pragma unroll
            for (int i = 0; i < 4; i++)
                lds128(af[i], aB + (uint32_t)((mtb + i) * 2 + kti) * 512 + aoff);
            #pragma unroll
            for (int j = 0; j < 4; j++)
                lds64(bfr[j], bB + (uint32_t)((ntb + j) * 2 + kti) * 256 + boff);
            #pragma unroll
            for (int i = 0; i < 4; i++)
                #pragma unroll
                for (int j = 0; j < 4; j++)
                    mma_f16(acc[i][j], af[i], bfr[j]);
        }
    }

    int mBase = mt0 * 16 + mtb * 16 + (lane >> 2);
    int nBase = nt0 * 8 + ntb * 8 + (lane & 3) * 2;
    #pragma unroll
    for (int i = 0; i < 4; i++) {
        int m0 = mBase + i * 16;
        #pragma unroll
        for (int j = 0; j < 4; j++) {
            int n = nBase + j * 8;
            float bx0 = bias[n], bx1 = bias[n + 1];
            float2 v0, v1;
            v0.x = acc[i][j][0] + bx0;
            v0.y = acc[i][j][1] + bx1;
            v1.x = acc[i][j][2] + bx0;
            v1.y = acc[i][j][3] + bx1;
            if (RESID) {
                float2 r0 = *(const float2*)(resid + (size_t)m0 * MODEL_DIM + n);
                float2 r1 = *(const float2*)(resid + (size_t)(m0 + 8) * MODEL_DIM + n);
                v0.x += r0.x; v0.y += r0.y;
                v1.x += r1.x; v1.y += r1.y;
            }
            *(float2*)(C + (size_t)m0 * ldc + n)       = v0;
            *(float2*)(C + (size_t)(m0 + 8) * ldc + n) = v1;
        }
    }
}

// ============================================================
// Banded MMA attention (fp16 fragments, fp32 softmax).
// Block = 64 queries x 1 head x 1 batch, 256 threads.
// ============================================================
#define AQT 64
// byte offsets in smem
#define SQ_B 0                        // Qf: 4mt x 4kt x 512B   = 8192
#define SK_B 8192                     // Kf: 16nt x 4kt x 256B  = 16384
#define SV_B 24576                    // Vf: 8nt x 8kt x 256B   = 16384
#define SP_B 40960                    // Pf32: 4mt x 10nt x 512B = 20480
#define SH_B 61440                    // Pfh: 4mt x 5kt x 512B  = 10240
#define SI_B 71680                    // inv: 64 floats          = 256
#define ATT_SMEM (71680 + 256)

__global__ __launch_bounds__(256, 2)
void attn_kernel(const float* __restrict__ QKV,
                 __half* __restrict__ Ox)
{
    extern __shared__ char smc[];
    uint32_t sb = smem_u32(smc);
    __half* Qf  = (__half*)(smc + SQ_B);
    __half* Kf  = (__half*)(smc + SK_B);
    __half* Vf  = (__half*)(smc + SV_B);
    float*  Pf  = (float*) (smc + SP_B);
    __half* Ph  = (__half*)(smc + SH_B);
    float*  inv = (float*) (smc + SI_B);

    int tid = threadIdx.x;
    int q0  = blockIdx.x * AQT;
    int h   = blockIdx.y;
    int b   = blockIdx.z;
    size_t base = (size_t)b * SEQ * QKV_LD;

    // ---- stage Q (scaled, fp16, A-frag). 64 rows x 16 float4 ----
    #pragma unroll
    for (int i = 0; i < 4; i++) {
        int idx4 = tid + i * 256;            // 0..1023
        int r  = idx4 >> 4;                  // 0..63
        int c4 = idx4 & 15;
        float4 v = *(const float4*)(QKV + base + (size_t)(q0 + r) * QKV_LD + h * HEAD_DIM + c4 * 4);
        int mt = r >> 4, rr = r & 15;
        int kt = c4 >> 2;
        int cc0 = (c4 * 4) & 15;
        __half* tile = Qf + (mt * 4 + kt) * 256;
        int o0 = a_off_h(rr, cc0);
        int o1 = a_off_h(rr, cc0 + 2);
        ((__half2*)tile)[o0 >> 1] = __floats2half2_rn(v.x * 0.125f, v.y * 0.125f);
        ((__half2*)tile)[o1 >> 1] = __floats2half2_rn(v.z * 0.125f, v.w * 0.125f);
    }
    // ---- stage K (B-frag: k=dim, n=key) and V (B-frag: k=token, n=dim) ----
    #pragma unroll
    for (int i = 0; i < 8; i++) {
        int idx4 = tid + i * 256;            // 0..2047
        int jrow = idx4 >> 4;                // 0..127 window token
        int c4   = idx4 & 15;
        int d0   = c4 * 4;
        int gk = q0 - WINDOW + jrow;
        float4 kv = make_float4(0.f, 0.f, 0.f, 0.f);
        float4 vv = kv;
        if (gk >= 0 && gk < SEQ) {
            const float* p = QKV + base + (size_t)gk * QKV_LD + h * HEAD_DIM + d0;
            kv = *(const float4*)(p + MODEL_DIM);
            vv = *(const float4*)(p + 2 * MODEL_DIM);
        }
        // K tile (nt = jrow>>3, kt = d>>4), element (d&15, jrow&7)
        {
            __half* tile = Kf + ((jrow >> 3) * 4 + (d0 >> 4)) * 128;
            int o = b_off_h(d0 & 15, jrow & 7);      // d0, d0+1 consecutive
            ((__half2*)tile)[o >> 1]       = __floats2half2_rn(kv.x, kv.y);
            ((__half2*)tile)[(o >> 1) + 2] = __floats2half2_rn(kv.z, kv.w);
        }
        // V tile (nt = d>>3, kt = jrow>>4), element (jrow&15, d&7)
        {
            float va[4] = {vv.x, vv.y, vv.z, vv.w};
            #pragma unroll
            for (int j = 0; j < 4; j++) {
                int d = d0 + j;
                Vf[((d >> 3) * 8 + (jrow >> 4)) * 128 + b_off_h(jrow & 15, d & 7)] = __float2half_rn(va[j]);
            }
        }
    }
    __syncthreads();

    int w  = tid >> 5;
    int L  = tid & 31;
    int mt = w >> 1;
    int half = w & 1;

    // ---- GEMM1: banded S = Q K^T, C (fp32) -> Pf in C-frag order ----
    {
        uint32_t qbase = sb + SQ_B;
        uint32_t kbase = sb + SK_B;
        uint32_t af[4][4];
        #pragma unroll
        for (int kt = 0; kt < 4; kt++)
            lds128(af[kt], qbase + (uint32_t)(mt * 4 + kt) * 512 + L * 16);
        #pragma unroll
        for (int nn = 0; nn < 5; nn++) {
            int ntl = half * 5 + nn;
            int ntg = 2 * mt + ntl;
            float acc[4] = {0.f, 0.f, 0.f, 0.f};
            #pragma unroll
            for (int kt = 0; kt < 4; kt++) {
                uint32_t bfr[2];
                lds64(bfr, kbase + (uint32_t)(ntg * 4 + kt) * 256 + L * 8);
                mma_f16(acc, af[kt], bfr);
            }
            int r = L >> 2, c = (L & 3) * 2;
            float* Pt = Pf + (mt * 10 + ntl) * 128;
            Pt[c_off(r, c)]         = acc[0];
            Pt[c_off(r, c + 1)]     = acc[1];
            Pt[c_off(r + 8, c)]     = acc[2];
            Pt[c_off(r + 8, c + 1)] = acc[3];
        }
    }
    __syncthreads();

    // ---- softmax: 4 threads per row, 20 cols each; write fp16 A-frag ----
    {
        int row  = tid >> 2;                 // 0..63
        int part = tid & 3;
        int rmt = row >> 4, r = row & 15;
        float* Pb = Pf + rmt * 10 * 128;
        __half* Pw = Ph + rmt * 5 * 256;
        int jb = rmt * 16;

        float mx = -1e30f;
        #pragma unroll
        for (int u = 0; u < 20; u++) {
            int jl = part * 20 + u;
            int J  = jb + jl;
            int gk = q0 - WINDOW + J;
            bool valid = (J >= row) && (J <= row + 64) && (gk >= 0) && (gk < SEQ);
            float s = Pb[(jl >> 3) * 128 + c_off(r, jl & 7)];
            if (valid) mx = fmaxf(mx, s);
        }
        mx = fmaxf(mx, __shfl_xor_sync(0xffffffffu, mx, 1));
        mx = fmaxf(mx, __shfl_xor_sync(0xffffffffu, mx, 2));

        float sum = 0.f;
        #pragma unroll
        for (int u = 0; u < 20; u++) {
            int jl = part * 20 + u;
            int J  = jb + jl;
            int gk = q0 - WINDOW + J;
            bool valid = (J >= row) && (J <= row + 64) && (gk >= 0) && (gk < SEQ);
            float s = Pb[(jl >> 3) * 128 + c_off(r, jl & 7)];
            float e = valid ? __expf(s - mx) : 0.f;
            sum += e;
            Pw[(jl >> 4) * 256 + a_off_h(r, jl & 15)] = __float2half_rn(e);
        }
        sum += __shfl_xor_sync(0xffffffffu, sum, 1);
        sum += __shfl_xor_sync(0xffffffffu, sum, 2);
        if (part == 0) inv[row] = 1.0f / sum;
    }
    __syncthreads();

    // ---- GEMM2: O = P V (banded), epilogue -> ATTx (fp16 A-frag) ----
    {
        uint32_t pbase = sb + SH_B;
        uint32_t vbase = sb + SV_B;
        int ntd0 = half * 4;
        float acc2[4][4];
        #pragma unroll
        for (int j = 0; j < 4; j++)
            #pragma unroll
            for (int q = 0; q < 4; q++) acc2[j][q] = 0.f;

        #pragma unroll
        for (int ktl = 0; ktl < 5; ktl++) {
            int kt_tok = mt + ktl;           // global token tile (16-wide)
            uint32_t af[4];
            lds128(af, pbase + (uint32_t)(mt * 5 + ktl) * 512 + L * 16);
            #pragma unroll
            for (int jn = 0; jn < 4; jn++) {
                uint32_t bfr[2];
                lds64(bfr, vbase + (uint32_t)((ntd0 + jn) * 8 + kt_tok) * 256 + L * 8);
                mma_f16(acc2[jn], af, bfr);
            }
        }

        int r0 = mt * 16 + (L >> 2);
        float i0 = inv[r0], i1 = inv[r0 + 8];
        int grow0 = b * SEQ + q0 + r0;
        int grow1 = grow0 + 8;
        int gmt0 = grow0 >> 4, grr0 = grow0 & 15;
        int gmt1 = grow1 >> 4, grr1 = grow1 & 15;
        #pragma unroll
        for (int jn = 0; jn < 4; jn++) {
            int col = h * HEAD_DIM + (ntd0 + jn) * 8 + (L & 3) * 2;
            int kt = col >> 4, cc = col & 15;
            __half2* t0 = (__half2*)(Ox + ((size_t)gmt0 * KT16 + kt) * 256);
            __half2* t1 = (__half2*)(Ox + ((size_t)gmt1 * KT16 + kt) * 256);
            t0[a_off_h(grr0, cc) >> 1] = __floats2half2_rn(acc2[jn][0] * i0, acc2[jn][1] * i0);
            t1[a_off_h(grr1, cc) >> 1] = __floats2half2_rn(acc2[jn][2] * i1, acc2[jn][3] * i1);
        }
    }
}

// ============================================================
// launch
// ============================================================
extern "C" void kernel_launch(void* const* d_in, const int* in_sizes, int n_in,
                              void* d_out, int out_size)
{
    (void)in_sizes; (void)n_in; (void)out_size;
    const float* x     = (const float*)d_in[0];
    const float* w_q   = (const float*)d_in[1];
    const float* b_q   = (const float*)d_in[2];
    const float* w_k   = (const float*)d_in[3];
    const float* b_k   = (const float*)d_in[4];
    const float* w_v   = (const float*)d_in[5];
    const float* b_v   = (const float*)d_in[6];
    const float* w_o   = (const float*)d_in[7];
    const float* b_o   = (const float*)d_in[8];
    const float* gamma = (const float*)d_in[9];
    const float* beta  = (const float*)d_in[10];
    float* out = (float*)d_out;

    void *pHx, *pWqkv, *pWo, *pBq, *pQKV, *pAx;
    cudaGetSymbolAddress(&pHx,   g_Hx);
    cudaGetSymbolAddress(&pWqkv, g_Wqkv);
    cudaGetSymbolAddress(&pWo,   g_Wo);
    cudaGetSymbolAddress(&pBq,   g_bqkv);
    cudaGetSymbolAddress(&pQKV,  g_QKV);
    cudaGetSymbolAddress(&pAx,   g_ATTx);
    __half* Hx   = (__half*)pHx;
    __half* Wqkv = (__half*)pWqkv;
    __half* Wo   = (__half*)pWo;
    float*  bqkv = (float*)pBq;
    float*  QKV  = (float*)pQKV;
    __half* ATTx = (__half*)pAx;

    cudaFuncSetAttribute(mm_kernel<false>, cudaFuncAttributeMaxDynamicSharedMemorySize, MM_SMEM);
    cudaFuncSetAttribute(mm_kernel<true>,  cudaFuncAttributeMaxDynamicSharedMemorySize, MM_SMEM);
    cudaFuncSetAttribute(attn_kernel, cudaFuncAttributeMaxDynamicSharedMemorySize, ATT_SMEM);

    // prep
    wconv_kernel<<<dim3(1024 * 1024 / 256, 4), 256>>>(w_q, w_k, w_v, w_o, Wqkv, Wo);
    bconcat_kernel<<<(QKV_LD + 255) / 256, 256>>>(b_q, b_k, b_v, bqkv);
    ln_kernel<<<MROWS, 256>>>(x, gamma, beta, Hx);

    // fused QKV GEMM
    dim3 gq(QKV_LD / BN, MROWS / BM);     // (24, 32)
    mm_kernel<false><<<gq, 256, MM_SMEM>>>(Hx, Wqkv, bqkv, nullptr, QKV, QKV_LD);

    // banded MMA attention
    dim3 ga(SEQ / AQT, NUM_HEADS, BATCH); // (32, 16, 2)
    attn_kernel<<<ga, 256, ATT_SMEM>>>(QKV, ATTx);

    // output projection + bias + residual
    dim3 go(MODEL_DIM / BN, MROWS / BM);  // (8, 32)
    mm_kernel<true><<<go, 256, MM_SMEM>>>(ATTx, Wo, b_o, x, out, MODEL_DIM);
}

// round 11
// speedup vs baseline: 3.7510x; 1.1539x over previous
#include <cuda_runtime.h>
#include <cuda_fp16.h>
#include <cstdint>
#include <math.h>

// ---------------- problem constants ----------------
#define MODEL_DIM 1024
#define NUM_HEADS 16
#define HEAD_DIM  64
#define WINDOW    32
#define EPS       1e-5f
#define BATCH     2
#define SEQ       2048
#define MROWS     (BATCH * SEQ)      // 4096
#define QKV_LD    (3 * MODEL_DIM)    // 3072
#define KDIM      MODEL_DIM          // 1024
#define KT16      (KDIM / 16)        // 64

// K fragment arrays: token padded by 32 both sides
#define KNT 264                       // (2048+64)/8 n-tiles
#define VKT 132                       // (2048+64)/16 k-tiles

// ---------------- scratch (fragment-ordered fp16) ----------------
__device__ __half g_Hx  [(MROWS / 16) * KT16 * 256];
__device__ __half g_Wqkv[(QKV_LD / 8) * KT16 * 128];
__device__ __half g_Wo  [(MODEL_DIM / 8) * KT16 * 128];
__device__ float  g_bqkv[QKV_LD];
__device__ __half g_QfG [BATCH * NUM_HEADS * (SEQ / 16) * 1024];     // A-frag Q (scaled)
__device__ __half g_KfG [BATCH * NUM_HEADS * KNT * 512];             // B-frag K (padded)
__device__ __half g_VfG [BATCH * NUM_HEADS * 8 * VKT * 128];         // B-frag V (padded)
__device__ __half g_ATTx[(MROWS / 16) * KT16 * 256];

// ---------------- helpers ----------------
__device__ __forceinline__ uint32_t smem_u32(const void* p) {
    uint32_t a;
    asm("{ .reg .u64 t; cvta.to.shared.u64 t, %1; cvt.u32.u64 %0, t; }" : "=r"(a) : "l"(p));
    return a;
}
__device__ __forceinline__ void cp_async16(uint32_t dst, const void* src) {
    asm volatile("cp.async.cg.shared.global [%0], [%1], 16;" :: "r"(dst), "l"(src) : "memory");
}
__device__ __forceinline__ void cp_commit() {
    asm volatile("cp.async.commit_group;" ::: "memory");
}
template<int N>
__device__ __forceinline__ void cp_wait() {
    asm volatile("cp.async.wait_group %0;" :: "n"(N) : "memory");
}
__device__ __forceinline__ void lds128(uint32_t* r, uint32_t a) {
    asm volatile("ld.shared.v4.b32 {%0,%1,%2,%3}, [%4];"
                 : "=r"(r[0]), "=r"(r[1]), "=r"(r[2]), "=r"(r[3]) : "r"(a));
}
__device__ __forceinline__ void lds64(uint32_t* r, uint32_t a) {
    asm volatile("ld.shared.v2.b32 {%0,%1}, [%2];"
                 : "=r"(r[0]), "=r"(r[1]) : "r"(a));
}
__device__ __forceinline__ void mma_f16(float* c, const uint32_t* a, const uint32_t* b) {
    asm volatile("mma.sync.aligned.m16n8k16.row.col.f32.f16.f16.f32 "
                 "{%0,%1,%2,%3},{%4,%5,%6,%7},{%8,%9},{%0,%1,%2,%3};"
                 : "+f"(c[0]), "+f"(c[1]), "+f"(c[2]), "+f"(c[3])
                 : "r"(a[0]), "r"(a[1]), "r"(a[2]), "r"(a[3]), "r"(b[0]), "r"(b[1]));
}

// fragment maps (half index within tile)
__device__ __forceinline__ int a_off_h(int rr, int cc) {
    return ((rr & 7) * 4 + ((cc & 7) >> 1)) * 8 + ((rr >> 3) + 2 * (cc >> 3)) * 2 + (cc & 1);
}
__device__ __forceinline__ int b_off_h(int k, int n) {
    return (n * 4 + ((k & 7) >> 1)) * 4 + (k >> 3) * 2 + (k & 1);
}
__device__ __forceinline__ int c_off(int rr, int cc) {
    return ((rr & 7) * 4 + (cc >> 1)) * 4 + (rr >> 3) * 2 + (cc & 1);
}

// ============================================================
// LayerNorm -> A-fragment-ordered fp16
// ============================================================
__global__ __launch_bounds__(256)
void ln_kernel(const float* __restrict__ x,
               const float* __restrict__ gamma,
               const float* __restrict__ beta,
               __half* __restrict__ Hx)
{
    int row = blockIdx.x;
    int tid = threadIdx.x;
    float4 a = ((const float4*)(x + (size_t)row * MODEL_DIM))[tid];

    __shared__ float red[8];
    __shared__ float stat;

    float s = a.x + a.y + a.z + a.w;
    #pragma unroll
    for (int o = 16; o; o >>= 1) s += __shfl_xor_sync(0xffffffffu, s, o);
    if ((tid & 31) == 0) red[tid >> 5] = s;
    __syncthreads();
    if (tid == 0) {
        float t = 0.f;
        #pragma unroll
        for (int i = 0; i < 8; i++) t += red[i];
        stat = t * (1.0f / MODEL_DIM);
    }
    __syncthreads();
    float mu = stat;

    float dx = a.x - mu, dy = a.y - mu, dz = a.z - mu, dw = a.w - mu;
    float s2 = dx*dx + dy*dy + dz*dz + dw*dw;
    #pragma unroll
    for (int o = 16; o; o >>= 1) s2 += __shfl_xor_sync(0xffffffffu, s2, o);
    __syncthreads();
    if ((tid & 31) == 0) red[tid >> 5] = s2;
    __syncthreads();
    if (tid == 0) {
        float t = 0.f;
        #pragma unroll
        for (int i = 0; i < 8; i++) t += red[i];
        stat = rsqrtf(t * (1.0f / MODEL_DIM) + EPS);
    }
    __syncthreads();
    float rstd = stat;

    float4 g = ((const float4*)gamma)[tid];
    float4 b = ((const float4*)beta)[tid];
    float v0 = dx * rstd * g.x + b.x;
    float v1 = dy * rstd * g.y + b.y;
    float v2 = dz * rstd * g.z + b.z;
    float v3 = dw * rstd * g.w + b.w;

    int mt = row >> 4, r = row & 15;
    int kt = tid >> 2;
    int cc0 = (tid * 4) & 15;
    __half* tile = Hx + ((size_t)mt * KT16 + kt) * 256;
    ((__half2*)tile)[a_off_h(r, cc0) >> 1]     = __floats2half2_rn(v0, v1);
    ((__half2*)tile)[a_off_h(r, cc0 + 2) >> 1] = __floats2half2_rn(v2, v3);
}

// ============================================================
// Weight -> B-fragment-ordered fp16
// ============================================================
__global__ __launch_bounds__(256)
void wconv_kernel(const float* __restrict__ wq, const float* __restrict__ wk,
                  const float* __restrict__ wv, const float* __restrict__ wo,
                  __half* __restrict__ Wqkv, __half* __restrict__ Wo)
{
    int bz = blockIdx.y;
    const float* w = (bz == 0) ? wq : (bz == 1) ? wk : (bz == 2) ? wv : wo;
    __half* WT = (bz < 3) ? (Wqkv + (size_t)bz * (1024 / 8) * KT16 * 128) : Wo;

    int idx = blockIdx.x * 256 + threadIdx.x;
    int k = idx >> 10;
    int n = idx & 1023;
    float v = w[idx];
    int nt = n >> 3, kt = k >> 4;
    WT[((size_t)nt * KT16 + kt) * 128 + b_off_h(k & 15, n & 7)] = __float2half_rn(v);
}

__global__ void bconcat_kernel(const float* __restrict__ bq,
                               const float* __restrict__ bk,
                               const float* __restrict__ bv,
                               float* __restrict__ dst)
{
    int i = blockIdx.x * 256 + threadIdx.x;
    if (i >= QKV_LD) return;
    const float* s = (i < 1024) ? bq : (i < 2048 ? bk : bv);
    dst[i] = s[i & 1023];
}

// ============================================================
// fp16 mma.sync GEMM. CTA 128x128x32, 8 warps, 3-stage cp.async.
// MODE 0: QKV gemm -> fragment arrays.  MODE 1: out proj + resid.
// ============================================================
#define BM 128
#define BN 128
#define BK 32
#define A_TILE 8192
#define B_TILE 8192
#define STAGE_BYTES (A_TILE + B_TILE)
#define NSTAGE 3
#define NIT (KDIM / BK)
#define MM_SMEM (NSTAGE * STAGE_BYTES)

__device__ __forceinline__ void stage_A(const __half* __restrict__ src,
                                        int mt0, int kt0, uint32_t dst)
{
    #pragma unroll
    for (int p = 0; p < 2; p++) {
        int ch = threadIdx.x + p * 256;
        int tl = ch >> 5;
        int in = ch & 31;
        int mti = tl >> 1, kti = tl & 1;
        const char* g = (const char*)(src + ((size_t)(mt0 + mti) * KT16 + kt0 + kti) * 256) + in * 16;
        cp_async16(dst + (uint32_t)tl * 512 + in * 16, g);
    }
}
__device__ __forceinline__ void stage_B(const __half* __restrict__ src,
                                        int nt0, int kt0, uint32_t dst)
{
    #pragma unroll
    for (int p = 0; p < 2; p++) {
        int ch = threadIdx.x + p * 256;
        int tl = ch >> 4;
        int in = ch & 15;
        int nti = tl >> 1, kti = tl & 1;
        const char* g = (const char*)(src + ((size_t)(nt0 + nti) * KT16 + kt0 + kti) * 128) + in * 16;
        cp_async16(dst + (uint32_t)tl * 256 + in * 16, g);
    }
}

template<int MODE>
__global__ __launch_bounds__(256, 2)
void mm_kernel(const __half* __restrict__ A,
               const __half* __restrict__ B,
               const float* __restrict__ bias,
               const float* __restrict__ resid,
               float* __restrict__ C, int ldc,
               __half* __restrict__ Qf, __half* __restrict__ Kf, __half* __restrict__ Vf)
{
    extern __shared__ char smem[];
    uint32_t sb = smem_u32(smem);

    int tid  = threadIdx.x;
    int wid  = tid >> 5;
    int lane = tid & 31;
    int mtb = (wid >> 2) * 4;
    int ntb = (wid & 3) * 4;
    int mt0 = blockIdx.y * 8;
    int nt0 = blockIdx.x * 16;

    float acc[4][4][4];
    #pragma unroll
    for (int i = 0; i < 4; i++)
        #pragma unroll
        for (int j = 0; j < 4; j++)
            #pragma unroll
            for (int q = 0; q < 4; q++) acc[i][j][q] = 0.f;

    stage_A(A, mt0, 0, sb);
    stage_B(B, nt0, 0, sb + A_TILE);
    cp_commit();
    stage_A(A, mt0, 2, sb + STAGE_BYTES);
    stage_B(B, nt0, 2, sb + STAGE_BYTES + A_TILE);
    cp_commit();

    uint32_t aoff = (uint32_t)lane * 16;
    uint32_t boff = (uint32_t)lane * 8;

    #pragma unroll 1
    for (int it = 0; it < NIT; it++) {
        cp_wait<1>();
        __syncthreads();

        if (it + 2 < NIT) {
            uint32_t nb = sb + (uint32_t)((it + 2) % NSTAGE) * STAGE_BYTES;
            stage_A(A, mt0, (it + 2) * 2, nb);
            stage_B(B, nt0, (it + 2) * 2, nb + A_TILE);
        }
        cp_commit();

        uint32_t aB = sb + (uint32_t)(it % NSTAGE) * STAGE_BYTES;
        uint32_t bB = aB + A_TILE;

        #pragma unroll
        for (int kti = 0; kti < 2; kti++) {
            uint32_t af[4][4];
            uint32_t bfr[4][2];
            #pragma unroll
            for (int i = 0; i < 4; i++)
                lds128(af[i], aB + (uint32_t)((mtb + i) * 2 + kti) * 512 + aoff);
            #pragma unroll
            for (int j = 0; j < 4; j++)
                lds64(bfr[j], bB + (uint32_t)((ntb + j) * 2 + kti) * 256 + boff);
            #pragma unroll
            for (int i = 0; i < 4; i++)
                #pragma unroll
                for (int j = 0; j < 4; j++)
                    mma_f16(acc[i][j], af[i], bfr[j]);
        }
    }

    int mBase = mt0 * 16 + mtb * 16 + (lane >> 2);
    int nBase = nt0 * 8 + ntb * 8 + (lane & 3) * 2;

    if (MODE == 1) {
        #pragma unroll
        for (int i = 0; i < 4; i++) {
            int m0 = mBase + i * 16;
            #pragma unroll
            for (int j = 0; j < 4; j++) {
                int n = nBase + j * 8;
                float bx0 = bias[n], bx1 = bias[n + 1];
                float2 v0, v1;
                v0.x = acc[i][j][0] + bx0;
                v0.y = acc[i][j][1] + bx1;
                v1.x = acc[i][j][2] + bx0;
                v1.y = acc[i][j][3] + bx1;
                float2 r0 = *(const float2*)(resid + (size_t)m0 * MODEL_DIM + n);
                float2 r1 = *(const float2*)(resid + (size_t)(m0 + 8) * MODEL_DIM + n);
                v0.x += r0.x; v0.y += r0.y;
                v1.x += r1.x; v1.y += r1.y;
                *(float2*)(C + (size_t)m0 * ldc + n)       = v0;
                *(float2*)(C + (size_t)(m0 + 8) * ldc + n) = v1;
            }
        }
    } else {
        // fragment writes; matrix type uniform per CTA
        int mtype = (nt0 * 8) >> 10;   // 0=Q 1=K 2=V
        #pragma unroll
        for (int i = 0; i < 4; i++) {
            int m0 = mBase + i * 16;
            int bb  = m0 >> 11;
            int tok = m0 & 2047;
            #pragma unroll
            for (int j = 0; j < 4; j++) {
                int n = nBase + j * 8;
                float bx0 = bias[n], bx1 = bias[n + 1];
                float va0 = acc[i][j][0] + bx0, vb0 = acc[i][j][1] + bx1;   // row tok
                float va1 = acc[i][j][2] + bx0, vb1 = acc[i][j][3] + bx1;   // row tok+8
                int nn = n & 1023;
                int h = nn >> 6, d = nn & 63;
                int bh = bb * NUM_HEADS + h;
                if (mtype == 0) {
                    int kt = d >> 4, cc = d & 15;
                    __half2 h0 = __floats2half2_rn(va0 * 0.125f, vb0 * 0.125f);
                    __half2 h1 = __floats2half2_rn(va1 * 0.125f, vb1 * 0.125f);
                    __half* t0 = Qf + ((size_t)(bh * (SEQ / 16) + (tok >> 4))) * 1024 + kt * 256;
                    __half* t1 = Qf + ((size_t)(bh * (SEQ / 16) + ((tok + 8) >> 4))) * 1024 + kt * 256;
                    ((__half2*)t0)[a_off_h(tok & 15, cc) >> 1]       = h0;
                    ((__half2*)t1)[a_off_h((tok + 8) & 15, cc) >> 1] = h1;
                } else if (mtype == 1) {
                    int kt = d >> 4;
                    int tl0 = tok + 32, tl1 = tok + 40;
                    __half* t0 = Kf + ((size_t)(bh * KNT + (tl0 >> 3))) * 512 + kt * 128;
                    __half* t1 = Kf + ((size_t)(bh * KNT + (tl1 >> 3))) * 512 + kt * 128;
                    ((__half2*)t0)[b_off_h(d & 15, tl0 & 7) >> 1] = __floats2half2_rn(va0, vb0);
                    ((__half2*)t1)[b_off_h(d & 15, tl1 & 7) >> 1] = __floats2half2_rn(va1, vb1);
                } else {
                    int nt = d >> 3;
                    int tl0 = tok + 32, tl1 = tok + 40;
                    __half* base = Vf + ((size_t)(bh * 8 + nt)) * (VKT * 128);
                    __half* t0 = base + (tl0 >> 4) * 128;
                    __half* t1 = base + (tl1 >> 4) * 128;
                    t0[b_off_h(tl0 & 15, d & 7)]       = __float2half_rn(va0);
                    t0[b_off_h(tl0 & 15, (d + 1) & 7)] = __float2half_rn(vb0);
                    t1[b_off_h(tl1 & 15, d & 7)]       = __float2half_rn(va1);
                    t1[b_off_h(tl1 & 15, (d + 1) & 7)] = __float2half_rn(vb1);
                }
            }
        }
    }
}

// ============================================================
// Banded MMA attention: bulk cp.async staging from fragment
// arrays, GEMM1 / softmax / GEMM2 unchanged.
// ============================================================
#define AQT 64
#define SQ_B 0
#define SK_B 8192
#define SV_B 24576
#define SP_B 40960
#define SH_B 61440
#define SI_B 71680
#define ATT_SMEM (71680 + 256)

__global__ __launch_bounds__(256, 2)
void attn_kernel(const __half* __restrict__ QfG,
                 const __half* __restrict__ KfG,
                 const __half* __restrict__ VfG,
                 __half* __restrict__ Ox)
{
    extern __shared__ char smc[];
    uint32_t sb = smem_u32(smc);
    float*  Pf  = (float*) (smc + SP_B);
    __half* Ph  = (__half*)(smc + SH_B);
    float*  inv = (float*) (smc + SI_B);

    int tid = threadIdx.x;
    int q0  = blockIdx.x * AQT;
    int h   = blockIdx.y;
    int b   = blockIdx.z;
    int bh  = b * NUM_HEADS + h;

    // ---- bulk staging ----
    {
        const char* qsrc = (const char*)(QfG + ((size_t)bh * (SEQ / 16) + (q0 >> 4)) * 1024);
        #pragma unroll
        for (int p = 0; p < 2; p++) {
            int ch = tid + p * 256;           // 512 x 16B = 8KB
            cp_async16(sb + SQ_B + ch * 16, qsrc + ch * 16);
        }
        const char* ksrc = (const char*)(KfG + ((size_t)bh * KNT + (q0 >> 3)) * 512);
        #pragma unroll
        for (int p = 0; p < 4; p++) {
            int ch = tid + p * 256;           // 1024 x 16B = 16KB
            cp_async16(sb + SK_B + ch * 16, ksrc + ch * 16);
        }
        #pragma unroll
        for (int p = 0; p < 4; p++) {
            int ch = tid + p * 256;           // 1024 chunks; 128 per nt (2KB)
            int nt = ch >> 7, in = ch & 127;
            const char* vsrc = (const char*)(VfG + ((size_t)(bh * 8 + nt)) * (VKT * 128) + (size_t)(q0 >> 4) * 128);
            cp_async16(sb + SV_B + ch * 16, vsrc + in * 16);
        }
        cp_commit();
        cp_wait<0>();
    }
    __syncthreads();

    int w  = tid >> 5;
    int L  = tid & 31;
    int mt = w >> 1;
    int half = w & 1;

    // ---- GEMM1: banded S = Q K^T ----
    {
        uint32_t qbase = sb + SQ_B;
        uint32_t kbase = sb + SK_B;
        uint32_t af[4][4];
        #pragma unroll
        for (int kt = 0; kt < 4; kt++)
            lds128(af[kt], qbase + (uint32_t)(mt * 4 + kt) * 512 + L * 16);
        #pragma unroll
        for (int nn = 0; nn < 5; nn++) {
            int ntl = half * 5 + nn;
            int ntg = 2 * mt + ntl;
            float acc[4] = {0.f, 0.f, 0.f, 0.f};
            #pragma unroll
            for (int kt = 0; kt < 4; kt++) {
                uint32_t bfr[2];
                lds64(bfr, kbase + (uint32_t)(ntg * 4 + kt) * 256 + L * 8);
                mma_f16(acc, af[kt], bfr);
            }
            int r = L >> 2, c = (L & 3) * 2;
            float* Pt = Pf + (mt * 10 + ntl) * 128;
            Pt[c_off(r, c)]         = acc[0];
            Pt[c_off(r, c + 1)]     = acc[1];
            Pt[c_off(r + 8, c)]     = acc[2];
            Pt[c_off(r + 8, c + 1)] = acc[3];
        }
    }
    __syncthreads();

    // ---- softmax ----
    {
        int row  = tid >> 2;
        int part = tid & 3;
        int rmt = row >> 4, r = row & 15;
        float* Pb = Pf + rmt * 10 * 128;
        __half* Pw = Ph + rmt * 5 * 256;
        int jb = rmt * 16;

        float mx = -1e30f;
        #pragma unroll
        for (int u = 0; u < 20; u++) {
            int jl = part * 20 + u;
            int J  = jb + jl;
            int gk = q0 - WINDOW + J;
            bool valid = (J >= row) && (J <= row + 64) && (gk >= 0) && (gk < SEQ);
            float s = Pb[(jl >> 3) * 128 + c_off(r, jl & 7)];
            if (valid) mx = fmaxf(mx, s);
        }
        mx = fmaxf(mx, __shfl_xor_sync(0xffffffffu, mx, 1));
        mx = fmaxf(mx, __shfl_xor_sync(0xffffffffu, mx, 2));

        float sum = 0.f;
        #pragma unroll
        for (int u = 0; u < 20; u++) {
            int jl = part * 20 + u;
            int J  = jb + jl;
            int gk = q0 - WINDOW + J;
            bool valid = (J >= row) && (J <= row + 64) && (gk >= 0) && (gk < SEQ);
            float s = Pb[(jl >> 3) * 128 + c_off(r, jl & 7)];
            float e = valid ? __expf(s - mx) : 0.f;
            sum += e;
            Pw[(jl >> 4) * 256 + a_off_h(r, jl & 15)] = __float2half_rn(e);
        }
        sum += __shfl_xor_sync(0xffffffffu, sum, 1);
        sum += __shfl_xor_sync(0xffffffffu, sum, 2);
        if (part == 0) inv[row] = 1.0f / sum;
    }
    __syncthreads();

    // ---- GEMM2: O = P V ----
    {
        uint32_t pbase = sb + SH_B;
        uint32_t vbase = sb + SV_B;
        int ntd0 = half * 4;
        float acc2[4][4];
        #pragma unroll
        for (int j = 0; j < 4; j++)
            #pragma unroll
            for (int q = 0; q < 4; q++) acc2[j][q] = 0.f;

        #pragma unroll
        for (int ktl = 0; ktl < 5; ktl++) {
            int kt_tok = mt + ktl;
            uint32_t af[4];
            lds128(af, pbase + (uint32_t)(mt * 5 + ktl) * 512 + L * 16);
            #pragma unroll
            for (int jn = 0; jn < 4; jn++) {
                uint32_t bfr[2];
                lds64(bfr, vbase + (uint32_t)((ntd0 + jn) * 8 + kt_tok) * 256 + L * 8);
                mma_f16(acc2[jn], af, bfr);
            }
        }

        int r0 = mt * 16 + (L >> 2);
        float i0 = inv[r0], i1 = inv[r0 + 8];
        int grow0 = b * SEQ + q0 + r0;
        int grow1 = grow0 + 8;
        int gmt0 = grow0 >> 4, grr0 = grow0 & 15;
        int gmt1 = grow1 >> 4, grr1 = grow1 & 15;
        #pragma unroll
        for (int jn = 0; jn < 4; jn++) {
            int col = h * HEAD_DIM + (ntd0 + jn) * 8 + (L & 3) * 2;
            int kt = col >> 4, cc = col & 15;
            __half2* t0 = (__half2*)(Ox + ((size_t)gmt0 * KT16 + kt) * 256);
            __half2* t1 = (__half2*)(Ox + ((size_t)gmt1 * KT16 + kt) * 256);
            t0[a_off_h(grr0, cc) >> 1] = __floats2half2_rn(acc2[jn][0] * i0, acc2[jn][1] * i0);
            t1[a_off_h(grr1, cc) >> 1] = __floats2half2_rn(acc2[jn][2] * i1, acc2[jn][3] * i1);
        }
    }
}

// ============================================================
// launch
// ============================================================
extern "C" void kernel_launch(void* const* d_in, const int* in_sizes, int n_in,
                              void* d_out, int out_size)
{
    (void)in_sizes; (void)n_in; (void)out_size;
    const float* x     = (const float*)d_in[0];
    const float* w_q   = (const float*)d_in[1];
    const float* b_q   = (const float*)d_in[2];
    const float* w_k   = (const float*)d_in[3];
    const float* b_k   = (const float*)d_in[4];
    const float* w_v   = (const float*)d_in[5];
    const float* b_v   = (const float*)d_in[6];
    const float* w_o   = (const float*)d_in[7];
    const float* b_o   = (const float*)d_in[8];
    const float* gamma = (const float*)d_in[9];
    const float* beta  = (const float*)d_in[10];
    float* out = (float*)d_out;

    void *pHx, *pWqkv, *pWo, *pBq, *pQf, *pKf, *pVf, *pAx;
    cudaGetSymbolAddress(&pHx,   g_Hx);
    cudaGetSymbolAddress(&pWqkv, g_Wqkv);
    cudaGetSymbolAddress(&pWo,   g_Wo);
    cudaGetSymbolAddress(&pBq,   g_bqkv);
    cudaGetSymbolAddress(&pQf,   g_QfG);
    cudaGetSymbolAddress(&pKf,   g_KfG);
    cudaGetSymbolAddress(&pVf,   g_VfG);
    cudaGetSymbolAddress(&pAx,   g_ATTx);
    __half* Hx   = (__half*)pHx;
    __half* Wqkv = (__half*)pWqkv;
    __half* Wo   = (__half*)pWo;
    float*  bqkv = (float*)pBq;
    __half* QfG  = (__half*)pQf;
    __half* KfG  = (__half*)pKf;
    __half* VfG  = (__half*)pVf;
    __half* ATTx = (__half*)pAx;

    cudaFuncSetAttribute(mm_kernel<0>, cudaFuncAttributeMaxDynamicSharedMemorySize, MM_SMEM);
    cudaFuncSetAttribute(mm_kernel<1>, cudaFuncAttributeMaxDynamicSharedMemorySize, MM_SMEM);
    cudaFuncSetAttribute(attn_kernel, cudaFuncAttributeMaxDynamicSharedMemorySize, ATT_SMEM);

    // prep
    wconv_kernel<<<dim3(1024 * 1024 / 256, 4), 256>>>(w_q, w_k, w_v, w_o, Wqkv, Wo);
    bconcat_kernel<<<(QKV_LD + 255) / 256, 256>>>(b_q, b_k, b_v, bqkv);
    ln_kernel<<<MROWS, 256>>>(x, gamma, beta, Hx);

    // fused QKV GEMM -> fragment arrays
    dim3 gq(QKV_LD / BN, MROWS / BM);     // (24, 32)
    mm_kernel<0><<<gq, 256, MM_SMEM>>>(Hx, Wqkv, bqkv, nullptr, nullptr, 0, QfG, KfG, VfG);

    // banded MMA attention
    dim3 ga(SEQ / AQT, NUM_HEADS, BATCH); // (32, 16, 2)
    attn_kernel<<<ga, 256, ATT_SMEM>>>(QfG, KfG, VfG, ATTx);

    // output projection + bias + residual
    dim3 go(MODEL_DIM / BN, MROWS / BM);  // (8, 32)
    mm_kernel<1><<<go, 256, MM_SMEM>>>(ATTx, Wo, b_o, x, out, MODEL_DIM, nullptr, nullptr, nullptr);
}

// round 12
// speedup vs baseline: 3.8024x; 1.0137x over previous
#include <cuda_runtime.h>
#include <cuda_fp16.h>
#include <cstdint>
#include <math.h>

// ---------------- problem constants ----------------
#define MODEL_DIM 1024
#define NUM_HEADS 16
#define HEAD_DIM  64
#define WINDOW    32
#define EPS       1e-5f
#define BATCH     2
#define SEQ       2048
#define MROWS     (BATCH * SEQ)      // 4096
#define QKV_LD    (3 * MODEL_DIM)    // 3072
#define KDIM      MODEL_DIM          // 1024
#define KT16      (KDIM / 16)        // 64

#define KNT 264                       // (2048+64)/8 n-tiles (padded)
#define VKT 132                       // (2048+64)/16 k-tiles (padded)

// ---------------- scratch (fragment-ordered fp16) ----------------
__device__ __half g_Hx  [(MROWS / 16) * KT16 * 256];
__device__ __half g_Wqkv[(QKV_LD / 8) * KT16 * 128];
__device__ __half g_Wo  [(MODEL_DIM / 8) * KT16 * 128];
__device__ float  g_bqkv[QKV_LD];
__device__ __half g_QfG [BATCH * NUM_HEADS * (SEQ / 16) * 1024];
__device__ __half g_KfG [BATCH * NUM_HEADS * KNT * 512];
__device__ __half g_VfG [BATCH * NUM_HEADS * 8 * VKT * 128];
__device__ __half g_ATTx[(MROWS / 16) * KT16 * 256];

// ---------------- helpers ----------------
__device__ __forceinline__ uint32_t smem_u32(const void* p) {
    uint32_t a;
    asm("{ .reg .u64 t; cvta.to.shared.u64 t, %1; cvt.u32.u64 %0, t; }" : "=r"(a) : "l"(p));
    return a;
}
__device__ __forceinline__ void cp_async16(uint32_t dst, const void* src) {
    asm volatile("cp.async.cg.shared.global [%0], [%1], 16;" :: "r"(dst), "l"(src) : "memory");
}
__device__ __forceinline__ void cp_commit() {
    asm volatile("cp.async.commit_group;" ::: "memory");
}
template<int N>
__device__ __forceinline__ void cp_wait() {
    asm volatile("cp.async.wait_group %0;" :: "n"(N) : "memory");
}
__device__ __forceinline__ void lds128(uint32_t* r, uint32_t a) {
    asm volatile("ld.shared.v4.b32 {%0,%1,%2,%3}, [%4];"
                 : "=r"(r[0]), "=r"(r[1]), "=r"(r[2]), "=r"(r[3]) : "r"(a));
}
__device__ __forceinline__ void lds64(uint32_t* r, uint32_t a) {
    asm volatile("ld.shared.v2.b32 {%0,%1}, [%2];"
                 : "=r"(r[0]), "=r"(r[1]) : "r"(a));
}
__device__ __forceinline__ void mma_f16(float* c, const uint32_t* a, const uint32_t* b) {
    asm volatile("mma.sync.aligned.m16n8k16.row.col.f32.f16.f16.f32 "
                 "{%0,%1,%2,%3},{%4,%5,%6,%7},{%8,%9},{%0,%1,%2,%3};"
                 : "+f"(c[0]), "+f"(c[1]), "+f"(c[2]), "+f"(c[3])
                 : "r"(a[0]), "r"(a[1]), "r"(a[2]), "r"(a[3]), "r"(b[0]), "r"(b[1]));
}

// fragment maps (half index within tile)
__device__ __forceinline__ int a_off_h(int rr, int cc) {
    return ((rr & 7) * 4 + ((cc & 7) >> 1)) * 8 + ((rr >> 3) + 2 * (cc >> 3)) * 2 + (cc & 1);
}
__device__ __forceinline__ int b_off_h(int k, int n) {
    return (n * 4 + ((k & 7) >> 1)) * 4 + (k >> 3) * 2 + (k & 1);
}
__device__ __forceinline__ int c_off(int rr, int cc) {
    return ((rr & 7) * 4 + (cc >> 1)) * 4 + (rr >> 3) * 2 + (cc & 1);
}

// ============================================================
// LayerNorm -> A-fragment-ordered fp16
// ============================================================
__global__ __launch_bounds__(256)
void ln_kernel(const float* __restrict__ x,
               const float* __restrict__ gamma,
               const float* __restrict__ beta,
               __half* __restrict__ Hx)
{
    int row = blockIdx.x;
    int tid = threadIdx.x;
    float4 a = ((const float4*)(x + (size_t)row * MODEL_DIM))[tid];

    __shared__ float red[8];
    __shared__ float stat;

    float s = a.x + a.y + a.z + a.w;
    #pragma unroll
    for (int o = 16; o; o >>= 1) s += __shfl_xor_sync(0xffffffffu, s, o);
    if ((tid & 31) == 0) red[tid >> 5] = s;
    __syncthreads();
    if (tid == 0) {
        float t = 0.f;
        #pragma unroll
        for (int i = 0; i < 8; i++) t += red[i];
        stat = t * (1.0f / MODEL_DIM);
    }
    __syncthreads();
    float mu = stat;

    float dx = a.x - mu, dy = a.y - mu, dz = a.z - mu, dw = a.w - mu;
    float s2 = dx*dx + dy*dy + dz*dz + dw*dw;
    #pragma unroll
    for (int o = 16; o; o >>= 1) s2 += __shfl_xor_sync(0xffffffffu, s2, o);
    __syncthreads();
    if ((tid & 31) == 0) red[tid >> 5] = s2;
    __syncthreads();
    if (tid == 0) {
        float t = 0.f;
        #pragma unroll
        for (int i = 0; i < 8; i++) t += red[i];
        stat = rsqrtf(t * (1.0f / MODEL_DIM) + EPS);
    }
    __syncthreads();
    float rstd = stat;

    float4 g = ((const float4*)gamma)[tid];
    float4 b = ((const float4*)beta)[tid];
    float v0 = dx * rstd * g.x + b.x;
    float v1 = dy * rstd * g.y + b.y;
    float v2 = dz * rstd * g.z + b.z;
    float v3 = dw * rstd * g.w + b.w;

    int mt = row >> 4, r = row & 15;
    int kt = tid >> 2;
    int cc0 = (tid * 4) & 15;
    __half* tile = Hx + ((size_t)mt * KT16 + kt) * 256;
    ((__half2*)tile)[a_off_h(r, cc0) >> 1]     = __floats2half2_rn(v0, v1);
    ((__half2*)tile)[a_off_h(r, cc0 + 2) >> 1] = __floats2half2_rn(v2, v3);
}

// ============================================================
// Weight -> B-fragment-ordered fp16
// ============================================================
__global__ __launch_bounds__(256)
void wconv_kernel(const float* __restrict__ wq, const float* __restrict__ wk,
                  const float* __restrict__ wv, const float* __restrict__ wo,
                  __half* __restrict__ Wqkv, __half* __restrict__ Wo)
{
    int bz = blockIdx.y;
    const float* w = (bz == 0) ? wq : (bz == 1) ? wk : (bz == 2) ? wv : wo;
    __half* WT = (bz < 3) ? (Wqkv + (size_t)bz * (1024 / 8) * KT16 * 128) : Wo;

    int idx = blockIdx.x * 256 + threadIdx.x;
    int k = idx >> 10;
    int n = idx & 1023;
    float v = w[idx];
    int nt = n >> 3, kt = k >> 4;
    WT[((size_t)nt * KT16 + kt) * 128 + b_off_h(k & 15, n & 7)] = __float2half_rn(v);
}

__global__ void bconcat_kernel(const float* __restrict__ bq,
                               const float* __restrict__ bk,
                               const float* __restrict__ bv,
                               float* __restrict__ dst)
{
    int i = blockIdx.x * 256 + threadIdx.x;
    if (i >= QKV_LD) return;
    const float* s = (i < 1024) ? bq : (i < 2048 ? bk : bv);
    dst[i] = s[i & 1023];
}

// ============================================================
// fp16 mma.sync GEMM. CTA 128x128x32, 4 warps, warp tile 64x64,
// 3-stage cp.async, 2 CTA/SM. MODE 0: QKV -> frag arrays.
// MODE 1: out proj + resid.
// ============================================================
#define BM 128
#define BN 128
#define BK 32
#define A_TILE 8192
#define B_TILE 8192
#define STAGE_BYTES (A_TILE + B_TILE)
#define NSTAGE 3
#define NIT (KDIM / BK)
#define MM_SMEM (NSTAGE * STAGE_BYTES)
#define MM_THREADS 128

__device__ __forceinline__ void stage_A(const __half* __restrict__ src,
                                        int mt0, int kt0, uint32_t dst)
{
    #pragma unroll
    for (int p = 0; p < 4; p++) {
        int ch = threadIdx.x + p * MM_THREADS;   // 512 chunks of 16B
        int tl = ch >> 5;
        int in = ch & 31;
        int mti = tl >> 1, kti = tl & 1;
        const char* g = (const char*)(src + ((size_t)(mt0 + mti) * KT16 + kt0 + kti) * 256) + in * 16;
        cp_async16(dst + (uint32_t)tl * 512 + in * 16, g);
    }
}
__device__ __forceinline__ void stage_B(const __half* __restrict__ src,
                                        int nt0, int kt0, uint32_t dst)
{
    #pragma unroll
    for (int p = 0; p < 4; p++) {
        int ch = threadIdx.x + p * MM_THREADS;   // 512 chunks
        int tl = ch >> 4;
        int in = ch & 15;
        int nti = tl >> 1, kti = tl & 1;
        const char* g = (const char*)(src + ((size_t)(nt0 + nti) * KT16 + kt0 + kti) * 128) + in * 16;
        cp_async16(dst + (uint32_t)tl * 256 + in * 16, g);
    }
}

template<int MODE>
__global__ __launch_bounds__(MM_THREADS, 2)
void mm_kernel(const __half* __restrict__ A,
               const __half* __restrict__ B,
               const float* __restrict__ bias,
               const float* __restrict__ resid,
               float* __restrict__ C, int ldc,
               __half* __restrict__ Qf, __half* __restrict__ Kf, __half* __restrict__ Vf)
{
    extern __shared__ char smem[];
    uint32_t sb = smem_u32(smem);

    int tid  = threadIdx.x;
    int wid  = tid >> 5;
    int lane = tid & 31;
    int mtb = (wid >> 1) * 4;            // 2 m-groups of 4 mt (64 rows)
    int ntb = (wid & 1) * 8;             // 2 n-groups of 8 nt (64 cols)
    int mt0 = blockIdx.y * 8;
    int nt0 = blockIdx.x * 16;

    float acc[4][8][4];
    #pragma unroll
    for (int i = 0; i < 4; i++)
        #pragma unroll
        for (int j = 0; j < 8; j++)
            #pragma unroll
            for (int q = 0; q < 4; q++) acc[i][j][q] = 0.f;

    stage_A(A, mt0, 0, sb);
    stage_B(B, nt0, 0, sb + A_TILE);
    cp_commit();
    stage_A(A, mt0, 2, sb + STAGE_BYTES);
    stage_B(B, nt0, 2, sb + STAGE_BYTES + A_TILE);
    cp_commit();

    uint32_t aoff = (uint32_t)lane * 16;
    uint32_t boff = (uint32_t)lane * 8;

    #pragma unroll 1
    for (int it = 0; it < NIT; it++) {
        cp_wait<1>();
        __syncthreads();

        if (it + 2 < NIT) {
            uint32_t nb = sb + (uint32_t)((it + 2) % NSTAGE) * STAGE_BYTES;
            stage_A(A, mt0, (it + 2) * 2, nb);
            stage_B(B, nt0, (it + 2) * 2, nb + A_TILE);
        }
        cp_commit();

        uint32_t aB = sb + (uint32_t)(it % NSTAGE) * STAGE_BYTES;
        uint32_t bB = aB + A_TILE;

        #pragma unroll
        for (int kti = 0; kti < 2; kti++) {
            uint32_t af[4][4];
            uint32_t bfr[8][2];
            #pragma unroll
            for (int i = 0; i < 4; i++)
                lds128(af[i], aB + (uint32_t)((mtb + i) * 2 + kti) * 512 + aoff);
            #pragma unroll
            for (int j = 0; j < 8; j++)
                lds64(bfr[j], bB + (uint32_t)((ntb + j) * 2 + kti) * 256 + boff);
            #pragma unroll
            for (int i = 0; i < 4; i++)
                #pragma unroll
                for (int j = 0; j < 8; j++)
                    mma_f16(acc[i][j], af[i], bfr[j]);
        }
    }

    int mBase = mt0 * 16 + mtb * 16 + (lane >> 2);
    int nBase = nt0 * 8 + ntb * 8 + (lane & 3) * 2;

    if (MODE == 1) {
        #pragma unroll
        for (int i = 0; i < 4; i++) {
            int m0 = mBase + i * 16;
            #pragma unroll
            for (int j = 0; j < 8; j++) {
                int n = nBase + j * 8;
                float bx0 = bias[n], bx1 = bias[n + 1];
                float2 v0, v1;
                v0.x = acc[i][j][0] + bx0;
                v0.y = acc[i][j][1] + bx1;
                v1.x = acc[i][j][2] + bx0;
                v1.y = acc[i][j][3] + bx1;
                float2 r0 = *(const float2*)(resid + (size_t)m0 * MODEL_DIM + n);
                float2 r1 = *(const float2*)(resid + (size_t)(m0 + 8) * MODEL_DIM + n);
                v0.x += r0.x; v0.y += r0.y;
                v1.x += r1.x; v1.y += r1.y;
                *(float2*)(C + (size_t)m0 * ldc + n)       = v0;
                *(float2*)(C + (size_t)(m0 + 8) * ldc + n) = v1;
            }
        }
    } else {
        int mtype = (nt0 * 8) >> 10;   // 0=Q 1=K 2=V (uniform per CTA)
        #pragma unroll
        for (int i = 0; i < 4; i++) {
            int m0 = mBase + i * 16;
            int bb  = m0 >> 11;
            int tok = m0 & 2047;
            #pragma unroll
            for (int j = 0; j < 8; j++) {
                int n = nBase + j * 8;
                float bx0 = bias[n], bx1 = bias[n + 1];
                float va0 = acc[i][j][0] + bx0, vb0 = acc[i][j][1] + bx1;
                float va1 = acc[i][j][2] + bx0, vb1 = acc[i][j][3] + bx1;
                int nn = n & 1023;
                int h = nn >> 6, d = nn & 63;
                int bh = bb * NUM_HEADS + h;
                if (mtype == 0) {
                    int kt = d >> 4, cc = d & 15;
                    __half2 h0 = __floats2half2_rn(va0 * 0.125f, vb0 * 0.125f);
                    __half2 h1 = __floats2half2_rn(va1 * 0.125f, vb1 * 0.125f);
                    __half* t0 = Qf + ((size_t)(bh * (SEQ / 16) + (tok >> 4))) * 1024 + kt * 256;
                    __half* t1 = Qf + ((size_t)(bh * (SEQ / 16) + ((tok + 8) >> 4))) * 1024 + kt * 256;
                    ((__half2*)t0)[a_off_h(tok & 15, cc) >> 1]       = h0;
                    ((__half2*)t1)[a_off_h((tok + 8) & 15, cc) >> 1] = h1;
                } else if (mtype == 1) {
                    int kt = d >> 4;
                    int tl0 = tok + 32, tl1 = tok + 40;
                    __half* t0 = Kf + ((size_t)(bh * KNT + (tl0 >> 3))) * 512 + kt * 128;
                    __half* t1 = Kf + ((size_t)(bh * KNT + (tl1 >> 3))) * 512 + kt * 128;
                    ((__half2*)t0)[b_off_h(d & 15, tl0 & 7) >> 1] = __floats2half2_rn(va0, vb0);
                    ((__half2*)t1)[b_off_h(d & 15, tl1 & 7) >> 1] = __floats2half2_rn(va1, vb1);
                } else {
                    int nt = d >> 3;
                    int tl0 = tok + 32, tl1 = tok + 40;
                    __half* base = Vf + ((size_t)(bh * 8 + nt)) * (VKT * 128);
                    __half* t0 = base + (tl0 >> 4) * 128;
                    __half* t1 = base + (tl1 >> 4) * 128;
                    t0[b_off_h(tl0 & 15, d & 7)]       = __float2half_rn(va0);
                    t0[b_off_h(tl0 & 15, (d + 1) & 7)] = __float2half_rn(vb0);
                    t1[b_off_h(tl1 & 15, d & 7)]       = __float2half_rn(va1);
                    t1[b_off_h(tl1 & 15, (d + 1) & 7)] = __float2half_rn(vb1);
                }
            }
        }
    }
}

// ============================================================
// Banded MMA attention (unchanged from R11)
// ============================================================
#define AQT 64
#define SQ_B 0
#define SK_B 8192
#define SV_B 24576
#define SP_B 40960
#define SH_B 61440
#define SI_B 71680
#define ATT_SMEM (71680 + 256)

__global__ __launch_bounds__(256, 2)
void attn_kernel(const __half* __restrict__ QfG,
                 const __half* __restrict__ KfG,
                 const __half* __restrict__ VfG,
                 __half* __restrict__ Ox)
{
    extern __shared__ char smc[];
    uint32_t sb = smem_u32(smc);
    float*  Pf  = (float*) (smc + SP_B);
    __half* Ph  = (__half*)(smc + SH_B);
    float*  inv = (float*) (smc + SI_B);

    int tid = threadIdx.x;
    int q0  = blockIdx.x * AQT;
    int h   = blockIdx.y;
    int b   = blockIdx.z;
    int bh  = b * NUM_HEADS + h;

    {
        const char* qsrc = (const char*)(QfG + ((size_t)bh * (SEQ / 16) + (q0 >> 4)) * 1024);
        #pragma unroll
        for (int p = 0; p < 2; p++) {
            int ch = tid + p * 256;
            cp_async16(sb + SQ_B + ch * 16, qsrc + ch * 16);
        }
        const char* ksrc = (const char*)(KfG + ((size_t)bh * KNT + (q0 >> 3)) * 512);
        #pragma unroll
        for (int p = 0; p < 4; p++) {
            int ch = tid + p * 256;
            cp_async16(sb + SK_B + ch * 16, ksrc + ch * 16);
        }
        #pragma unroll
        for (int p = 0; p < 4; p++) {
            int ch = tid + p * 256;
            int nt = ch >> 7, in = ch & 127;
            const char* vsrc = (const char*)(VfG + ((size_t)(bh * 8 + nt)) * (VKT * 128) + (size_t)(q0 >> 4) * 128);
            cp_async16(sb + SV_B + ch * 16, vsrc + in * 16);
        }
        cp_commit();
        cp_wait<0>();
    }
    __syncthreads();

    int w  = tid >> 5;
    int L  = tid & 31;
    int mt = w >> 1;
    int half = w & 1;

    // ---- GEMM1: banded S = Q K^T ----
    {
        uint32_t qbase = sb + SQ_B;
        uint32_t kbase = sb + SK_B;
        uint32_t af[4][4];
        #pragma unroll
        for (int kt = 0; kt < 4; kt++)
            lds128(af[kt], qbase + (uint32_t)(mt * 4 + kt) * 512 + L * 16);
        #pragma unroll
        for (int nn = 0; nn < 5; nn++) {
            int ntl = half * 5 + nn;
            int ntg = 2 * mt + ntl;
            float acc[4] = {0.f, 0.f, 0.f, 0.f};
            #pragma unroll
            for (int kt = 0; kt < 4; kt++) {
                uint32_t bfr[2];
                lds64(bfr, kbase + (uint32_t)(ntg * 4 + kt) * 256 + L * 8);
                mma_f16(acc, af[kt], bfr);
            }
            int r = L >> 2, c = (L & 3) * 2;
            float* Pt = Pf + (mt * 10 + ntl) * 128;
            Pt[c_off(r, c)]         = acc[0];
            Pt[c_off(r, c + 1)]     = acc[1];
            Pt[c_off(r + 8, c)]     = acc[2];
            Pt[c_off(r + 8, c + 1)] = acc[3];
        }
    }
    __syncthreads();

    // ---- softmax ----
    {
        int row  = tid >> 2;
        int part = tid & 3;
        int rmt = row >> 4, r = row & 15;
        float* Pb = Pf + rmt * 10 * 128;
        __half* Pw = Ph + rmt * 5 * 256;
        int jb = rmt * 16;

        float mx = -1e30f;
        #pragma unroll
        for (int u = 0; u < 20; u++) {
            int jl = part * 20 + u;
            int J  = jb + jl;
            int gk = q0 - WINDOW + J;
            bool valid = (J >= row) && (J <= row + 64) && (gk >= 0) && (gk < SEQ);
            float s = Pb[(jl >> 3) * 128 + c_off(r, jl & 7)];
            if (valid) mx = fmaxf(mx, s);
        }
        mx = fmaxf(mx, __shfl_xor_sync(0xffffffffu, mx, 1));
        mx = fmaxf(mx, __shfl_xor_sync(0xffffffffu, mx, 2));

        float sum = 0.f;
        #pragma unroll
        for (int u = 0; u < 20; u++) {
            int jl = part * 20 + u;
            int J  = jb + jl;
            int gk = q0 - WINDOW + J;
            bool valid = (J >= row) && (J <= row + 64) && (gk >= 0) && (gk < SEQ);
            float s = Pb[(jl >> 3) * 128 + c_off(r, jl & 7)];
            float e = valid ? __expf(s - mx) : 0.f;
            sum += e;
            Pw[(jl >> 4) * 256 + a_off_h(r, jl & 15)] = __float2half_rn(e);
        }
        sum += __shfl_xor_sync(0xffffffffu, sum, 1);
        sum += __shfl_xor_sync(0xffffffffu, sum, 2);
        if (part == 0) inv[row] = 1.0f / sum;
    }
    __syncthreads();

    // ---- GEMM2: O = P V ----
    {
        uint32_t pbase = sb + SH_B;
        uint32_t vbase = sb + SV_B;
        int ntd0 = half * 4;
        float acc2[4][4];
        #pragma unroll
        for (int j = 0; j < 4; j++)
            #pragma unroll
            for (int q = 0; q < 4; q++) acc2[j][q] = 0.f;

        #pragma unroll
        for (int ktl = 0; ktl < 5; ktl++) {
            int kt_tok = mt + ktl;
            uint32_t af[4];
            lds128(af, pbase + (uint32_t)(mt * 5 + ktl) * 512 + L * 16);
            #pragma unroll
            for (int jn = 0; jn < 4; jn++) {
                uint32_t bfr[2];
                lds64(bfr, vbase + (uint32_t)((ntd0 + jn) * 8 + kt_tok) * 256 + L * 8);
                mma_f16(acc2[jn], af, bfr);
            }
        }

        int r0 = mt * 16 + (L >> 2);
        float i0 = inv[r0], i1 = inv[r0 + 8];
        int grow0 = b * SEQ + q0 + r0;
        int grow1 = grow0 + 8;
        int gmt0 = grow0 >> 4, grr0 = grow0 & 15;
        int gmt1 = grow1 >> 4, grr1 = grow1 & 15;
        #pragma unroll
        for (int jn = 0; jn < 4; jn++) {
            int col = h * HEAD_DIM + (ntd0 + jn) * 8 + (L & 3) * 2;
            int kt = col >> 4, cc = col & 15;
            __half2* t0 = (__half2*)(Ox + ((size_t)gmt0 * KT16 + kt) * 256);
            __half2* t1 = (__half2*)(Ox + ((size_t)gmt1 * KT16 + kt) * 256);
            t0[a_off_h(grr0, cc) >> 1] = __floats2half2_rn(acc2[jn][0] * i0, acc2[jn][1] * i0);
            t1[a_off_h(grr1, cc) >> 1] = __floats2half2_rn(acc2[jn][2] * i1, acc2[jn][3] * i1);
        }
    }
}

// ============================================================
// launch
// ============================================================
extern "C" void kernel_launch(void* const* d_in, const int* in_sizes, int n_in,
                              void* d_out, int out_size)
{
    (void)in_sizes; (void)n_in; (void)out_size;
    const float* x     = (const float*)d_in[0];
    const float* w_q   = (const float*)d_in[1];
    const float* b_q   = (const float*)d_in[2];
    const float* w_k   = (const float*)d_in[3];
    const float* b_k   = (const float*)d_in[4];
    const float* w_v   = (const float*)d_in[5];
    const float* b_v   = (const float*)d_in[6];
    const float* w_o   = (const float*)d_in[7];
    const float* b_o   = (const float*)d_in[8];
    const float* gamma = (const float*)d_in[9];
    const float* beta  = (const float*)d_in[10];
    float* out = (float*)d_out;

    void *pHx, *pWqkv, *pWo, *pBq, *pQf, *pKf, *pVf, *pAx;
    cudaGetSymbolAddress(&pHx,   g_Hx);
    cudaGetSymbolAddress(&pWqkv, g_Wqkv);
    cudaGetSymbolAddress(&pWo,   g_Wo);
    cudaGetSymbolAddress(&pBq,   g_bqkv);
    cudaGetSymbolAddress(&pQf,   g_QfG);
    cudaGetSymbolAddress(&pKf,   g_KfG);
    cudaGetSymbolAddress(&pVf,   g_VfG);
    cudaGetSymbolAddress(&pAx,   g_ATTx);
    __half* Hx   = (__half*)pHx;
    __half* Wqkv = (__half*)pWqkv;
    __half* Wo   = (__half*)pWo;
    float*  bqkv = (float*)pBq;
    __half* QfG  = (__half*)pQf;
    __half* KfG  = (__half*)pKf;
    __half* VfG  = (__half*)pVf;
    __half* ATTx = (__half*)pAx;

    cudaFuncSetAttribute(mm_kernel<0>, cudaFuncAttributeMaxDynamicSharedMemorySize, MM_SMEM);
    cudaFuncSetAttribute(mm_kernel<1>, cudaFuncAttributeMaxDynamicSharedMemorySize, MM_SMEM);
    cudaFuncSetAttribute(attn_kernel, cudaFuncAttributeMaxDynamicSharedMemorySize, ATT_SMEM);

    // prep
    wconv_kernel<<<dim3(1024 * 1024 / 256, 4), 256>>>(w_q, w_k, w_v, w_o, Wqkv, Wo);
    bconcat_kernel<<<(QKV_LD + 255) / 256, 256>>>(b_q, b_k, b_v, bqkv);
    ln_kernel<<<MROWS, 256>>>(x, gamma, beta, Hx);

    // fused QKV GEMM -> fragment arrays
    dim3 gq(QKV_LD / BN, MROWS / BM);     // (24, 32)
    mm_kernel<0><<<gq, MM_THREADS, MM_SMEM>>>(Hx, Wqkv, bqkv, nullptr, nullptr, 0, QfG, KfG, VfG);

    // banded MMA attention
    dim3 ga(SEQ / AQT, NUM_HEADS, BATCH); // (32, 16, 2)
    attn_kernel<<<ga, 256, ATT_SMEM>>>(QfG, KfG, VfG, ATTx);

    // output projection + bias + residual
    dim3 go(MODEL_DIM / BN, MROWS / BM);  // (8, 32)
    mm_kernel<1><<<go, MM_THREADS, MM_SMEM>>>(ATTx, Wo, b_o, x, out, MODEL_DIM, nullptr, nullptr, nullptr);
}

// round 13
// speedup vs baseline: 3.8657x; 1.0166x over previous
#include <cuda_runtime.h>
#include <cuda_fp16.h>
#include <cstdint>
#include <math.h>

// ---------------- problem constants ----------------
#define MODEL_DIM 1024
#define NUM_HEADS 16
#define HEAD_DIM  64
#define WINDOW    32
#define EPS       1e-5f
#define BATCH     2
#define SEQ       2048
#define MROWS     (BATCH * SEQ)      // 4096
#define QKV_LD    (3 * MODEL_DIM)    // 3072
#define KDIM      MODEL_DIM          // 1024
#define KT16      (KDIM / 16)        // 64

#define KNT 264                       // (2048+64)/8 n-tiles (padded)
#define VKT 132                       // (2048+64)/16 k-tiles (padded)

// ---------------- scratch (fragment-ordered fp16) ----------------
__device__ __half g_Hx  [(MROWS / 16) * KT16 * 256];
__device__ __half g_Wqkv[(QKV_LD / 8) * KT16 * 128];
__device__ __half g_Wo  [(MODEL_DIM / 8) * KT16 * 128];
__device__ float  g_bqkv[QKV_LD];
__device__ __half g_QfG [BATCH * NUM_HEADS * (SEQ / 16) * 1024];
__device__ __half g_KfG [BATCH * NUM_HEADS * KNT * 512];
__device__ __half g_VfG [BATCH * NUM_HEADS * 8 * VKT * 128];
__device__ __half g_ATTx[(MROWS / 16) * KT16 * 256];

// ---------------- helpers ----------------
__device__ __forceinline__ uint32_t smem_u32(const void* p) {
    uint32_t a;
    asm("{ .reg .u64 t; cvta.to.shared.u64 t, %1; cvt.u32.u64 %0, t; }" : "=r"(a) : "l"(p));
    return a;
}
__device__ __forceinline__ void cp_async16(uint32_t dst, const void* src) {
    asm volatile("cp.async.cg.shared.global [%0], [%1], 16;" :: "r"(dst), "l"(src) : "memory");
}
__device__ __forceinline__ void cp_commit() {
    asm volatile("cp.async.commit_group;" ::: "memory");
}
template<int N>
__device__ __forceinline__ void cp_wait() {
    asm volatile("cp.async.wait_group %0;" :: "n"(N) : "memory");
}
__device__ __forceinline__ void lds128(uint32_t* r, uint32_t a) {
    asm volatile("ld.shared.v4.b32 {%0,%1,%2,%3}, [%4];"
                 : "=r"(r[0]), "=r"(r[1]), "=r"(r[2]), "=r"(r[3]) : "r"(a));
}
__device__ __forceinline__ void lds64(uint32_t* r, uint32_t a) {
    asm volatile("ld.shared.v2.b32 {%0,%1}, [%2];"
                 : "=r"(r[0]), "=r"(r[1]) : "r"(a));
}
__device__ __forceinline__ void mma_f16(float* c, const uint32_t* a, const uint32_t* b) {
    asm volatile("mma.sync.aligned.m16n8k16.row.col.f32.f16.f16.f32 "
                 "{%0,%1,%2,%3},{%4,%5,%6,%7},{%8,%9},{%0,%1,%2,%3};"
                 : "+f"(c[0]), "+f"(c[1]), "+f"(c[2]), "+f"(c[3])
                 : "r"(a[0]), "r"(a[1]), "r"(a[2]), "r"(a[3]), "r"(b[0]), "r"(b[1]));
}

// fragment maps (half index within tile)
__device__ __forceinline__ int a_off_h(int rr, int cc) {
    return ((rr & 7) * 4 + ((cc & 7) >> 1)) * 8 + ((rr >> 3) + 2 * (cc >> 3)) * 2 + (cc & 1);
}
__device__ __forceinline__ int b_off_h(int k, int n) {
    return (n * 4 + ((k & 7) >> 1)) * 4 + (k >> 3) * 2 + (k & 1);
}
__device__ __forceinline__ int c_off(int rr, int cc) {
    return ((rr & 7) * 4 + (cc >> 1)) * 4 + (rr >> 3) * 2 + (cc & 1);
}

// ============================================================
// LayerNorm -> A-fragment-ordered fp16
// ============================================================
__global__ __launch_bounds__(256)
void ln_kernel(const float* __restrict__ x,
               const float* __restrict__ gamma,
               const float* __restrict__ beta,
               __half* __restrict__ Hx)
{
    int row = blockIdx.x;
    int tid = threadIdx.x;
    float4 a = ((const float4*)(x + (size_t)row * MODEL_DIM))[tid];

    __shared__ float red[8];
    __shared__ float stat;

    float s = a.x + a.y + a.z + a.w;
    #pragma unroll
    for (int o = 16; o; o >>= 1) s += __shfl_xor_sync(0xffffffffu, s, o);
    if ((tid & 31) == 0) red[tid >> 5] = s;
    __syncthreads();
    if (tid == 0) {
        float t = 0.f;
        #pragma unroll
        for (int i = 0; i < 8; i++) t += red[i];
        stat = t * (1.0f / MODEL_DIM);
    }
    __syncthreads();
    float mu = stat;

    float dx = a.x - mu, dy = a.y - mu, dz = a.z - mu, dw = a.w - mu;
    float s2 = dx*dx + dy*dy + dz*dz + dw*dw;
    #pragma unroll
    for (int o = 16; o; o >>= 1) s2 += __shfl_xor_sync(0xffffffffu, s2, o);
    __syncthreads();
    if ((tid & 31) == 0) red[tid >> 5] = s2;
    __syncthreads();
    if (tid == 0) {
        float t = 0.f;
        #pragma unroll
        for (int i = 0; i < 8; i++) t += red[i];
        stat = rsqrtf(t * (1.0f / MODEL_DIM) + EPS);
    }
    __syncthreads();
    float rstd = stat;

    float4 g = ((const float4*)gamma)[tid];
    float4 b = ((const float4*)beta)[tid];
    float v0 = dx * rstd * g.x + b.x;
    float v1 = dy * rstd * g.y + b.y;
    float v2 = dz * rstd * g.z + b.z;
    float v3 = dw * rstd * g.w + b.w;

    int mt = row >> 4, r = row & 15;
    int kt = tid >> 2;
    int cc0 = (tid * 4) & 15;
    __half* tile = Hx + ((size_t)mt * KT16 + kt) * 256;
    ((__half2*)tile)[a_off_h(r, cc0) >> 1]     = __floats2half2_rn(v0, v1);
    ((__half2*)tile)[a_off_h(r, cc0 + 2) >> 1] = __floats2half2_rn(v2, v3);
}

// ============================================================
// Weight -> B-fragment-ordered fp16
// ============================================================
__global__ __launch_bounds__(256)
void wconv_kernel(const float* __restrict__ wq, const float* __restrict__ wk,
                  const float* __restrict__ wv, const float* __restrict__ wo,
                  __half* __restrict__ Wqkv, __half* __restrict__ Wo)
{
    int bz = blockIdx.y;
    const float* w = (bz == 0) ? wq : (bz == 1) ? wk : (bz == 2) ? wv : wo;
    __half* WT = (bz < 3) ? (Wqkv + (size_t)bz * (1024 / 8) * KT16 * 128) : Wo;

    int idx = blockIdx.x * 256 + threadIdx.x;
    int k = idx >> 10;
    int n = idx & 1023;
    float v = w[idx];
    int nt = n >> 3, kt = k >> 4;
    WT[((size_t)nt * KT16 + kt) * 128 + b_off_h(k & 15, n & 7)] = __float2half_rn(v);
}

__global__ void bconcat_kernel(const float* __restrict__ bq,
                               const float* __restrict__ bk,
                               const float* __restrict__ bv,
                               float* __restrict__ dst)
{
    int i = blockIdx.x * 256 + threadIdx.x;
    if (i >= QKV_LD) return;
    const float* s = (i < 1024) ? bq : (i < 2048 ? bk : bv);
    dst[i] = s[i & 1023];
}

// ============================================================
// fp16 mma.sync GEMM. CTA 128x128x64, 4 warps (64x64), 3-stage
// cp.async (32KB stages), 2 CTA/SM, 16 K-iterations.
// ============================================================
#define BM 128
#define BN 128
#define BK 64
#define A_TILE 16384                  // 8mt x 4kt x 512B
#define B_TILE 16384                  // 16nt x 4kt x 256B
#define STAGE_BYTES (A_TILE + B_TILE) // 32768
#define NSTAGE 3
#define NIT (KDIM / BK)               // 16
#define MM_SMEM (NSTAGE * STAGE_BYTES)// 98304
#define MM_THREADS 128

__device__ __forceinline__ void stage_A(const __half* __restrict__ src,
                                        int mt0, int kt0, uint32_t dst)
{
    #pragma unroll
    for (int p = 0; p < 8; p++) {
        int ch = threadIdx.x + p * MM_THREADS;   // 1024 chunks of 16B
        int tl = ch >> 5;                        // 32 tiles (mti*4+kti)
        int in = ch & 31;
        int mti = tl >> 2, kti = tl & 3;
        const char* g = (const char*)(src + ((size_t)(mt0 + mti) * KT16 + kt0 + kti) * 256) + in * 16;
        cp_async16(dst + (uint32_t)tl * 512 + in * 16, g);
    }
}
__device__ __forceinline__ void stage_B(const __half* __restrict__ src,
                                        int nt0, int kt0, uint32_t dst)
{
    #pragma unroll
    for (int p = 0; p < 8; p++) {
        int ch = threadIdx.x + p * MM_THREADS;   // 1024 chunks
        int tl = ch >> 4;                        // 64 tiles (nti*4+kti)
        int in = ch & 15;
        int nti = tl >> 2, kti = tl & 3;
        const char* g = (const char*)(src + ((size_t)(nt0 + nti) * KT16 + kt0 + kti) * 128) + in * 16;
        cp_async16(dst + (uint32_t)tl * 256 + in * 16, g);
    }
}

template<int MODE>
__global__ __launch_bounds__(MM_THREADS, 2)
void mm_kernel(const __half* __restrict__ A,
               const __half* __restrict__ B,
               const float* __restrict__ bias,
               const float* __restrict__ resid,
               float* __restrict__ C, int ldc,
               __half* __restrict__ Qf, __half* __restrict__ Kf, __half* __restrict__ Vf)
{
    extern __shared__ char smem[];
    uint32_t sb = smem_u32(smem);

    int tid  = threadIdx.x;
    int wid  = tid >> 5;
    int lane = tid & 31;
    int mtb = (wid >> 1) * 4;
    int ntb = (wid & 1) * 8;
    int mt0 = blockIdx.y * 8;
    int nt0 = blockIdx.x * 16;

    float acc[4][8][4];
    #pragma unroll
    for (int i = 0; i < 4; i++)
        #pragma unroll
        for (int j = 0; j < 8; j++)
            #pragma unroll
            for (int q = 0; q < 4; q++) acc[i][j][q] = 0.f;

    stage_A(A, mt0, 0, sb);
    stage_B(B, nt0, 0, sb + A_TILE);
    cp_commit();
    stage_A(A, mt0, 4, sb + STAGE_BYTES);
    stage_B(B, nt0, 4, sb + STAGE_BYTES + A_TILE);
    cp_commit();

    uint32_t aoff = (uint32_t)lane * 16;
    uint32_t boff = (uint32_t)lane * 8;

    #pragma unroll 1
    for (int it = 0; it < NIT; it++) {
        cp_wait<1>();
        __syncthreads();

        if (it + 2 < NIT) {
            uint32_t nb = sb + (uint32_t)((it + 2) % NSTAGE) * STAGE_BYTES;
            stage_A(A, mt0, (it + 2) * 4, nb);
            stage_B(B, nt0, (it + 2) * 4, nb + A_TILE);
        }
        cp_commit();

        uint32_t aB = sb + (uint32_t)(it % NSTAGE) * STAGE_BYTES;
        uint32_t bB = aB + A_TILE;

        #pragma unroll
        for (int kti = 0; kti < 4; kti++) {
            uint32_t af[4][4];
            uint32_t bfr[8][2];
            #pragma unroll
            for (int i = 0; i < 4; i++)
                lds128(af[i], aB + (uint32_t)((mtb + i) * 4 + kti) * 512 + aoff);
            #pragma unroll
            for (int j = 0; j < 8; j++)
                lds64(bfr[j], bB + (uint32_t)((ntb + j) * 4 + kti) * 256 + boff);
            #pragma unroll
            for (int i = 0; i < 4; i++)
                #pragma unroll
                for (int j = 0; j < 8; j++)
                    mma_f16(acc[i][j], af[i], bfr[j]);
        }
    }

    int mBase = mt0 * 16 + mtb * 16 + (lane >> 2);
    int nBase = nt0 * 8 + ntb * 8 + (lane & 3) * 2;

    if (MODE == 1) {
        #pragma unroll
        for (int i = 0; i < 4; i++) {
            int m0 = mBase + i * 16;
            #pragma unroll
            for (int j = 0; j < 8; j++) {
                int n = nBase + j * 8;
                float bx0 = bias[n], bx1 = bias[n + 1];
                float2 v0, v1;
                v0.x = acc[i][j][0] + bx0;
                v0.y = acc[i][j][1] + bx1;
                v1.x = acc[i][j][2] + bx0;
                v1.y = acc[i][j][3] + bx1;
                float2 r0 = *(const float2*)(resid + (size_t)m0 * MODEL_DIM + n);
                float2 r1 = *(const float2*)(resid + (size_t)(m0 + 8) * MODEL_DIM + n);
                v0.x += r0.x; v0.y += r0.y;
                v1.x += r1.x; v1.y += r1.y;
                *(float2*)(C + (size_t)m0 * ldc + n)       = v0;
                *(float2*)(C + (size_t)(m0 + 8) * ldc + n) = v1;
            }
        }
    } else {
        int mtype = (nt0 * 8) >> 10;   // 0=Q 1=K 2=V (uniform per CTA)
        #pragma unroll
        for (int i = 0; i < 4; i++) {
            int m0 = mBase + i * 16;
            int bb  = m0 >> 11;
            int tok = m0 & 2047;
            #pragma unroll
            for (int j = 0; j < 8; j++) {
                int n = nBase + j * 8;
                float bx0 = bias[n], bx1 = bias[n + 1];
                float va0 = acc[i][j][0] + bx0, vb0 = acc[i][j][1] + bx1;
                float va1 = acc[i][j][2] + bx0, vb1 = acc[i][j][3] + bx1;
                int nn = n & 1023;
                int h = nn >> 6, d = nn & 63;
                int bh = bb * NUM_HEADS + h;
                if (mtype == 0) {
                    int kt = d >> 4, cc = d & 15;
                    __half2 h0 = __floats2half2_rn(va0 * 0.125f, vb0 * 0.125f);
                    __half2 h1 = __floats2half2_rn(va1 * 0.125f, vb1 * 0.125f);
                    __half* t0 = Qf + ((size_t)(bh * (SEQ / 16) + (tok >> 4))) * 1024 + kt * 256;
                    __half* t1 = Qf + ((size_t)(bh * (SEQ / 16) + ((tok + 8) >> 4))) * 1024 + kt * 256;
                    ((__half2*)t0)[a_off_h(tok & 15, cc) >> 1]       = h0;
                    ((__half2*)t1)[a_off_h((tok + 8) & 15, cc) >> 1] = h1;
                } else if (mtype == 1) {
                    int kt = d >> 4;
                    int tl0 = tok + 32, tl1 = tok + 40;
                    __half* t0 = Kf + ((size_t)(bh * KNT + (tl0 >> 3))) * 512 + kt * 128;
                    __half* t1 = Kf + ((size_t)(bh * KNT + (tl1 >> 3))) * 512 + kt * 128;
                    ((__half2*)t0)[b_off_h(d & 15, tl0 & 7) >> 1] = __floats2half2_rn(va0, vb0);
                    ((__half2*)t1)[b_off_h(d & 15, tl1 & 7) >> 1] = __floats2half2_rn(va1, vb1);
                } else {
                    int nt = d >> 3;
                    int tl0 = tok + 32, tl1 = tok + 40;
                    __half* base = Vf + ((size_t)(bh * 8 + nt)) * (VKT * 128);
                    __half* t0 = base + (tl0 >> 4) * 128;
                    __half* t1 = base + (tl1 >> 4) * 128;
                    t0[b_off_h(tl0 & 15, d & 7)]       = __float2half_rn(va0);
                    t0[b_off_h(tl0 & 15, (d + 1) & 7)] = __float2half_rn(vb0);
                    t1[b_off_h(tl1 & 15, d & 7)]       = __float2half_rn(va1);
                    t1[b_off_h(tl1 & 15, (d + 1) & 7)] = __float2half_rn(vb1);
                }
            }
        }
    }
}

// ============================================================
// Banded MMA attention (unchanged)
// ============================================================
#define AQT 64
#define SQ_B 0
#define SK_B 8192
#define SV_B 24576
#define SP_B 40960
#define SH_B 61440
#define SI_B 71680
#define ATT_SMEM (71680 + 256)

__global__ __launch_bounds__(256, 2)
void attn_kernel(const __half* __restrict__ QfG,
                 const __half* __restrict__ KfG,
                 const __half* __restrict__ VfG,
                 __half* __restrict__ Ox)
{
    extern __shared__ char smc[];
    uint32_t sb = smem_u32(smc);
    float*  Pf  = (float*) (smc + SP_B);
    __half* Ph  = (__half*)(smc + SH_B);
    float*  inv = (float*) (smc + SI_B);

    int tid = threadIdx.x;
    int q0  = blockIdx.x * AQT;
    int h   = blockIdx.y;
    int b   = blockIdx.z;
    int bh  = b * NUM_HEADS + h;

    {
        const char* qsrc = (const char*)(QfG + ((size_t)bh * (SEQ / 16) + (q0 >> 4)) * 1024);
        #pragma unroll
        for (int p = 0; p < 2; p++) {
            int ch = tid + p * 256;
            cp_async16(sb + SQ_B + ch * 16, qsrc + ch * 16);
        }
        const char* ksrc = (const char*)(KfG + ((size_t)bh * KNT + (q0 >> 3)) * 512);
        #pragma unroll
        for (int p = 0; p < 4; p++) {
            int ch = tid + p * 256;
            cp_async16(sb + SK_B + ch * 16, ksrc + ch * 16);
        }
        #pragma unroll
        for (int p = 0; p < 4; p++) {
            int ch = tid + p * 256;
            int nt = ch >> 7, in = ch & 127;
            const char* vsrc = (const char*)(VfG + ((size_t)(bh * 8 + nt)) * (VKT * 128) + (size_t)(q0 >> 4) * 128);
            cp_async16(sb + SV_B + ch * 16, vsrc + in * 16);
        }
        cp_commit();
        cp_wait<0>();
    }
    __syncthreads();

    int w  = tid >> 5;
    int L  = tid & 31;
    int mt = w >> 1;
    int half = w & 1;

    // ---- GEMM1: banded S = Q K^T ----
    {
        uint32_t qbase = sb + SQ_B;
        uint32_t kbase = sb + SK_B;
        uint32_t af[4][4];
        #pragma unroll
        for (int kt = 0; kt < 4; kt++)
            lds128(af[kt], qbase + (uint32_t)(mt * 4 + kt) * 512 + L * 16);
        #pragma unroll
        for (int nn = 0; nn < 5; nn++) {
            int ntl = half * 5 + nn;
            int ntg = 2 * mt + ntl;
            float acc[4] = {0.f, 0.f, 0.f, 0.f};
            #pragma unroll
            for (int kt = 0; kt < 4; kt++) {
                uint32_t bfr[2];
                lds64(bfr, kbase + (uint32_t)(ntg * 4 + kt) * 256 + L * 8);
                mma_f16(acc, af[kt], bfr);
            }
            int r = L >> 2, c = (L & 3) * 2;
            float* Pt = Pf + (mt * 10 + ntl) * 128;
            Pt[c_off(r, c)]         = acc[0];
            Pt[c_off(r, c + 1)]     = acc[1];
            Pt[c_off(r + 8, c)]     = acc[2];
            Pt[c_off(r + 8, c + 1)] = acc[3];
        }
    }
    __syncthreads();

    // ---- softmax ----
    {
        int row  = tid >> 2;
        int part = tid & 3;
        int rmt = row >> 4, r = row & 15;
        float* Pb = Pf + rmt * 10 * 128;
        __half* Pw = Ph + rmt * 5 * 256;
        int jb = rmt * 16;

        float mx = -1e30f;
        #pragma unroll
        for (int u = 0; u < 20; u++) {
            int jl = part * 20 + u;
            int J  = jb + jl;
            int gk = q0 - WINDOW + J;
            bool valid = (J >= row) && (J <= row + 64) && (gk >= 0) && (gk < SEQ);
            float s = Pb[(jl >> 3) * 128 + c_off(r, jl & 7)];
            if (valid) mx = fmaxf(mx, s);
        }
        mx = fmaxf(mx, __shfl_xor_sync(0xffffffffu, mx, 1));
        mx = fmaxf(mx, __shfl_xor_sync(0xffffffffu, mx, 2));

        float sum = 0.f;
        #pragma unroll
        for (int u = 0; u < 20; u++) {
            int jl = part * 20 + u;
            int J  = jb + jl;
            int gk = q0 - WINDOW + J;
            bool valid = (J >= row) && (J <= row + 64) && (gk >= 0) && (gk < SEQ);
            float s = Pb[(jl >> 3) * 128 + c_off(r, jl & 7)];
            float e = valid ? __expf(s - mx) : 0.f;
            sum += e;
            Pw[(jl >> 4) * 256 + a_off_h(r, jl & 15)] = __float2half_rn(e);
        }
        sum += __shfl_xor_sync(0xffffffffu, sum, 1);
        sum += __shfl_xor_sync(0xffffffffu, sum, 2);
        if (part == 0) inv[row] = 1.0f / sum;
    }
    __syncthreads();

    // ---- GEMM2: O = P V ----
    {
        uint32_t pbase = sb + SH_B;
        uint32_t vbase = sb + SV_B;
        int ntd0 = half * 4;
        float acc2[4][4];
        #pragma unroll
        for (int j = 0; j < 4; j++)
            #pragma unroll
            for (int q = 0; q < 4; q++) acc2[j][q] = 0.f;

        #pragma unroll
        for (int ktl = 0; ktl < 5; ktl++) {
            int kt_tok = mt + ktl;
            uint32_t af[4];
            lds128(af, pbase + (uint32_t)(mt * 5 + ktl) * 512 + L * 16);
            #pragma unroll
            for (int jn = 0; jn < 4; jn++) {
                uint32_t bfr[2];
                lds64(bfr, vbase + (uint32_t)((ntd0 + jn) * 8 + kt_tok) * 256 + L * 8);
                mma_f16(acc2[jn], af, bfr);
            }
        }

        int r0 = mt * 16 + (L >> 2);
        float i0 = inv[r0], i1 = inv[r0 + 8];
        int grow0 = b * SEQ + q0 + r0;
        int grow1 = grow0 + 8;
        int gmt0 = grow0 >> 4, grr0 = grow0 & 15;
        int gmt1 = grow1 >> 4, grr1 = grow1 & 15;
        #pragma unroll
        for (int jn = 0; jn < 4; jn++) {
            int col = h * HEAD_DIM + (ntd0 + jn) * 8 + (L & 3) * 2;
            int kt = col >> 4, cc = col & 15;
            __half2* t0 = (__half2*)(Ox + ((size_t)gmt0 * KT16 + kt) * 256);
            __half2* t1 = (__half2*)(Ox + ((size_t)gmt1 * KT16 + kt) * 256);
            t0[a_off_h(grr0, cc) >> 1] = __floats2half2_rn(acc2[jn][0] * i0, acc2[jn][1] * i0);
            t1[a_off_h(grr1, cc) >> 1] = __floats2half2_rn(acc2[jn][2] * i1, acc2[jn][3] * i1);
        }
    }
}

// ============================================================
// launch
// ============================================================
extern "C" void kernel_launch(void* const* d_in, const int* in_sizes, int n_in,
                              void* d_out, int out_size)
{
    (void)in_sizes; (void)n_in; (void)out_size;
    const float* x     = (const float*)d_in[0];
    const float* w_q   = (const float*)d_in[1];
    const float* b_q   = (const float*)d_in[2];
    const float* w_k   = (const float*)d_in[3];
    const float* b_k   = (const float*)d_in[4];
    const float* w_v   = (const float*)d_in[5];
    const float* b_v   = (const float*)d_in[6];
    const float* w_o   = (const float*)d_in[7];
    const float* b_o   = (const float*)d_in[8];
    const float* gamma = (const float*)d_in[9];
    const float* beta  = (const float*)d_in[10];
    float* out = (float*)d_out;

    void *pHx, *pWqkv, *pWo, *pBq, *pQf, *pKf, *pVf, *pAx;
    cudaGetSymbolAddress(&pHx,   g_Hx);
    cudaGetSymbolAddress(&pWqkv, g_Wqkv);
    cudaGetSymbolAddress(&pWo,   g_Wo);
    cudaGetSymbolAddress(&pBq,   g_bqkv);
    cudaGetSymbolAddress(&pQf,   g_QfG);
    cudaGetSymbolAddress(&pKf,   g_KfG);
    cudaGetSymbolAddress(&pVf,   g_VfG);
    cudaGetSymbolAddress(&pAx,   g_ATTx);
    __half* Hx   = (__half*)pHx;
    __half* Wqkv = (__half*)pWqkv;
    __half* Wo   = (__half*)pWo;
    float*  bqkv = (float*)pBq;
    __half* QfG  = (__half*)pQf;
    __half* KfG  = (__half*)pKf;
    __half* VfG  = (__half*)pVf;
    __half* ATTx = (__half*)pAx;

    cudaFuncSetAttribute(mm_kernel<0>, cudaFuncAttributeMaxDynamicSharedMemorySize, MM_SMEM);
    cudaFuncSetAttribute(mm_kernel<1>, cudaFuncAttributeMaxDynamicSharedMemorySize, MM_SMEM);
    cudaFuncSetAttribute(attn_kernel, cudaFuncAttributeMaxDynamicSharedMemorySize, ATT_SMEM);

    // prep
    wconv_kernel<<<dim3(1024 * 1024 / 256, 4), 256>>>(w_q, w_k, w_v, w_o, Wqkv, Wo);
    bconcat_kernel<<<(QKV_LD + 255) / 256, 256>>>(b_q, b_k, b_v, bqkv);
    ln_kernel<<<MROWS, 256>>>(x, gamma, beta, Hx);

    // fused QKV GEMM -> fragment arrays
    dim3 gq(QKV_LD / BN, MROWS / BM);     // (24, 32)
    mm_kernel<0><<<gq, MM_THREADS, MM_SMEM>>>(Hx, Wqkv, bqkv, nullptr, nullptr, 0, QfG, KfG, VfG);

    // banded MMA attention
    dim3 ga(SEQ / AQT, NUM_HEADS, BATCH); // (32, 16, 2)
    attn_kernel<<<ga, 256, ATT_SMEM>>>(QfG, KfG, VfG, ATTx);

    // output projection + bias + residual
    dim3 go(MODEL_DIM / BN, MROWS / BM);  // (8, 32)
    mm_kernel<1><<<go, MM_THREADS, MM_SMEM>>>(ATTx, Wo, b_o, x, out, MODEL_DIM, nullptr, nullptr, nullptr);
}

// round 15
// speedup vs baseline: 3.9994x; 1.0346x over previous
#include <cuda_runtime.h>
#include <cuda_fp16.h>
#include <cstdint>
#include <math.h>

// ---------------- problem constants ----------------
#define MODEL_DIM 1024
#define NUM_HEADS 16
#define HEAD_DIM  64
#define WINDOW    32
#define EPS       1e-5f
#define BATCH     2
#define SEQ       2048
#define MROWS     (BATCH * SEQ)      // 4096
#define QKV_LD    (3 * MODEL_DIM)    // 3072
#define KDIM      MODEL_DIM          // 1024
#define KT16      (KDIM / 16)        // 64

#define KNT 264                       // (2048+64)/8 n-tiles (padded)
#define VKT 132                       // (2048+64)/16 k-tiles (padded)

// ---------------- scratch (fragment-ordered fp16) ----------------
__device__ __half g_Hx  [(MROWS / 16) * KT16 * 256];
__device__ __half g_Wqkv[(QKV_LD / 8) * KT16 * 128];
__device__ __half g_Wo  [(MODEL_DIM / 8) * KT16 * 128];
__device__ float  g_bqkv[QKV_LD];
__device__ __half g_QfG [BATCH * NUM_HEADS * (SEQ / 16) * 1024];
__device__ __half g_KfG [BATCH * NUM_HEADS * KNT * 512];
__device__ __half g_VfG [BATCH * NUM_HEADS * 8 * VKT * 128];
__device__ __half g_ATTx[(MROWS / 16) * KT16 * 256];

// ---------------- helpers ----------------
__device__ __forceinline__ uint32_t smem_u32(const void* p) {
    uint32_t a;
    asm("{ .reg .u64 t; cvta.to.shared.u64 t, %1; cvt.u32.u64 %0, t; }" : "=r"(a) : "l"(p));
    return a;
}
__device__ __forceinline__ void cp_async16(uint32_t dst, const void* src) {
    asm volatile("cp.async.cg.shared.global [%0], [%1], 16;" :: "r"(dst), "l"(src) : "memory");
}
__device__ __forceinline__ void cp_commit() {
    asm volatile("cp.async.commit_group;" ::: "memory");
}
template<int N>
__device__ __forceinline__ void cp_wait() {
    asm volatile("cp.async.wait_group %0;" :: "n"(N) : "memory");
}
__device__ __forceinline__ void lds128(uint32_t* r, uint32_t a) {
    asm volatile("ld.shared.v4.b32 {%0,%1,%2,%3}, [%4];"
                 : "=r"(r[0]), "=r"(r[1]), "=r"(r[2]), "=r"(r[3]) : "r"(a));
}
__device__ __forceinline__ void lds64(uint32_t* r, uint32_t a) {
    asm volatile("ld.shared.v2.b32 {%0,%1}, [%2];"
                 : "=r"(r[0]), "=r"(r[1]) : "r"(a));
}
__device__ __forceinline__ void mma_f16(float* c, const uint32_t* a, const uint32_t* b) {
    asm volatile("mma.sync.aligned.m16n8k16.row.col.f32.f16.f16.f32 "
                 "{%0,%1,%2,%3},{%4,%5,%6,%7},{%8,%9},{%0,%1,%2,%3};"
                 : "+f"(c[0]), "+f"(c[1]), "+f"(c[2]), "+f"(c[3])
                 : "r"(a[0]), "r"(a[1]), "r"(a[2]), "r"(a[3]), "r"(b[0]), "r"(b[1]));
}

// fragment maps (half index within tile)
__device__ __forceinline__ int a_off_h(int rr, int cc) {
    return ((rr & 7) * 4 + ((cc & 7) >> 1)) * 8 + ((rr >> 3) + 2 * (cc >> 3)) * 2 + (cc & 1);
}
__device__ __forceinline__ int b_off_h(int k, int n) {
    return (n * 4 + ((k & 7) >> 1)) * 4 + (k >> 3) * 2 + (k & 1);
}
__device__ __forceinline__ int c_off(int rr, int cc) {
    return ((rr & 7) * 4 + (cc >> 1)) * 4 + (rr >> 3) * 2 + (cc & 1);
}

// ============================================================
// LayerNorm -> A-fragment-ordered fp16
// ============================================================
__global__ __launch_bounds__(256)
void ln_kernel(const float* __restrict__ x,
               const float* __restrict__ gamma,
               const float* __restrict__ beta,
               __half* __restrict__ Hx)
{
    int row = blockIdx.x;
    int tid = threadIdx.x;
    float4 a = ((const float4*)(x + (size_t)row * MODEL_DIM))[tid];

    __shared__ float red[8];
    __shared__ float stat;

    float s = a.x + a.y + a.z + a.w;
    #pragma unroll
    for (int o = 16; o; o >>= 1) s += __shfl_xor_sync(0xffffffffu, s, o);
    if ((tid & 31) == 0) red[tid >> 5] = s;
    __syncthreads();
    if (tid == 0) {
        float t = 0.f;
        #pragma unroll
        for (int i = 0; i < 8; i++) t += red[i];
        stat = t * (1.0f / MODEL_DIM);
    }
    __syncthreads();
    float mu = stat;

    float dx = a.x - mu, dy = a.y - mu, dz = a.z - mu, dw = a.w - mu;
    float s2 = dx*dx + dy*dy + dz*dz + dw*dw;
    #pragma unroll
    for (int o = 16; o; o >>= 1) s2 += __shfl_xor_sync(0xffffffffu, s2, o);
    __syncthreads();
    if ((tid & 31) == 0) red[tid >> 5] = s2;
    __syncthreads();
    if (tid == 0) {
        float t = 0.f;
        #pragma unroll
        for (int i = 0; i < 8; i++) t += red[i];
        stat = rsqrtf(t * (1.0f / MODEL_DIM) + EPS);
    }
    __syncthreads();
    float rstd = stat;

    float4 g = ((const float4*)gamma)[tid];
    float4 b = ((const float4*)beta)[tid];
    float v0 = dx * rstd * g.x + b.x;
    float v1 = dy * rstd * g.y + b.y;
    float v2 = dz * rstd * g.z + b.z;
    float v3 = dw * rstd * g.w + b.w;

    int mt = row >> 4, r = row & 15;
    int kt = tid >> 2;
    int cc0 = (tid * 4) & 15;
    __half* tile = Hx + ((size_t)mt * KT16 + kt) * 256;
    ((__half2*)tile)[a_off_h(r, cc0) >> 1]     = __floats2half2_rn(v0, v1);
    ((__half2*)tile)[a_off_h(r, cc0 + 2) >> 1] = __floats2half2_rn(v2, v3);
}

// ============================================================
// Weight -> B-fragment-ordered fp16
// ============================================================
__global__ __launch_bounds__(256)
void wconv_kernel(const float* __restrict__ wq, const float* __restrict__ wk,
                  const float* __restrict__ wv, const float* __restrict__ wo,
                  __half* __restrict__ Wqkv, __half* __restrict__ Wo)
{
    int bz = blockIdx.y;
    const float* w = (bz == 0) ? wq : (bz == 1) ? wk : (bz == 2) ? wv : wo;
    __half* WT = (bz < 3) ? (Wqkv + (size_t)bz * (1024 / 8) * KT16 * 128) : Wo;

    int idx = blockIdx.x * 256 + threadIdx.x;
    int k = idx >> 10;
    int n = idx & 1023;
    float v = w[idx];
    int nt = n >> 3, kt = k >> 4;
    WT[((size_t)nt * KT16 + kt) * 128 + b_off_h(k & 15, n & 7)] = __float2half_rn(v);
}

__global__ void bconcat_kernel(const float* __restrict__ bq,
                               const float* __restrict__ bk,
                               const float* __restrict__ bv,
                               float* __restrict__ dst)
{
    int i = blockIdx.x * 256 + threadIdx.x;
    if (i >= QKV_LD) return;
    const float* s = (i < 1024) ? bq : (i < 2048 ? bk : bv);
    dst[i] = s[i & 1023];
}

// ============================================================
// fp16 mma.sync GEMM. CTA 128x128x64, 4 warps (64x64).
// A: 3-stage cp.async smem.  B: direct coalesced LDG.64 of
// fragment-ordered global data (no smem round-trip).
// ============================================================
#define BM 128
#define BN 128
#define BK 64
#define A_TILE 16384                  // 8mt x 4kt x 512B
#define NSTAGE 3
#define NIT (KDIM / BK)               // 16
#define MM_SMEM (NSTAGE * A_TILE)     // 49152
#define MM_THREADS 128

__device__ __forceinline__ void stage_A(const __half* __restrict__ src,
                                        int mt0, int kt0, uint32_t dst)
{
    #pragma unroll
    for (int p = 0; p < 8; p++) {
        int ch = threadIdx.x + p * MM_THREADS;   // 1024 chunks of 16B
        int tl = ch >> 5;                        // 32 tiles (mti*4+kti)
        int in = ch & 31;
        int mti = tl >> 2, kti = tl & 3;
        const char* g = (const char*)(src + ((size_t)(mt0 + mti) * KT16 + kt0 + kti) * 256) + in * 16;
        cp_async16(dst + (uint32_t)tl * 512 + in * 16, g);
    }
}

template<int MODE>
__global__ __launch_bounds__(MM_THREADS, 2)
void mm_kernel(const __half* __restrict__ A,
               const __half* __restrict__ B,
               const float* __restrict__ bias,
               const float* __restrict__ resid,
               float* __restrict__ C, int ldc,
               __half* __restrict__ Qf, __half* __restrict__ Kf, __half* __restrict__ Vf)
{
    extern __shared__ char smem[];
    uint32_t sb = smem_u32(smem);

    int tid  = threadIdx.x;
    int wid  = tid >> 5;
    int lane = tid & 31;
    int mtb = (wid >> 1) * 4;
    int ntb = (wid & 1) * 8;
    int mt0 = blockIdx.y * 8;
    int nt0 = blockIdx.x * 16;

    float acc[4][8][4];
    #pragma unroll
    for (int i = 0; i < 4; i++)
        #pragma unroll
        for (int j = 0; j < 8; j++)
            #pragma unroll
            for (int q = 0; q < 4; q++) acc[i][j][q] = 0.f;

    stage_A(A, mt0, 0, sb);
    cp_commit();
    stage_A(A, mt0, 4, sb + A_TILE);
    cp_commit();

    uint32_t aoff = (uint32_t)lane * 16;
    // per-warp B base: fragment tile (nt0+ntb+j, ktg) is 128 halves = 32 uint2;
    // thread L's fragment = uint2 at tile_base + L.
    const uint2* Bbase = (const uint2*)(B + ((size_t)(nt0 + ntb) * KT16) * 128) + lane;

    #pragma unroll 1
    for (int it = 0; it < NIT; it++) {
        cp_wait<1>();
        __syncthreads();

        if (it + 2 < NIT) {
            uint32_t nb = sb + (uint32_t)((it + 2) % NSTAGE) * A_TILE;
            stage_A(A, mt0, (it + 2) * 4, nb);
        }
        cp_commit();

        uint32_t aB = sb + (uint32_t)(it % NSTAGE) * A_TILE;

        #pragma unroll
        for (int kti = 0; kti < 4; kti++) {
            int ktg = it * 4 + kti;
            uint32_t af[4][4];
            uint2 bv[8];
            #pragma unroll
            for (int j = 0; j < 8; j++)
                bv[j] = __ldg(Bbase + ((size_t)j * KT16 + ktg) * 32);   // tile = 32 uint2
            #pragma unroll
            for (int i = 0; i < 4; i++)
                lds128(af[i], aB + (uint32_t)((mtb + i) * 4 + kti) * 512 + aoff);
            #pragma unroll
            for (int i = 0; i < 4; i++)
                #pragma unroll
                for (int j = 0; j < 8; j++) {
                    uint32_t br[2] = {bv[j].x, bv[j].y};
                    mma_f16(acc[i][j], af[i], br);
                }
        }
    }

    int mBase = mt0 * 16 + mtb * 16 + (lane >> 2);
    int nBase = nt0 * 8 + ntb * 8 + (lane & 3) * 2;

    if (MODE == 1) {
        #pragma unroll
        for (int i = 0; i < 4; i++) {
            int m0 = mBase + i * 16;
            #pragma unroll
            for (int j = 0; j < 8; j++) {
                int n = nBase + j * 8;
                float bx0 = bias[n], bx1 = bias[n + 1];
                float2 v0, v1;
                v0.x = acc[i][j][0] + bx0;
                v0.y = acc[i][j][1] + bx1;
                v1.x = acc[i][j][2] + bx0;
                v1.y = acc[i][j][3] + bx1;
                float2 r0 = *(const float2*)(resid + (size_t)m0 * MODEL_DIM + n);
                float2 r1 = *(const float2*)(resid + (size_t)(m0 + 8) * MODEL_DIM + n);
                v0.x += r0.x; v0.y += r0.y;
                v1.x += r1.x; v1.y += r1.y;
                *(float2*)(C + (size_t)m0 * ldc + n)       = v0;
                *(float2*)(C + (size_t)(m0 + 8) * ldc + n) = v1;
            }
        }
    } else {
        int mtype = (nt0 * 8) >> 10;   // 0=Q 1=K 2=V (uniform per CTA)
        #pragma unroll
        for (int i = 0; i < 4; i++) {
            int m0 = mBase + i * 16;
            int bb  = m0 >> 11;
            int tok = m0 & 2047;
            #pragma unroll
            for (int j = 0; j < 8; j++) {
                int n = nBase + j * 8;
                float bx0 = bias[n], bx1 = bias[n + 1];
                float va0 = acc[i][j][0] + bx0, vb0 = acc[i][j][1] + bx1;
                float va1 = acc[i][j][2] + bx0, vb1 = acc[i][j][3] + bx1;
                int nn = n & 1023;
                int h = nn >> 6, d = nn & 63;
                int bh = bb * NUM_HEADS + h;
                if (mtype == 0) {
                    int kt = d >> 4, cc = d & 15;
                    __half2 h0 = __floats2half2_rn(va0 * 0.125f, vb0 * 0.125f);
                    __half2 h1 = __floats2half2_rn(va1 * 0.125f, vb1 * 0.125f);
                    __half* t0 = Qf + ((size_t)(bh * (SEQ / 16) + (tok >> 4))) * 1024 + kt * 256;
                    __half* t1 = Qf + ((size_t)(bh * (SEQ / 16) + ((tok + 8) >> 4))) * 1024 + kt * 256;
                    ((__half2*)t0)[a_off_h(tok & 15, cc) >> 1]       = h0;
                    ((__half2*)t1)[a_off_h((tok + 8) & 15, cc) >> 1] = h1;
                } else if (mtype == 1) {
                    int kt = d >> 4;
                    int tl0 = tok + 32, tl1 = tok + 40;
                    __half* t0 = Kf + ((size_t)(bh * KNT + (tl0 >> 3))) * 512 + kt * 128;
                    __half* t1 = Kf + ((size_t)(bh * KNT + (tl1 >> 3))) * 512 + kt * 128;
                    ((__half2*)t0)[b_off_h(d & 15, tl0 & 7) >> 1] = __floats2half2_rn(va0, vb0);
                    ((__half2*)t1)[b_off_h(d & 15, tl1 & 7) >> 1] = __floats2half2_rn(va1, vb1);
                } else {
                    int nt = d >> 3;
                    int tl0 = tok + 32, tl1 = tok + 40;
                    __half* base = Vf + ((size_t)(bh * 8 + nt)) * (VKT * 128);
                    __half* t0 = base + (tl0 >> 4) * 128;
                    __half* t1 = base + (tl1 >> 4) * 128;
                    t0[b_off_h(tl0 & 15, d & 7)]       = __float2half_rn(va0);
                    t0[b_off_h(tl0 & 15, (d + 1) & 7)] = __float2half_rn(vb0);
                    t1[b_off_h(tl1 & 15, d & 7)]       = __float2half_rn(va1);
                    t1[b_off_h(tl1 & 15, (d + 1) & 7)] = __float2half_rn(vb1);
                }
            }
        }
    }
}

// ============================================================
// Banded MMA attention (unchanged)
// ============================================================
#define AQT 64
#define SQ_B 0
#define SK_B 8192
#define SV_B 24576
#define SP_B 40960
#define SH_B 61440
#define SI_B 71680
#define ATT_SMEM (71680 + 256)

__global__ __launch_bounds__(256, 2)
void attn_kernel(const __half* __restrict__ QfG,
                 const __half* __restrict__ KfG,
                 const __half* __restrict__ VfG,
                 __half* __restrict__ Ox)
{
    extern __shared__ char smc[];
    uint32_t sb = smem_u32(smc);
    float*  Pf  = (float*) (smc + SP_B);
    __half* Ph  = (__half*)(smc + SH_B);
    float*  inv = (float*) (smc + SI_B);

    int tid = threadIdx.x;
    int q0  = blockIdx.x * AQT;
    int h   = blockIdx.y;
    int b   = blockIdx.z;
    int bh  = b * NUM_HEADS + h;

    {
        const char* qsrc = (const char*)(QfG + ((size_t)bh * (SEQ / 16) + (q0 >> 4)) * 1024);
        #pragma unroll
        for (int p = 0; p < 2; p++) {
            int ch = tid + p * 256;
            cp_async16(sb + SQ_B + ch * 16, qsrc + ch * 16);
        }
        const char* ksrc = (const char*)(KfG + ((size_t)bh * KNT + (q0 >> 3)) * 512);
        #pragma unroll
        for (int p = 0; p < 4; p++) {
            int ch = tid + p * 256;
            cp_async16(sb + SK_B + ch * 16, ksrc + ch * 16);
        }
        #pragma unroll
        for (int p = 0; p < 4; p++) {
            int ch = tid + p * 256;
            int nt = ch >> 7, in = ch & 127;
            const char* vsrc = (const char*)(VfG + ((size_t)(bh * 8 + nt)) * (VKT * 128) + (size_t)(q0 >> 4) * 128);
            cp_async16(sb + SV_B + ch * 16, vsrc + in * 16);
        }
        cp_commit();
        cp_wait<0>();
    }
    __syncthreads();

    int w  = tid >> 5;
    int L  = tid & 31;
    int mt = w >> 1;
    int half = w & 1;

    // ---- GEMM1: banded S = Q K^T ----
    {
        uint32_t qbase = sb + SQ_B;
        uint32_t kbase = sb + SK_B;
        uint32_t af[4][4];
        #pragma unroll
        for (int kt = 0; kt < 4; kt++)
            lds128(af[kt], qbase + (uint32_t)(mt * 4 + kt) * 512 + L * 16);
        #pragma unroll
        for (int nn = 0; nn < 5; nn++) {
            int ntl = half * 5 + nn;
            int ntg = 2 * mt + ntl;
            float acc[4] = {0.f, 0.f, 0.f, 0.f};
            #pragma unroll
            for (int kt = 0; kt < 4; kt++) {
                uint32_t bfr[2];
                lds64(bfr, kbase + (uint32_t)(ntg * 4 + kt) * 256 + L * 8);
                mma_f16(acc, af[kt], bfr);
            }
            int r = L >> 2, c = (L & 3) * 2;
            float* Pt = Pf + (mt * 10 + ntl) * 128;
            Pt[c_off(r, c)]         = acc[0];
            Pt[c_off(r, c + 1)]     = acc[1];
            Pt[c_off(r + 8, c)]     = acc[2];
            Pt[c_off(r + 8, c + 1)] = acc[3];
        }
    }
    __syncthreads();

    // ---- softmax ----
    {
        int row  = tid >> 2;
        int part = tid & 3;
        int rmt = row >> 4, r = row & 15;
        float* Pb = Pf + rmt * 10 * 128;
        __half* Pw = Ph + rmt * 5 * 256;
        int jb = rmt * 16;

        float mx = -1e30f;
        #pragma unroll
        for (int u = 0; u < 20; u++) {
            int jl = part * 20 + u;
            int J  = jb + jl;
            int gk = q0 - WINDOW + J;
            bool valid = (J >= row) && (J <= row + 64) && (gk >= 0) && (gk < SEQ);
            float s = Pb[(jl >> 3) * 128 + c_off(r, jl & 7)];
            if (valid) mx = fmaxf(mx, s);
        }
        mx = fmaxf(mx, __shfl_xor_sync(0xffffffffu, mx, 1));
        mx = fmaxf(mx, __shfl_xor_sync(0xffffffffu, mx, 2));

        float sum = 0.f;
        #pragma unroll
        for (int u = 0; u < 20; u++) {
            int jl = part * 20 + u;
            int J  = jb + jl;
            int gk = q0 - WINDOW + J;
            bool valid = (J >= row) && (J <= row + 64) && (gk >= 0) && (gk < SEQ);
            float s = Pb[(jl >> 3) * 128 + c_off(r, jl & 7)];
            float e = valid ? __expf(s - mx) : 0.f;
            sum += e;
            Pw[(jl >> 4) * 256 + a_off_h(r, jl & 15)] = __float2half_rn(e);
        }
        sum += __shfl_xor_sync(0xffffffffu, sum, 1);
        sum += __shfl_xor_sync(0xffffffffu, sum, 2);
        if (part == 0) inv[row] = 1.0f / sum;
    }
    __syncthreads();

    // ---- GEMM2: O = P V ----
    {
        uint32_t pbase = sb + SH_B;
        uint32_t vbase = sb + SV_B;
        int ntd0 = half * 4;
        float acc2[4][4];
        #pragma unroll
        for (int j = 0; j < 4; j++)
            #pragma unroll
            for (int q = 0; q < 4; q++) acc2[j][q] = 0.f;

        #pragma unroll
        for (int ktl = 0; ktl < 5; ktl++) {
            int kt_tok = mt + ktl;
            uint32_t af[4];
            lds128(af, pbase + (uint32_t)(mt * 5 + ktl) * 512 + L * 16);
            #pragma unroll
            for (int jn = 0; jn < 4; jn++) {
                uint32_t bfr[2];
                lds64(bfr, vbase + (uint32_t)((ntd0 + jn) * 8 + kt_tok) * 256 + L * 8);
                mma_f16(acc2[jn], af, bfr);
            }
        }

        int r0 = mt * 16 + (L >> 2);
        float i0 = inv[r0], i1 = inv[r0 + 8];
        int grow0 = b * SEQ + q0 + r0;
        int grow1 = grow0 + 8;
        int gmt0 = grow0 >> 4, grr0 = grow0 & 15;
        int gmt1 = grow1 >> 4, grr1 = grow1 & 15;
        #pragma unroll
        for (int jn = 0; jn < 4; jn++) {
            int col = h * HEAD_DIM + (ntd0 + jn) * 8 + (L & 3) * 2;
            int kt = col >> 4, cc = col & 15;
            __half2* t0 = (__half2*)(Ox + ((size_t)gmt0 * KT16 + kt) * 256);
            __half2* t1 = (__half2*)(Ox + ((size_t)gmt1 * KT16 + kt) * 256);
            t0[a_off_h(grr0, cc) >> 1] = __floats2half2_rn(acc2[jn][0] * i0, acc2[jn][1] * i0);
            t1[a_off_h(grr1, cc) >> 1] = __floats2half2_rn(acc2[jn][2] * i1, acc2[jn][3] * i1);
        }
    }
}

// ============================================================
// launch
// ============================================================
extern "C" void kernel_launch(void* const* d_in, const int* in_sizes, int n_in,
                              void* d_out, int out_size)
{
    (void)in_sizes; (void)n_in; (void)out_size;
    const float* x     = (const float*)d_in[0];
    const float* w_q   = (const float*)d_in[1];
    const float* b_q   = (const float*)d_in[2];
    const float* w_k   = (const float*)d_in[3];
    const float* b_k   = (const float*)d_in[4];
    const float* w_v   = (const float*)d_in[5];
    const float* b_v   = (const float*)d_in[6];
    const float* w_o   = (const float*)d_in[7];
    const float* b_o   = (const float*)d_in[8];
    const float* gamma = (const float*)d_in[9];
    const float* beta  = (const float*)d_in[10];
    float* out = (float*)d_out;

    void *pHx, *pWqkv, *pWo, *pBq, *pQf, *pKf, *pVf, *pAx;
    cudaGetSymbolAddress(&pHx,   g_Hx);
    cudaGetSymbolAddress(&pWqkv, g_Wqkv);
    cudaGetSymbolAddress(&pWo,   g_Wo);
    cudaGetSymbolAddress(&pBq,   g_bqkv);
    cudaGetSymbolAddress(&pQf,   g_QfG);
    cudaGetSymbolAddress(&pKf,   g_KfG);
    cudaGetSymbolAddress(&pVf,   g_VfG);
    cudaGetSymbolAddress(&pAx,   g_ATTx);
    __half* Hx   = (__half*)pHx;
    __half* Wqkv = (__half*)pWqkv;
    __half* Wo   = (__half*)pWo;
    float*  bqkv = (float*)pBq;
    __half* QfG  = (__half*)pQf;
    __half* KfG  = (__half*)pKf;
    __half* VfG  = (__half*)pVf;
    __half* ATTx = (__half*)pAx;

    cudaFuncSetAttribute(mm_kernel<0>, cudaFuncAttributeMaxDynamicSharedMemorySize, MM_SMEM);
    cudaFuncSetAttribute(mm_kernel<1>, cudaFuncAttributeMaxDynamicSharedMemorySize, MM_SMEM);
    cudaFuncSetAttribute(attn_kernel, cudaFuncAttributeMaxDynamicSharedMemorySize, ATT_SMEM);

    // prep
    wconv_kernel<<<dim3(1024 * 1024 / 256, 4), 256>>>(w_q, w_k, w_v, w_o, Wqkv, Wo);
    bconcat_kernel<<<(QKV_LD + 255) / 256, 256>>>(b_q, b_k, b_v, bqkv);
    ln_kernel<<<MROWS, 256>>>(x, gamma, beta, Hx);

    // fused QKV GEMM -> fragment arrays
    dim3 gq(QKV_LD / BN, MROWS / BM);     // (24, 32)
    mm_kernel<0><<<gq, MM_THREADS, MM_SMEM>>>(Hx, Wqkv, bqkv, nullptr, nullptr, 0, QfG, KfG, VfG);

    // banded MMA attention
    dim3 ga(SEQ / AQT, NUM_HEADS, BATCH); // (32, 16, 2)
    attn_kernel<<<ga, 256, ATT_SMEM>>>(QfG, KfG, VfG, ATTx);

    // output projection + bias + residual
    dim3 go(MODEL_DIM / BN, MROWS / BM);  // (8, 32)
    mm_kernel<1><<<go, MM_THREADS, MM_SMEM>>>(ATTx, Wo, b_o, x, out, MODEL_DIM, nullptr, nullptr, nullptr);
}